// round 1
// baseline (speedup 1.0000x reference)
#include <cuda_runtime.h>
#include <cuda_bf16.h>
#include <math.h>

// Problem constants
#define BB   512      // batch
#define SS   200      // seq len
#define DD   128      // model dim
#define NLAY 2
#define DH   256      // complex hidden (DH complex = 512 reals)
#define DFF  512
#define LPAD 256      // padded length (2^8)
#define PAD  56       // LPAD - SS
#define MTOK (BB*LPAD) // 131072 tokens

// ---------------- scratch (device globals; no allocation allowed) ------------
__device__ float g_x  [MTOK * DD];       // 67 MB
__device__ float g_h  [MTOK * 2 * DH];   // 268 MB (real|imag concat)
__device__ float g_hf [MTOK * DFF];      // 268 MB
__device__ float g_x2 [MTOK * DD];       // 67 MB
__device__ float g_Win [2*DH * DD];      // packed in-proj weights (gamma folded)
__device__ float g_bin [2*DH];
__device__ float g_Wout[DD * 2*DH];      // packed out-proj weights [wr | -wi]

// ---------------- small helpers ----------------------------------------------
__device__ __forceinline__ float block128_sum(float v, volatile float* sh) {
    #pragma unroll
    for (int o = 16; o > 0; o >>= 1) v += __shfl_xor_sync(0xffffffffu, v, o);
    __syncthreads();
    if ((threadIdx.x & 31) == 0) sh[threadIdx.x >> 5] = v;
    __syncthreads();
    return sh[0] + sh[1] + sh[2] + sh[3];
}

// ---------------- embedding gather + LN + front-pad ---------------------------
__global__ void embed_kernel(const float* __restrict__ emb,
                             const float* __restrict__ g,
                             const float* __restrict__ bta,
                             const int*   __restrict__ seq,
                             float* __restrict__ x) {
    __shared__ float sh[4];
    int b = blockIdx.y, t = blockIdx.x, tid = threadIdx.x;
    size_t o = ((size_t)b * LPAD + t) * DD + tid;
    if (t < PAD) { x[o] = 0.f; return; }
    int item = seq[b * SS + (t - PAD)];
    float v = emb[(size_t)item * DD + tid];
    float mu  = block128_sum(v, sh) * (1.f / DD);
    float d   = v - mu;
    float var = block128_sum(d * d, sh) * (1.f / DD);
    x[o] = d * rsqrtf(var + 1e-5f) * g[tid] + bta[tid];
}

// ---------------- generic LayerNorm (in-place, D=128) --------------------------
__global__ void ln_kernel(float* __restrict__ X,
                          const float* __restrict__ g,
                          const float* __restrict__ bta) {
    __shared__ float sh[4];
    size_t r = blockIdx.x;
    float v = X[r * DD + threadIdx.x];
    float mu  = block128_sum(v, sh) * (1.f / DD);
    float d   = v - mu;
    float var = block128_sum(d * d, sh) * (1.f / DD);
    X[r * DD + threadIdx.x] = d * rsqrtf(var + 1e-5f) * g[threadIdx.x] + bta[threadIdx.x];
}

// ---------------- per-layer weight packing ------------------------------------
// Win[n,k]  (n in [0,512), k in [0,128)): gamma-folded [in_wr ; in_wi]
// bin[n]  = gamma-folded [in_br ; in_bi]
// Wout[n,k] (n in [0,128), k in [0,512)): [out_wr | -out_wi]
__global__ void pack_kernel(const float* __restrict__ in_wr, const float* __restrict__ in_wi,
                            const float* __restrict__ in_br, const float* __restrict__ in_bi,
                            const float* __restrict__ out_wr, const float* __restrict__ out_wi,
                            const float* __restrict__ params_log, int li) {
    int idx = blockIdx.x * 256 + threadIdx.x;
    if (idx < 2*DH*DD) {
        int n = idx >> 7, k = idx & 127;
        int d = n & (DH - 1);
        float gamma = expf(params_log[(li * 3 + 2) * DH + d]);
        float w = (n < DH) ? in_wr[(size_t)li * DH * DD + n * DD + k]
                           : in_wi[(size_t)li * DH * DD + (n - DH) * DD + k];
        g_Win[idx] = w * gamma;
        if (k == 0) {
            float bv = (n < DH) ? in_br[li * DH + n] : in_bi[li * DH + n - DH];
            g_bin[n] = bv * gamma;
        }
    } else {
        int q = idx - 2*DH*DD;           // 0 .. 128*512-1
        int n = q >> 9, k = q & 511;
        float w = (k < DH) ? out_wr[(size_t)li * DD * DH + n * DH + k]
                           : -out_wi[(size_t)li * DD * DH + n * DH + (k - DH)];
        g_Wout[q] = w;
    }
}

// ---------------- masked LRU tree scan (exact reference tree) ------------------
// h layout: h[(b*LPAD + t)*512 + c] real for c<256, imag at c+256.
// 16 channel-groups of 16 complex channels per block; 8 levels.
__global__ void __launch_bounds__(256) scan_kernel(float* __restrict__ h,
                            const int* __restrict__ seq,
                            const float* __restrict__ params_log, int li) {
    __shared__ float sr[LPAD][16];
    __shared__ float si[LPAD][16];
    __shared__ float ms[LPAD];
    __shared__ float s_nu[16], s_th[16];
    int b = blockIdx.y, cg = blockIdx.x, tid = threadIdx.x;

    if (tid < LPAD) {
        int t = tid;
        ms[t] = (t >= PAD && seq[b * SS + (t - PAD)] > 0) ? 1.f : 0.f;
    }
    if (tid < 16) {
        int d = cg * 16 + tid;
        s_nu[tid] = expf(params_log[(li * 3 + 0) * DH + d]);
        s_th[tid] = expf(params_log[(li * 3 + 1) * DH + d]);
    }
    for (int i = tid; i < LPAD * 16; i += 256) {
        int t = i >> 4, c = i & 15;
        int d = cg * 16 + c;
        size_t o = ((size_t)b * LPAD + t) * (2*DH);
        sr[t][c] = h[o + d];
        si[t][c] = h[o + DH + d];
    }
    __syncthreads();

    for (int lev = 1; lev <= 8; lev++) {
        int l = 1 << lev, half = l >> 1;
        // 128 updated positions per channel, 16 channels = 2048 updates
        for (int i = tid; i < 2048; i += 256) {
            int c = i & 15;
            int u = i >> 4;              // 0..127
            int blk = u / half;
            int p = (u % half) + 1;      // distance 1..half
            int cpos = blk * l + half - 1;
            int t = cpos + p;
            float gte = ms[cpos];
            if (gte != 0.f) {
                float mag = expf(-s_nu[c] * (float)p);
                float sv, cv;
                sincosf(s_th[c] * (float)p, &sv, &cv);
                float lr = mag * cv, lim = mag * sv;
                float hr = sr[cpos][c], hi = si[cpos][c];
                sr[t][c] += lr * hr - lim * hi;
                si[t][c] += lr * hi + lim * hr;
            }
        }
        __syncthreads();
    }

    for (int i = tid; i < LPAD * 16; i += 256) {
        int t = i >> 4, c = i & 15;
        int d = cg * 16 + c;
        size_t o = ((size_t)b * LPAD + t) * (2*DH);
        h[o + d]      = sr[t][c];
        h[o + DH + d] = si[t][c];
    }
}

// ---------------- gather last valid token for layer-2 tail ---------------------
__global__ void gather_kernel(const float* __restrict__ h, const float* __restrict__ x,
                              const int* __restrict__ slen,
                              float* __restrict__ hg, float* __restrict__ xg) {
    int b = blockIdx.x, tid = threadIdx.x;
    int t = PAD + slen[b] - 1;
    hg[(size_t)b * 512 + tid] = h[((size_t)b * LPAD + t) * 512 + tid];
    if (tid < DD) xg[(size_t)b * DD + tid] = x[((size_t)b * LPAD + t) * DD + tid];
}

// ---------------- generic fp32 GEMM: C[m,n] = sum_k A[m,k]*Bw[n,k] + bias + res -
#define BM 128
#define BN 128
#define BK 16

template<bool GELU>
__global__ void __launch_bounds__(256) gemm_kernel(
        const float* __restrict__ A, const float* __restrict__ Bw,
        const float* __restrict__ bias, const float* __restrict__ Res,
        float* __restrict__ C, int M, int N, int K) {
    __shared__ float As[BK][BM];
    __shared__ float Bs[BK][BN];
    int m0 = blockIdx.y * BM;
    int n0 = blockIdx.x * BN;
    int tid = threadIdx.x;
    int tx = tid & 15, ty = tid >> 4;
    float acc[8][8];
    #pragma unroll
    for (int i = 0; i < 8; i++)
        #pragma unroll
        for (int j = 0; j < 8; j++) acc[i][j] = 0.f;

    for (int k0 = 0; k0 < K; k0 += BK) {
        #pragma unroll
        for (int j = 0; j < 2; j++) {
            int idx = tid + 256 * j;
            int m  = idx >> 2;
            int kq = (idx & 3) * 4;
            float4 va = *reinterpret_cast<const float4*>(&A [(size_t)(m0 + m) * K + k0 + kq]);
            As[kq + 0][m] = va.x; As[kq + 1][m] = va.y; As[kq + 2][m] = va.z; As[kq + 3][m] = va.w;
            float4 vb = *reinterpret_cast<const float4*>(&Bw[(size_t)(n0 + m) * K + k0 + kq]);
            Bs[kq + 0][m] = vb.x; Bs[kq + 1][m] = vb.y; Bs[kq + 2][m] = vb.z; Bs[kq + 3][m] = vb.w;
        }
        __syncthreads();
        #pragma unroll
        for (int kk = 0; kk < BK; kk++) {
            float a[8], bb[8];
            #pragma unroll
            for (int i = 0; i < 8; i += 4) {
                float4 va = *reinterpret_cast<const float4*>(&As[kk][ty * 8 + i]);
                a[i] = va.x; a[i+1] = va.y; a[i+2] = va.z; a[i+3] = va.w;
                float4 vb = *reinterpret_cast<const float4*>(&Bs[kk][tx * 8 + i]);
                bb[i] = vb.x; bb[i+1] = vb.y; bb[i+2] = vb.z; bb[i+3] = vb.w;
            }
            #pragma unroll
            for (int i = 0; i < 8; i++)
                #pragma unroll
                for (int j = 0; j < 8; j++)
                    acc[i][j] = fmaf(a[i], bb[j], acc[i][j]);
        }
        __syncthreads();
    }

    #pragma unroll
    for (int i = 0; i < 8; i++) {
        int m = m0 + ty * 8 + i;
        #pragma unroll
        for (int j = 0; j < 8; j += 4) {
            int n = n0 + tx * 8 + j;
            float4 o;
            o.x = acc[i][j+0] + bias[n+0];
            o.y = acc[i][j+1] + bias[n+1];
            o.z = acc[i][j+2] + bias[n+2];
            o.w = acc[i][j+3] + bias[n+3];
            if (Res) {
                float4 r = *reinterpret_cast<const float4*>(&Res[(size_t)m * N + n]);
                o.x += r.x; o.y += r.y; o.z += r.z; o.w += r.w;
            }
            if (GELU) {
                o.x = 0.5f * o.x * (1.f + erff(o.x * 0.70710678118654752f));
                o.y = 0.5f * o.y * (1.f + erff(o.y * 0.70710678118654752f));
                o.z = 0.5f * o.z * (1.f + erff(o.z * 0.70710678118654752f));
                o.w = 0.5f * o.w * (1.f + erff(o.w * 0.70710678118654752f));
            }
            *reinterpret_cast<float4*>(&C[(size_t)m * N + n]) = o;
        }
    }
}

// ---------------- host driver --------------------------------------------------
extern "C" void kernel_launch(void* const* d_in, const int* in_sizes, int n_in,
                              void* d_out, int out_size) {
    const float* token_emb  = (const float*)d_in[0];
    const float* emb_ln_g   = (const float*)d_in[1];
    const float* emb_ln_b   = (const float*)d_in[2];
    const float* params_log = (const float*)d_in[3];
    const float* in_wr      = (const float*)d_in[4];
    const float* in_wi      = (const float*)d_in[5];
    const float* in_br      = (const float*)d_in[6];
    const float* in_bi      = (const float*)d_in[7];
    const float* out_wr     = (const float*)d_in[8];
    const float* out_wi     = (const float*)d_in[9];
    const float* out_br     = (const float*)d_in[10];
    const float* out_bi     = (const float*)d_in[11]; (void)out_bi; // imag bias unused (real part only)
    const float* lru_ln_g   = (const float*)d_in[12];
    const float* lru_ln_b   = (const float*)d_in[13];
    const float* w1         = (const float*)d_in[14];
    const float* b1         = (const float*)d_in[15];
    const float* w2         = (const float*)d_in[16];
    const float* b2         = (const float*)d_in[17];
    const float* ffn_ln_g   = (const float*)d_in[18];
    const float* ffn_ln_b   = (const float*)d_in[19];
    const int*   item_seq   = (const int*)d_in[20];
    const int*   item_len   = (const int*)d_in[21];
    float* out = (float*)d_out;

    float *px, *ph, *phf, *px2, *pWin, *pbin, *pWout;
    cudaGetSymbolAddress((void**)&px,    g_x);
    cudaGetSymbolAddress((void**)&ph,    g_h);
    cudaGetSymbolAddress((void**)&phf,   g_hf);
    cudaGetSymbolAddress((void**)&px2,   g_x2);
    cudaGetSymbolAddress((void**)&pWin,  g_Win);
    cudaGetSymbolAddress((void**)&pbin,  g_bin);
    cudaGetSymbolAddress((void**)&pWout, g_Wout);

    embed_kernel<<<dim3(LPAD, BB), 128>>>(token_emb, emb_ln_g, emb_ln_b, item_seq, px);

    for (int li = 0; li < NLAY; li++) {
        pack_kernel<<<512, 256>>>(in_wr, in_wi, in_br, in_bi, out_wr, out_wi, params_log, li);
        // in-projection: h = (x @ [wr;wi]^T + b) * gamma   (M x 512, K=128)
        gemm_kernel<false><<<dim3(4, MTOK / BM), 256>>>(px, pWin, pbin, nullptr, ph, MTOK, 512, 128);
        // masked LRU tree scan, in place
        scan_kernel<<<dim3(16, BB), 256>>>(ph, item_seq, params_log, li);

        if (li == 0) {
            // out-projection + residual, then LN
            gemm_kernel<false><<<dim3(1, MTOK / BM), 256>>>(ph, pWout, out_br + li * DD, px, px2,
                                                            MTOK, DD, 512);
            ln_kernel<<<MTOK, 128>>>(px2, lru_ln_g + li * DD, lru_ln_b + li * DD);
            // FFN
            gemm_kernel<true ><<<dim3(4, MTOK / BM), 256>>>(px2, w1 + (size_t)li * DFF * DD,
                                                            b1 + li * DFF, nullptr, phf,
                                                            MTOK, DFF, DD);
            gemm_kernel<false><<<dim3(1, MTOK / BM), 256>>>(phf, w2 + (size_t)li * DD * DFF,
                                                            b2 + li * DD, px2, px,
                                                            MTOK, DD, DFF);
            ln_kernel<<<MTOK, 128>>>(px, ffn_ln_g + li * DD, ffn_ln_b + li * DD);
        } else {
            // only the gathered position per batch is needed downstream
            gather_kernel<<<BB, 512>>>(ph, px, item_len, phf, px2);     // hg -> phf, xg -> px2
            gemm_kernel<false><<<dim3(1, BB / BM), 256>>>(phf, pWout, out_br + li * DD, px2, ph,
                                                          BB, DD, 512); // yg -> ph
            ln_kernel<<<BB, 128>>>(ph, lru_ln_g + li * DD, lru_ln_b + li * DD);
            gemm_kernel<true ><<<dim3(4, BB / BM), 256>>>(ph, w1 + (size_t)li * DFF * DD,
                                                          b1 + li * DFF, nullptr, phf,
                                                          BB, DFF, DD);
            gemm_kernel<false><<<dim3(1, BB / BM), 256>>>(phf, w2 + (size_t)li * DD * DFF,
                                                          b2 + li * DD, ph, out,
                                                          BB, DD, DFF);
            ln_kernel<<<BB, 128>>>(out, ffn_ln_g + li * DD, ffn_ln_b + li * DD);
        }
    }
}

// round 4
// speedup vs baseline: 1.6108x; 1.6108x over previous
#include <cuda_runtime.h>
#include <cuda_bf16.h>
#include <math.h>
#include <stdint.h>

// Problem constants
#define BB   512
#define SS   200
#define DD   128
#define NLAY 2
#define DH   256      // complex hidden (512 reals)
#define DFF  512
#define LPAD 256
#define PAD  56
#define MTOK (BB*LPAD)

// single dynamic-smem symbol shared by all kernels
extern __shared__ __align__(16) char dyn_smem[];

// ---------------- scratch (device globals) ------------------------------------
__device__ float g_x  [MTOK * DD];
__device__ float g_h  [MTOK * 2 * DH];
__device__ float g_hf [MTOK * DFF];
__device__ float g_x2 [MTOK * DD];
__device__ float g_Win [2*DH * DD];
__device__ float g_bin [2*DH];
__device__ float g_Wout[DD * 2*DH];

// ---------------- helpers -------------------------------------------------------
__device__ __forceinline__ uint32_t smem_u32(const void* p) {
    uint32_t a;
    asm("{ .reg .u64 t; cvta.to.shared.u64 t, %1; cvt.u32.u64 %0, t; }" : "=r"(a) : "l"(p));
    return a;
}
__device__ __forceinline__ void ldsm4(uint32_t (&r)[4], uint32_t addr) {
    asm volatile("ldmatrix.sync.aligned.m8n8.x4.shared.b16 {%0,%1,%2,%3}, [%4];"
                 : "=r"(r[0]), "=r"(r[1]), "=r"(r[2]), "=r"(r[3]) : "r"(addr));
}
__device__ __forceinline__ void mma16816(float* c, const uint32_t* a, uint32_t b0, uint32_t b1) {
    asm volatile("mma.sync.aligned.m16n8k16.row.col.f32.bf16.bf16.f32 "
                 "{%0,%1,%2,%3}, {%4,%5,%6,%7}, {%8,%9}, {%0,%1,%2,%3};"
                 : "+f"(c[0]), "+f"(c[1]), "+f"(c[2]), "+f"(c[3])
                 : "r"(a[0]), "r"(a[1]), "r"(a[2]), "r"(a[3]), "r"(b0), "r"(b1));
}

__device__ __forceinline__ float block128_sum(float v, volatile float* sh) {
    #pragma unroll
    for (int o = 16; o > 0; o >>= 1) v += __shfl_xor_sync(0xffffffffu, v, o);
    __syncthreads();
    if ((threadIdx.x & 31) == 0) sh[threadIdx.x >> 5] = v;
    __syncthreads();
    return sh[0] + sh[1] + sh[2] + sh[3];
}

// ---------------- embedding gather + LN + front-pad ----------------------------
__global__ void embed_kernel(const float* __restrict__ emb,
                             const float* __restrict__ g,
                             const float* __restrict__ bta,
                             const int*   __restrict__ seq,
                             float* __restrict__ x) {
    __shared__ float sh[4];
    int b = blockIdx.y, t = blockIdx.x, tid = threadIdx.x;
    size_t o = ((size_t)b * LPAD + t) * DD + tid;
    if (t < PAD) { x[o] = 0.f; return; }
    int item = seq[b * SS + (t - PAD)];
    float v = emb[(size_t)item * DD + tid];
    float mu  = block128_sum(v, sh) * (1.f / DD);
    float d   = v - mu;
    float var = block128_sum(d * d, sh) * (1.f / DD);
    x[o] = d * rsqrtf(var + 1e-5f) * g[tid] + bta[tid];
}

// ---------------- per-layer weight packing -------------------------------------
__global__ void pack_kernel(const float* __restrict__ in_wr, const float* __restrict__ in_wi,
                            const float* __restrict__ in_br, const float* __restrict__ in_bi,
                            const float* __restrict__ out_wr, const float* __restrict__ out_wi,
                            const float* __restrict__ params_log, int li) {
    int idx = blockIdx.x * 256 + threadIdx.x;
    if (idx < 2*DH*DD) {
        int n = idx >> 7, k = idx & 127;
        int d = n & (DH - 1);
        float gamma = expf(params_log[(li * 3 + 2) * DH + d]);
        float w = (n < DH) ? in_wr[(size_t)li * DH * DD + n * DD + k]
                           : in_wi[(size_t)li * DH * DD + (n - DH) * DD + k];
        g_Win[idx] = w * gamma;
        if (k == 0) {
            float bv = (n < DH) ? in_br[li * DH + n] : in_bi[li * DH + n - DH];
            g_bin[n] = bv * gamma;
        }
    } else {
        int q = idx - 2*DH*DD;
        int n = q >> 9, k = q & 511;
        float w = (k < DH) ? out_wr[(size_t)li * DD * DH + n * DH + k]
                           : -out_wi[(size_t)li * DD * DH + n * DH + (k - DH)];
        g_Wout[q] = w;
    }
}

// ---------------- masked LRU tree scan with lambda-power table ------------------
__global__ void __launch_bounds__(256) scan_kernel(float* __restrict__ h,
                            const int* __restrict__ seq,
                            const float* __restrict__ params_log, int li) {
    float* sm = (float*)dyn_smem;
    float* sr = sm;                       // 256*16
    float* si = sm + 4096;                // 256*16
    float* tr = sm + 8192;                // 128*16
    float* ti = sm + 8192 + 2048;         // 128*16
    float* ms = sm + 8192 + 4096;         // 256
    __shared__ float s_nu[16], s_th[16];
    int b = blockIdx.y, cg = blockIdx.x, tid = threadIdx.x;

    if (tid < LPAD)
        ms[tid] = (tid >= PAD && seq[b * SS + (tid - PAD)] > 0) ? 1.f : 0.f;
    if (tid < 16) {
        int d = cg * 16 + tid;
        s_nu[tid] = expf(params_log[(li * 3 + 0) * DH + d]);
        s_th[tid] = expf(params_log[(li * 3 + 1) * DH + d]);
    }
    for (int i = tid; i < LPAD * 16; i += 256) {
        int t = i >> 4, c = i & 15, d = cg * 16 + c;
        size_t o = ((size_t)b * LPAD + t) * (2*DH);
        sr[t*16 + c] = h[o + d];
        si[t*16 + c] = h[o + DH + d];
    }
    __syncthreads();
    // lambda^p table, p = 1..128
    for (int i = tid; i < 2048; i += 256) {
        int c = i & 15, p = (i >> 4) + 1;
        float mag = expf(-s_nu[c] * (float)p);
        float sv, cv;
        sincosf(s_th[c] * (float)p, &sv, &cv);
        tr[(p-1)*16 + c] = mag * cv;
        ti[(p-1)*16 + c] = mag * sv;
    }
    __syncthreads();

    #pragma unroll
    for (int lev = 1; lev <= 8; lev++) {
        int half = 1 << (lev - 1);
        for (int i = tid; i < 2048; i += 256) {
            int c = i & 15;
            int u = i >> 4;
            int blk = u >> (lev - 1);
            int p = (u & (half - 1)) + 1;
            int cpos = blk * (half << 1) + half - 1;
            int t = cpos + p;
            if (ms[cpos] != 0.f) {
                float lr  = tr[(p-1)*16 + c];
                float lim = ti[(p-1)*16 + c];
                float hr = sr[cpos*16 + c], hi2 = si[cpos*16 + c];
                sr[t*16 + c] += lr * hr - lim * hi2;
                si[t*16 + c] += lr * hi2 + lim * hr;
            }
        }
        __syncthreads();
    }

    for (int i = tid; i < LPAD * 16; i += 256) {
        int t = i >> 4, c = i & 15, d = cg * 16 + c;
        size_t o = ((size_t)b * LPAD + t) * (2*DH);
        h[o + d]      = sr[t*16 + c];
        h[o + DH + d] = si[t*16 + c];
    }
}

// ---------------- gather last valid token --------------------------------------
__global__ void gather_kernel(const float* __restrict__ h, const float* __restrict__ x,
                              const int* __restrict__ slen,
                              float* __restrict__ hg, float* __restrict__ xg) {
    int b = blockIdx.x, tid = threadIdx.x;
    int t = PAD + slen[b] - 1;
    hg[(size_t)b * 512 + tid] = h[((size_t)b * LPAD + t) * 512 + tid];
    if (tid < DD) xg[(size_t)b * DD + tid] = x[((size_t)b * LPAD + t) * DD + tid];
}

// ---------------- split-bf16 mma.sync GEMM --------------------------------------
// C[m,n] = sum_k A[m,k]*Bw[n,k] + bias[n] (+Res/+gelu/+LN per EPI)
// EPI 0: bias. EPI 1: bias+gelu. EPI 2: bias+residual+LayerNorm (N==128).
// BM=128, BN=128, BK=64. 8 warps, each warp: 16 rows x 128 cols.
// Precision: acc += Ah*Bh + Al*Bh + Ah*Bl (fp32 accumulators).

#define PITCH 144                     // (64 bf16 = 128B) + 16B pad, conflict-free
#define TILEB (128*PITCH)             // 18432 bytes
#define SM_FIX 1536                   // bias/g/b (3*128 floats)
#define SM_TOT (SM_FIX + 4*TILEB)     // 75264

__device__ __forceinline__ void cvt_store(char* hi, char* lo, int row, int c4, float4 f) {
    __nv_bfloat162 h0 = __floats2bfloat162_rn(f.x, f.y);
    __nv_bfloat162 h1 = __floats2bfloat162_rn(f.z, f.w);
    __nv_bfloat162 l0 = __floats2bfloat162_rn(f.x - __bfloat162float(h0.x),
                                              f.y - __bfloat162float(h0.y));
    __nv_bfloat162 l1 = __floats2bfloat162_rn(f.z - __bfloat162float(h1.x),
                                              f.w - __bfloat162float(h1.y));
    uint32_t off = row * PITCH + c4 * 8;
    *reinterpret_cast<uint2*>(hi + off) =
        make_uint2(*reinterpret_cast<uint32_t*>(&h0), *reinterpret_cast<uint32_t*>(&h1));
    *reinterpret_cast<uint2*>(lo + off) =
        make_uint2(*reinterpret_cast<uint32_t*>(&l0), *reinterpret_cast<uint32_t*>(&l1));
}

template<int EPI>
__global__ void __launch_bounds__(256) hmma_gemm(
        const float* __restrict__ A, const float* __restrict__ Bw,
        const float* __restrict__ bias, const float* __restrict__ Res,
        const float* __restrict__ lng, const float* __restrict__ lnb,
        float* __restrict__ C, int M, int N, int K) {
    char* sm = dyn_smem;
    float* sBias = (float*)sm;
    float* sG    = sBias + 128;
    float* sB    = sG + 128;
    char* tAh = sm + SM_FIX;
    char* tAl = tAh + TILEB;
    char* tBh = tAl + TILEB;
    char* tBl = tBh + TILEB;
    uint32_t sb = smem_u32(sm);
    uint32_t aAh = sb + SM_FIX, aAl = aAh + TILEB, aBh = aAl + TILEB, aBl = aBh + TILEB;

    int tid = threadIdx.x, lane = tid & 31, wid = tid >> 5;
    int q = lane & 3, hrow = lane >> 2;
    int m0 = blockIdx.y * 128, n0 = blockIdx.x * 128;

    if (tid < 128) {
        sBias[tid] = bias[n0 + tid];
        if (EPI == 2) { sG[tid] = lng[n0 + tid]; sB[tid] = lnb[n0 + tid]; }
    }

    float acc[16][4];
    #pragma unroll
    for (int i = 0; i < 16; i++)
        #pragma unroll
        for (int j = 0; j < 4; j++) acc[i][j] = 0.f;

    for (int kc = 0; kc < K; kc += 64) {
        __syncthreads();
        #pragma unroll
        for (int j = 0; j < 8; j++) {
            int v = tid + 256 * j;
            int row = v >> 4, c4 = v & 15;
            float4 fa = *(const float4*)(A  + (size_t)(m0 + row) * K + kc + c4 * 4);
            cvt_store(tAh, tAl, row, c4, fa);
            float4 fb = *(const float4*)(Bw + (size_t)(n0 + row) * K + kc + c4 * 4);
            cvt_store(tBh, tBl, row, c4, fb);
        }
        __syncthreads();
        #pragma unroll
        for (int ks = 0; ks < 4; ks++) {
            uint32_t aoff = (uint32_t)((wid * 16 + (lane & 15)) * PITCH + ks * 32 + (lane >> 4) * 16);
            uint32_t ah[4], al[4];
            ldsm4(ah, aAh + aoff);
            ldsm4(al, aAl + aoff);
            #pragma unroll
            for (int nb = 0; nb < 8; nb++) {
                uint32_t boff = (uint32_t)((nb * 16 + (lane & 15)) * PITCH + ks * 32 + (lane >> 4) * 16);
                uint32_t bh[4], bl[4];
                ldsm4(bh, aBh + boff);
                ldsm4(bl, aBl + boff);
                mma16816(acc[2*nb],   ah, bh[0], bh[2]);
                mma16816(acc[2*nb+1], ah, bh[1], bh[3]);
                mma16816(acc[2*nb],   al, bh[0], bh[2]);
                mma16816(acc[2*nb+1], al, bh[1], bh[3]);
                mma16816(acc[2*nb],   ah, bl[0], bl[2]);
                mma16816(acc[2*nb+1], ah, bl[1], bl[3]);
            }
        }
    }

    // ---------------- epilogue ----------------
    int r0 = m0 + wid * 16 + hrow;
    int r1 = r0 + 8;
    #pragma unroll
    for (int nt = 0; nt < 16; nt++) {
        float b0 = sBias[nt * 8 + q * 2], b1 = sBias[nt * 8 + q * 2 + 1];
        acc[nt][0] += b0; acc[nt][1] += b1;
        acc[nt][2] += b0; acc[nt][3] += b1;
    }
    if (EPI == 1) {
        #pragma unroll
        for (int nt = 0; nt < 16; nt++)
            #pragma unroll
            for (int j = 0; j < 4; j++)
                acc[nt][j] = 0.5f * acc[nt][j] * (1.f + erff(acc[nt][j] * 0.70710678118654752f));
    }
    if (EPI == 2) {
        #pragma unroll
        for (int nt = 0; nt < 16; nt++) {
            float2 ra = *(const float2*)(Res + (size_t)r0 * 128 + nt * 8 + q * 2);
            float2 rb = *(const float2*)(Res + (size_t)r1 * 128 + nt * 8 + q * 2);
            acc[nt][0] += ra.x; acc[nt][1] += ra.y;
            acc[nt][2] += rb.x; acc[nt][3] += rb.y;
        }
        float s0 = 0.f, s1 = 0.f;
        #pragma unroll
        for (int nt = 0; nt < 16; nt++) { s0 += acc[nt][0] + acc[nt][1]; s1 += acc[nt][2] + acc[nt][3]; }
        s0 += __shfl_xor_sync(0xffffffffu, s0, 1); s0 += __shfl_xor_sync(0xffffffffu, s0, 2);
        s1 += __shfl_xor_sync(0xffffffffu, s1, 1); s1 += __shfl_xor_sync(0xffffffffu, s1, 2);
        float mu0 = s0 * (1.f / 128.f), mu1 = s1 * (1.f / 128.f);
        float v0 = 0.f, v1 = 0.f;
        #pragma unroll
        for (int nt = 0; nt < 16; nt++) {
            float d0 = acc[nt][0] - mu0, d1 = acc[nt][1] - mu0;
            float d2 = acc[nt][2] - mu1, d3 = acc[nt][3] - mu1;
            v0 += d0 * d0 + d1 * d1; v1 += d2 * d2 + d3 * d3;
        }
        v0 += __shfl_xor_sync(0xffffffffu, v0, 1); v0 += __shfl_xor_sync(0xffffffffu, v0, 2);
        v1 += __shfl_xor_sync(0xffffffffu, v1, 1); v1 += __shfl_xor_sync(0xffffffffu, v1, 2);
        float rs0 = rsqrtf(v0 * (1.f / 128.f) + 1e-5f);
        float rs1 = rsqrtf(v1 * (1.f / 128.f) + 1e-5f);
        #pragma unroll
        for (int nt = 0; nt < 16; nt++) {
            int c0 = nt * 8 + q * 2;
            float g0 = sG[c0], g1 = sG[c0 + 1], bb0 = sB[c0], bb1 = sB[c0 + 1];
            acc[nt][0] = (acc[nt][0] - mu0) * rs0 * g0 + bb0;
            acc[nt][1] = (acc[nt][1] - mu0) * rs0 * g1 + bb1;
            acc[nt][2] = (acc[nt][2] - mu1) * rs1 * g0 + bb0;
            acc[nt][3] = (acc[nt][3] - mu1) * rs1 * g1 + bb1;
        }
    }
    #pragma unroll
    for (int nt = 0; nt < 16; nt++) {
        int c0 = n0 + nt * 8 + q * 2;
        *(float2*)(C + (size_t)r0 * N + c0) = make_float2(acc[nt][0], acc[nt][1]);
        *(float2*)(C + (size_t)r1 * N + c0) = make_float2(acc[nt][2], acc[nt][3]);
    }
}

// ---------------- host driver ---------------------------------------------------
extern "C" void kernel_launch(void* const* d_in, const int* in_sizes, int n_in,
                              void* d_out, int out_size) {
    const float* token_emb  = (const float*)d_in[0];
    const float* emb_ln_g   = (const float*)d_in[1];
    const float* emb_ln_b   = (const float*)d_in[2];
    const float* params_log = (const float*)d_in[3];
    const float* in_wr      = (const float*)d_in[4];
    const float* in_wi      = (const float*)d_in[5];
    const float* in_br      = (const float*)d_in[6];
    const float* in_bi      = (const float*)d_in[7];
    const float* out_wr     = (const float*)d_in[8];
    const float* out_wi     = (const float*)d_in[9];
    const float* out_br     = (const float*)d_in[10];
    const float* lru_ln_g   = (const float*)d_in[12];
    const float* lru_ln_b   = (const float*)d_in[13];
    const float* w1         = (const float*)d_in[14];
    const float* b1         = (const float*)d_in[15];
    const float* w2         = (const float*)d_in[16];
    const float* b2         = (const float*)d_in[17];
    const float* ffn_ln_g   = (const float*)d_in[18];
    const float* ffn_ln_b   = (const float*)d_in[19];
    const int*   item_seq   = (const int*)d_in[20];
    const int*   item_len   = (const int*)d_in[21];
    float* out = (float*)d_out;

    float *px, *ph, *phf, *px2, *pWin, *pbin, *pWout;
    cudaGetSymbolAddress((void**)&px,    g_x);
    cudaGetSymbolAddress((void**)&ph,    g_h);
    cudaGetSymbolAddress((void**)&phf,   g_hf);
    cudaGetSymbolAddress((void**)&px2,   g_x2);
    cudaGetSymbolAddress((void**)&pWin,  g_Win);
    cudaGetSymbolAddress((void**)&pbin,  g_bin);
    cudaGetSymbolAddress((void**)&pWout, g_Wout);

    cudaFuncSetAttribute(hmma_gemm<0>, cudaFuncAttributeMaxDynamicSharedMemorySize, SM_TOT);
    cudaFuncSetAttribute(hmma_gemm<1>, cudaFuncAttributeMaxDynamicSharedMemorySize, SM_TOT);
    cudaFuncSetAttribute(hmma_gemm<2>, cudaFuncAttributeMaxDynamicSharedMemorySize, SM_TOT);
    cudaFuncSetAttribute(scan_kernel, cudaFuncAttributeMaxDynamicSharedMemorySize, 50176);

    embed_kernel<<<dim3(LPAD, BB), 128>>>(token_emb, emb_ln_g, emb_ln_b, item_seq, px);

    for (int li = 0; li < NLAY; li++) {
        pack_kernel<<<512, 256>>>(in_wr, in_wi, in_br, in_bi, out_wr, out_wi, params_log, li);
        // in-projection: h = (x @ [wr;wi]^T + b) * gamma
        hmma_gemm<0><<<dim3(4, MTOK/128), 256, SM_TOT>>>(
            px, pWin, pbin, nullptr, nullptr, nullptr, ph, MTOK, 512, 128);
        scan_kernel<<<dim3(16, BB), 256, 50176>>>(ph, item_seq, params_log, li);

        if (li == 0) {
            hmma_gemm<2><<<dim3(1, MTOK/128), 256, SM_TOT>>>(
                ph, pWout, out_br + li*DD, px, lru_ln_g + li*DD, lru_ln_b + li*DD,
                px2, MTOK, 128, 512);
            hmma_gemm<1><<<dim3(4, MTOK/128), 256, SM_TOT>>>(
                px2, w1 + (size_t)li*DFF*DD, b1 + li*DFF, nullptr, nullptr, nullptr,
                phf, MTOK, 512, 128);
            hmma_gemm<2><<<dim3(1, MTOK/128), 256, SM_TOT>>>(
                phf, w2 + (size_t)li*DD*DFF, b2 + li*DD, px2, ffn_ln_g + li*DD, ffn_ln_b + li*DD,
                px, MTOK, 128, 512);
        } else {
            gather_kernel<<<BB, 512>>>(ph, px, item_len, phf, px2);
            hmma_gemm<2><<<dim3(1, BB/128), 256, SM_TOT>>>(
                phf, pWout, out_br + li*DD, px2, lru_ln_g + li*DD, lru_ln_b + li*DD,
                ph, BB, 128, 512);
            hmma_gemm<1><<<dim3(4, BB/128), 256, SM_TOT>>>(
                ph, w1 + (size_t)li*DFF*DD, b1 + li*DFF, nullptr, nullptr, nullptr,
                phf, BB, 512, 128);
            hmma_gemm<2><<<dim3(1, BB/128), 256, SM_TOT>>>(
                phf, w2 + (size_t)li*DD*DFF, b2 + li*DD, ph, ffn_ln_g + li*DD, ffn_ln_b + li*DD,
                out, BB, 128, 512);
        }
    }
}

// round 5
// speedup vs baseline: 1.6623x; 1.0319x over previous
#include <cuda_runtime.h>
#include <cuda_bf16.h>
#include <math.h>
#include <stdint.h>

// Problem constants
#define BB   512
#define SS   200
#define DD   128
#define NLAY 2
#define DH   256      // complex hidden (512 reals)
#define DFF  512
#define LPAD 256
#define PAD  56
#define MTOK (BB*LPAD)

// single dynamic-smem symbol shared by all kernels
extern __shared__ __align__(16) char dyn_smem[];

// ---------------- scratch (device globals) ------------------------------------
__device__ float g_x  [MTOK * DD];
__device__ float g_h  [MTOK * 2 * DH];   // interleaved: [tok][2d]=re, [tok][2d+1]=im
__device__ float g_hf [MTOK * DFF];
__device__ float g_x2 [MTOK * DD];
__device__ float g_Win [2*DH * DD];      // row n=2d+s: (s? wi : wr)[d] * gamma[d]
__device__ float g_bin [2*DH];
__device__ float g_Wout[DD * 2*DH];      // [n][k=2d+s]: s? -out_wi[n][d] : out_wr[n][d]

// ---------------- helpers -------------------------------------------------------
__device__ __forceinline__ uint32_t smem_u32(const void* p) {
    uint32_t a;
    asm("{ .reg .u64 t; cvta.to.shared.u64 t, %1; cvt.u32.u64 %0, t; }" : "=r"(a) : "l"(p));
    return a;
}
__device__ __forceinline__ void ldsm4(uint32_t (&r)[4], uint32_t addr) {
    asm volatile("ldmatrix.sync.aligned.m8n8.x4.shared.b16 {%0,%1,%2,%3}, [%4];"
                 : "=r"(r[0]), "=r"(r[1]), "=r"(r[2]), "=r"(r[3]) : "r"(addr));
}
__device__ __forceinline__ void mma16816(float* c, const uint32_t* a, uint32_t b0, uint32_t b1) {
    asm volatile("mma.sync.aligned.m16n8k16.row.col.f32.bf16.bf16.f32 "
                 "{%0,%1,%2,%3}, {%4,%5,%6,%7}, {%8,%9}, {%0,%1,%2,%3};"
                 : "+f"(c[0]), "+f"(c[1]), "+f"(c[2]), "+f"(c[3])
                 : "r"(a[0]), "r"(a[1]), "r"(a[2]), "r"(a[3]), "r"(b0), "r"(b1));
}
__device__ __forceinline__ float block128_sum(float v, volatile float* sh) {
    #pragma unroll
    for (int o = 16; o > 0; o >>= 1) v += __shfl_xor_sync(0xffffffffu, v, o);
    __syncthreads();
    if ((threadIdx.x & 31) == 0) sh[threadIdx.x >> 5] = v;
    __syncthreads();
    return sh[0] + sh[1] + sh[2] + sh[3];
}

#define PITCH 144   // 64 bf16 = 128B + 16B pad

// convert 8 fp32 (row, cols c4*4..c4*4+7... actually 4) -> hi/lo bf16, padded-pitch store
__device__ __forceinline__ void cvt_store(char* hi, char* lo, int row, int c4, float4 f) {
    __nv_bfloat162 h0 = __floats2bfloat162_rn(f.x, f.y);
    __nv_bfloat162 h1 = __floats2bfloat162_rn(f.z, f.w);
    __nv_bfloat162 l0 = __floats2bfloat162_rn(f.x - __bfloat162float(h0.x),
                                              f.y - __bfloat162float(h0.y));
    __nv_bfloat162 l1 = __floats2bfloat162_rn(f.z - __bfloat162float(h1.x),
                                              f.w - __bfloat162float(h1.y));
    uint32_t off = row * PITCH + c4 * 8;
    *reinterpret_cast<uint2*>(hi + off) =
        make_uint2(*reinterpret_cast<uint32_t*>(&h0), *reinterpret_cast<uint32_t*>(&h1));
    *reinterpret_cast<uint2*>(lo + off) =
        make_uint2(*reinterpret_cast<uint32_t*>(&l0), *reinterpret_cast<uint32_t*>(&l1));
}

// ---------------- embedding gather + LN + front-pad ----------------------------
__global__ void embed_kernel(const float* __restrict__ emb,
                             const float* __restrict__ g,
                             const float* __restrict__ bta,
                             const int*   __restrict__ seq,
                             float* __restrict__ x) {
    __shared__ float sh[4];
    int b = blockIdx.y, t = blockIdx.x, tid = threadIdx.x;
    size_t o = ((size_t)b * LPAD + t) * DD + tid;
    if (t < PAD) { x[o] = 0.f; return; }
    int item = seq[b * SS + (t - PAD)];
    float v = emb[(size_t)item * DD + tid];
    float mu  = block128_sum(v, sh) * (1.f / DD);
    float d   = v - mu;
    float var = block128_sum(d * d, sh) * (1.f / DD);
    x[o] = d * rsqrtf(var + 1e-5f) * g[tid] + bta[tid];
}

// ---------------- per-layer weight packing (interleaved complex) ----------------
__global__ void pack_kernel(const float* __restrict__ in_wr, const float* __restrict__ in_wi,
                            const float* __restrict__ in_br, const float* __restrict__ in_bi,
                            const float* __restrict__ out_wr, const float* __restrict__ out_wi,
                            const float* __restrict__ params_log, int li) {
    int idx = blockIdx.x * 256 + threadIdx.x;
    if (idx < 2*DH*DD) {
        int n = idx >> 7, k = idx & 127;
        int d = n >> 1, s = n & 1;
        float gamma = expf(params_log[(li * 3 + 2) * DH + d]);
        float w = s ? in_wi[(size_t)li * DH * DD + d * DD + k]
                    : in_wr[(size_t)li * DH * DD + d * DD + k];
        g_Win[idx] = w * gamma;
        if (k == 0) {
            float bv = s ? in_bi[li * DH + d] : in_br[li * DH + d];
            g_bin[n] = bv * gamma;
        }
    } else {
        int qq = idx - 2*DH*DD;
        int n = qq >> 9, k = qq & 511;
        int d = k >> 1, s = k & 1;
        float w = s ? -out_wi[(size_t)li * DD * DH + n * DH + d]
                    :  out_wr[(size_t)li * DD * DH + n * DH + d];
        g_Wout[qq] = w;
    }
}

// ---------------- gather last valid token --------------------------------------
__global__ void gather_kernel(const float* __restrict__ h, const float* __restrict__ x,
                              const int* __restrict__ slen,
                              float* __restrict__ hg, float* __restrict__ xg) {
    int b = blockIdx.x, tid = threadIdx.x;
    int t = PAD + slen[b] - 1;
    hg[(size_t)b * 512 + tid] = h[((size_t)b * LPAD + t) * 512 + tid];
    if (tid < DD) xg[(size_t)b * DD + tid] = x[((size_t)b * LPAD + t) * DD + tid];
}

// ================= fused in-projection GEMM + masked LRU scan ===================
// Per block: one batch (256 tokens) x 128 interleaved channels (64 complex).
// GEMM M=256,N=128,K=128 split-bf16 3-pass; then 8-level tree scan in smem; write h.
#define F_TILE0 1536
#define F_AH (F_TILE0)
#define F_AL (F_AH + 256*PITCH)
#define F_BH (F_AL + 256*PITCH)
#define F_BL (F_BH + 128*PITCH)
#define F_BUF  F_TILE0                 // overlay after GEMM: 256*128 fp32
#define F_LAM  (F_TILE0 + 131072)      // lamR 128*64 fp32, then lamI
#define F_SMEM (F_LAM + 2*8192*4)      // 198144

__global__ void __launch_bounds__(512, 1) fused_inproj_scan(
        const float* __restrict__ A, const float* __restrict__ Bw,
        const float* __restrict__ bias, float* __restrict__ hout,
        const int* __restrict__ seq, const float* __restrict__ params_log, int li) {
    char* sm = dyn_smem;
    float* sBias = (float*)sm;             // [0,512)
    float* ms    = (float*)(sm + 512);     // [512,1536)
    char* tAh = sm + F_AH;
    char* tAl = sm + F_AL;
    char* tBh = sm + F_BH;
    char* tBl = sm + F_BL;
    float* buf  = (float*)(sm + F_BUF);
    float* lamR = (float*)(sm + F_LAM);
    float* lamI = lamR + 8192;
    __shared__ float s_nu[64], s_th[64];
    uint32_t sb = smem_u32(sm);
    uint32_t aAh = sb + F_AH, aAl = sb + F_AL, aBh = sb + F_BH, aBl = sb + F_BL;

    int tid = threadIdx.x, lane = tid & 31, wid = tid >> 5;
    int q = lane & 3, hrow = lane >> 2;
    int wm = wid & 7, wn = wid >> 3;
    int b = blockIdx.y, cg = blockIdx.x;
    int m0 = b * 256, n0 = cg * 128;

    if (tid < 128) sBias[tid] = bias[n0 + tid];
    if (tid >= 256 && tid < 512) {
        int t = tid - 256;
        ms[t] = (t >= PAD && seq[b * SS + t - PAD] > 0) ? 1.f : 0.f;
    }
    if (tid < 64) {
        int d = cg * 64 + tid;
        s_nu[tid] = expf(params_log[(li * 3 + 0) * DH + d]);
        s_th[tid] = expf(params_log[(li * 3 + 1) * DH + d]);
    }

    float acc[2][8][4];
    #pragma unroll
    for (int a1 = 0; a1 < 2; a1++)
        #pragma unroll
        for (int a2 = 0; a2 < 8; a2++)
            #pragma unroll
            for (int a3 = 0; a3 < 4; a3++) acc[a1][a2][a3] = 0.f;

    #pragma unroll
    for (int kc = 0; kc < 128; kc += 64) {
        __syncthreads();
        #pragma unroll
        for (int j = 0; j < 8; j++) {
            int idx = j * 512 + tid;
            int row = idx >> 4, c4 = idx & 15;
            float4 fa = *(const float4*)(A + (size_t)(m0 + row) * 128 + kc + c4 * 4);
            cvt_store(tAh, tAl, row, c4, fa);
        }
        #pragma unroll
        for (int j = 0; j < 4; j++) {
            int idx = j * 512 + tid;
            int row = idx >> 4, c4 = idx & 15;
            float4 fb = *(const float4*)(Bw + (size_t)(n0 + row) * 128 + kc + c4 * 4);
            cvt_store(tBh, tBl, row, c4, fb);
        }
        __syncthreads();
        #pragma unroll
        for (int ks = 0; ks < 4; ks++) {
            uint32_t ah[2][4], al[2][4];
            #pragma unroll
            for (int mt = 0; mt < 2; mt++) {
                uint32_t aoff = (uint32_t)((wm*32 + mt*16 + (lane & 15)) * PITCH + ks*32 + (lane >> 4) * 16);
                ldsm4(ah[mt], aAh + aoff);
                ldsm4(al[mt], aAl + aoff);
            }
            #pragma unroll
            for (int nb = 0; nb < 4; nb++) {
                uint32_t boff = (uint32_t)((wn*64 + nb*16 + (lane & 15)) * PITCH + ks*32 + (lane >> 4) * 16);
                uint32_t bh[4], bl[4];
                ldsm4(bh, aBh + boff);
                ldsm4(bl, aBl + boff);
                #pragma unroll
                for (int mt = 0; mt < 2; mt++) {
                    mma16816(acc[mt][2*nb],   ah[mt], bh[0], bh[2]);
                    mma16816(acc[mt][2*nb+1], ah[mt], bh[1], bh[3]);
                    mma16816(acc[mt][2*nb],   al[mt], bh[0], bh[2]);
                    mma16816(acc[mt][2*nb+1], al[mt], bh[1], bh[3]);
                    mma16816(acc[mt][2*nb],   ah[mt], bl[0], bl[2]);
                    mma16816(acc[mt][2*nb+1], ah[mt], bl[1], bl[3]);
                }
            }
        }
    }

    // epilogue -> scan buffer (overlays tiles)
    __syncthreads();
    #pragma unroll
    for (int mt = 0; mt < 2; mt++) {
        int r0 = wm*32 + mt*16 + hrow;
        #pragma unroll
        for (int j = 0; j < 8; j++) {
            int col = wn*64 + j*8 + q*2;
            float b0 = sBias[col], b1 = sBias[col+1];
            *(float2*)&buf[r0*128 + col]     = make_float2(acc[mt][j][0] + b0, acc[mt][j][1] + b1);
            *(float2*)&buf[(r0+8)*128 + col] = make_float2(acc[mt][j][2] + b0, acc[mt][j][3] + b1);
        }
    }
    // lambda^p table (region disjoint from buf)
    for (int i = tid; i < 8192; i += 512) {
        int c = i & 63, p = (i >> 6) + 1;
        float mag = expf(-s_nu[c] * (float)p);
        float sv, cv;
        sincosf(s_th[c] * (float)p, &sv, &cv);
        lamR[(p-1)*64 + c] = mag * cv;
        lamI[(p-1)*64 + c] = mag * sv;
    }
    __syncthreads();

    // 8-level masked tree scan over 64 complex channels
    #pragma unroll
    for (int lev = 1; lev <= 8; lev++) {
        int half = 1 << (lev - 1);
        for (int i = tid; i < 8192; i += 512) {
            int c = i & 63, u = i >> 6;
            int blk = u >> (lev - 1);
            int p = (u & (half - 1)) + 1;
            int cpos = blk * (half << 1) + half - 1;
            int t = cpos + p;
            if (ms[cpos] != 0.f) {
                float2 src = *(float2*)&buf[cpos*128 + 2*c];
                float lr = lamR[(p-1)*64 + c], lim = lamI[(p-1)*64 + c];
                float2 dst = *(float2*)&buf[t*128 + 2*c];
                dst.x += lr * src.x - lim * src.y;
                dst.y += lr * src.y + lim * src.x;
                *(float2*)&buf[t*128 + 2*c] = dst;
            }
        }
        __syncthreads();
    }

    // write h
    for (int i = tid; i < 8192; i += 512) {
        int t = i >> 5, c4 = i & 31;
        float4 v = *(const float4*)&buf[t*128 + c4*4];
        *(float4*)&hout[((size_t)(m0 + t)) * 512 + n0 + c4*4] = v;
    }
}

// ================= standalone split-bf16 GEMM (warp tile 32x64) =================
// EPI 0: bias. EPI 1: bias+gelu. EPI 2: bias+residual+LayerNorm (N==128, Res stride 128).
#define SM_FIX 1536
#define SM_TOT (SM_FIX + 4*128*PITCH)   // 75264

template<int EPI>
__global__ void __launch_bounds__(256) hmma_gemm(
        const float* __restrict__ A, const float* __restrict__ Bw,
        const float* __restrict__ bias, const float* __restrict__ Res,
        const float* __restrict__ lng, const float* __restrict__ lnb,
        float* __restrict__ C, int M, int N, int K) {
    char* sm = dyn_smem;
    float* sBias = (float*)sm;
    float* sG    = sBias + 128;
    float* sB    = sG + 128;
    char* tAh = sm + SM_FIX;
    char* tAl = tAh + 128*PITCH;
    char* tBh = tAl + 128*PITCH;
    char* tBl = tBh + 128*PITCH;
    float* sred = (float*)(sm + SM_FIX);   // overlay after mainloop: [2][128][2]
    uint32_t sb = smem_u32(sm);
    uint32_t aAh = sb + SM_FIX, aAl = aAh + 128*PITCH, aBh = aAl + 128*PITCH, aBl = aBh + 128*PITCH;

    int tid = threadIdx.x, lane = tid & 31, wid = tid >> 5;
    int q = lane & 3, hrow = lane >> 2;
    int wm = wid & 3, wn = wid >> 2;
    int m0 = blockIdx.y * 128, n0 = blockIdx.x * 128;

    if (tid < 128) {
        sBias[tid] = bias[n0 + tid];
        if (EPI == 2) { sG[tid] = lng[n0 + tid]; sB[tid] = lnb[n0 + tid]; }
    }

    float acc[2][8][4];
    #pragma unroll
    for (int a1 = 0; a1 < 2; a1++)
        #pragma unroll
        for (int a2 = 0; a2 < 8; a2++)
            #pragma unroll
            for (int a3 = 0; a3 < 4; a3++) acc[a1][a2][a3] = 0.f;

    for (int kc = 0; kc < K; kc += 64) {
        __syncthreads();
        #pragma unroll
        for (int j = 0; j < 8; j++) {
            int idx = tid + 256 * j;
            int row = idx >> 4, c4 = idx & 15;
            float4 fa = *(const float4*)(A  + (size_t)(m0 + row) * K + kc + c4 * 4);
            cvt_store(tAh, tAl, row, c4, fa);
            float4 fb = *(const float4*)(Bw + (size_t)(n0 + row) * K + kc + c4 * 4);
            cvt_store(tBh, tBl, row, c4, fb);
        }
        __syncthreads();
        #pragma unroll
        for (int ks = 0; ks < 4; ks++) {
            uint32_t ah[2][4], al[2][4];
            #pragma unroll
            for (int mt = 0; mt < 2; mt++) {
                uint32_t aoff = (uint32_t)((wm*32 + mt*16 + (lane & 15)) * PITCH + ks*32 + (lane >> 4) * 16);
                ldsm4(ah[mt], aAh + aoff);
                ldsm4(al[mt], aAl + aoff);
            }
            #pragma unroll
            for (int nb = 0; nb < 4; nb++) {
                uint32_t boff = (uint32_t)((wn*64 + nb*16 + (lane & 15)) * PITCH + ks*32 + (lane >> 4) * 16);
                uint32_t bh[4], bl[4];
                ldsm4(bh, aBh + boff);
                ldsm4(bl, aBl + boff);
                #pragma unroll
                for (int mt = 0; mt < 2; mt++) {
                    mma16816(acc[mt][2*nb],   ah[mt], bh[0], bh[2]);
                    mma16816(acc[mt][2*nb+1], ah[mt], bh[1], bh[3]);
                    mma16816(acc[mt][2*nb],   al[mt], bh[0], bh[2]);
                    mma16816(acc[mt][2*nb+1], al[mt], bh[1], bh[3]);
                    mma16816(acc[mt][2*nb],   ah[mt], bl[0], bl[2]);
                    mma16816(acc[mt][2*nb+1], ah[mt], bl[1], bl[3]);
                }
            }
        }
    }

    // ---------------- epilogue ----------------
    #pragma unroll
    for (int mt = 0; mt < 2; mt++)
        #pragma unroll
        for (int j = 0; j < 8; j++) {
            int col = wn*64 + j*8 + q*2;
            float b0 = sBias[col], b1 = sBias[col+1];
            acc[mt][j][0] += b0; acc[mt][j][1] += b1;
            acc[mt][j][2] += b0; acc[mt][j][3] += b1;
        }
    if (EPI == 1) {
        #pragma unroll
        for (int mt = 0; mt < 2; mt++)
            #pragma unroll
            for (int j = 0; j < 8; j++)
                #pragma unroll
                for (int v = 0; v < 4; v++)
                    acc[mt][j][v] = 0.5f * acc[mt][j][v] *
                                    (1.f + erff(acc[mt][j][v] * 0.70710678118654752f));
    }
    float mu[2][2], rs[2][2];
    if (EPI == 2) {
        #pragma unroll
        for (int mt = 0; mt < 2; mt++) {
            int r0 = m0 + wm*32 + mt*16 + hrow;
            #pragma unroll
            for (int j = 0; j < 8; j++) {
                int col = wn*64 + j*8 + q*2;
                float2 ra = *(const float2*)(Res + (size_t)r0 * 128 + col);
                float2 rb = *(const float2*)(Res + (size_t)(r0+8) * 128 + col);
                acc[mt][j][0] += ra.x; acc[mt][j][1] += ra.y;
                acc[mt][j][2] += rb.x; acc[mt][j][3] += rb.y;
            }
        }
        float ssum[2][2] = {{0,0},{0,0}}, ssq[2][2] = {{0,0},{0,0}};
        #pragma unroll
        for (int mt = 0; mt < 2; mt++)
            #pragma unroll
            for (int j = 0; j < 8; j++)
                #pragma unroll
                for (int hh = 0; hh < 2; hh++) {
                    float v0 = acc[mt][j][2*hh], v1 = acc[mt][j][2*hh+1];
                    ssum[mt][hh] += v0 + v1;
                    ssq[mt][hh]  += v0*v0 + v1*v1;
                }
        #pragma unroll
        for (int mt = 0; mt < 2; mt++)
            #pragma unroll
            for (int hh = 0; hh < 2; hh++) {
                ssum[mt][hh] += __shfl_xor_sync(0xffffffffu, ssum[mt][hh], 1);
                ssum[mt][hh] += __shfl_xor_sync(0xffffffffu, ssum[mt][hh], 2);
                ssq[mt][hh]  += __shfl_xor_sync(0xffffffffu, ssq[mt][hh], 1);
                ssq[mt][hh]  += __shfl_xor_sync(0xffffffffu, ssq[mt][hh], 2);
            }
        __syncthreads();   // tiles no longer read; safe to overlay sred
        if (q == 0) {
            #pragma unroll
            for (int mt = 0; mt < 2; mt++)
                #pragma unroll
                for (int hh = 0; hh < 2; hh++) {
                    int lr = wm*32 + mt*16 + hrow + hh*8;
                    sred[lr*2 + wn]       = ssum[mt][hh];
                    sred[256 + lr*2 + wn] = ssq[mt][hh];
                }
        }
        __syncthreads();
        #pragma unroll
        for (int mt = 0; mt < 2; mt++)
            #pragma unroll
            for (int hh = 0; hh < 2; hh++) {
                int lr = wm*32 + mt*16 + hrow + hh*8;
                float S  = sred[lr*2] + sred[lr*2 + 1];
                float S2 = sred[256 + lr*2] + sred[256 + lr*2 + 1];
                float m  = S * (1.f/128.f);
                float var = S2 * (1.f/128.f) - m * m;
                mu[mt][hh] = m;
                rs[mt][hh] = rsqrtf(var + 1e-5f);
            }
        #pragma unroll
        for (int mt = 0; mt < 2; mt++)
            #pragma unroll
            for (int j = 0; j < 8; j++) {
                int col = wn*64 + j*8 + q*2;
                float g0 = sG[col], g1 = sG[col+1], bb0 = sB[col], bb1 = sB[col+1];
                acc[mt][j][0] = (acc[mt][j][0] - mu[mt][0]) * rs[mt][0] * g0 + bb0;
                acc[mt][j][1] = (acc[mt][j][1] - mu[mt][0]) * rs[mt][0] * g1 + bb1;
                acc[mt][j][2] = (acc[mt][j][2] - mu[mt][1]) * rs[mt][1] * g0 + bb0;
                acc[mt][j][3] = (acc[mt][j][3] - mu[mt][1]) * rs[mt][1] * g1 + bb1;
            }
    }
    #pragma unroll
    for (int mt = 0; mt < 2; mt++) {
        int r0 = m0 + wm*32 + mt*16 + hrow;
        #pragma unroll
        for (int j = 0; j < 8; j++) {
            int col = n0 + wn*64 + j*8 + q*2;
            *(float2*)(C + (size_t)r0 * N + col)     = make_float2(acc[mt][j][0], acc[mt][j][1]);
            *(float2*)(C + (size_t)(r0+8) * N + col) = make_float2(acc[mt][j][2], acc[mt][j][3]);
        }
    }
}

// ---------------- host driver ---------------------------------------------------
extern "C" void kernel_launch(void* const* d_in, const int* in_sizes, int n_in,
                              void* d_out, int out_size) {
    const float* token_emb  = (const float*)d_in[0];
    const float* emb_ln_g   = (const float*)d_in[1];
    const float* emb_ln_b   = (const float*)d_in[2];
    const float* params_log = (const float*)d_in[3];
    const float* in_wr      = (const float*)d_in[4];
    const float* in_wi      = (const float*)d_in[5];
    const float* in_br      = (const float*)d_in[6];
    const float* in_bi      = (const float*)d_in[7];
    const float* out_wr     = (const float*)d_in[8];
    const float* out_wi     = (const float*)d_in[9];
    const float* out_br     = (const float*)d_in[10];
    const float* lru_ln_g   = (const float*)d_in[12];
    const float* lru_ln_b   = (const float*)d_in[13];
    const float* w1         = (const float*)d_in[14];
    const float* b1         = (const float*)d_in[15];
    const float* w2         = (const float*)d_in[16];
    const float* b2         = (const float*)d_in[17];
    const float* ffn_ln_g   = (const float*)d_in[18];
    const float* ffn_ln_b   = (const float*)d_in[19];
    const int*   item_seq   = (const int*)d_in[20];
    const int*   item_len   = (const int*)d_in[21];
    float* out = (float*)d_out;

    float *px, *ph, *phf, *px2, *pWin, *pbin, *pWout;
    cudaGetSymbolAddress((void**)&px,    g_x);
    cudaGetSymbolAddress((void**)&ph,    g_h);
    cudaGetSymbolAddress((void**)&phf,   g_hf);
    cudaGetSymbolAddress((void**)&px2,   g_x2);
    cudaGetSymbolAddress((void**)&pWin,  g_Win);
    cudaGetSymbolAddress((void**)&pbin,  g_bin);
    cudaGetSymbolAddress((void**)&pWout, g_Wout);

    cudaFuncSetAttribute(hmma_gemm<0>, cudaFuncAttributeMaxDynamicSharedMemorySize, SM_TOT);
    cudaFuncSetAttribute(hmma_gemm<1>, cudaFuncAttributeMaxDynamicSharedMemorySize, SM_TOT);
    cudaFuncSetAttribute(hmma_gemm<2>, cudaFuncAttributeMaxDynamicSharedMemorySize, SM_TOT);
    cudaFuncSetAttribute(fused_inproj_scan, cudaFuncAttributeMaxDynamicSharedMemorySize, F_SMEM);

    embed_kernel<<<dim3(LPAD, BB), 128>>>(token_emb, emb_ln_g, emb_ln_b, item_seq, px);

    for (int li = 0; li < NLAY; li++) {
        pack_kernel<<<512, 256>>>(in_wr, in_wi, in_br, in_bi, out_wr, out_wi, params_log, li);
        // fused in-projection + masked LRU tree scan
        fused_inproj_scan<<<dim3(4, BB), 512, F_SMEM>>>(
            px, pWin, pbin, ph, item_seq, params_log, li);

        if (li == 0) {
            hmma_gemm<2><<<dim3(1, MTOK/128), 256, SM_TOT>>>(
                ph, pWout, out_br + li*DD, px, lru_ln_g + li*DD, lru_ln_b + li*DD,
                px2, MTOK, 128, 512);
            hmma_gemm<1><<<dim3(4, MTOK/128), 256, SM_TOT>>>(
                px2, w1 + (size_t)li*DFF*DD, b1 + li*DFF, nullptr, nullptr, nullptr,
                phf, MTOK, 512, 128);
            hmma_gemm<2><<<dim3(1, MTOK/128), 256, SM_TOT>>>(
                phf, w2 + (size_t)li*DD*DFF, b2 + li*DD, px2, ffn_ln_g + li*DD, ffn_ln_b + li*DD,
                px, MTOK, 128, 512);
        } else {
            gather_kernel<<<BB, 512>>>(ph, px, item_len, phf, px2);
            hmma_gemm<2><<<dim3(1, BB/128), 256, SM_TOT>>>(
                phf, pWout, out_br + li*DD, px2, lru_ln_g + li*DD, lru_ln_b + li*DD,
                ph, BB, 128, 512);
            hmma_gemm<1><<<dim3(4, BB/128), 256, SM_TOT>>>(
                ph, w1 + (size_t)li*DFF*DD, b1 + li*DFF, nullptr, nullptr, nullptr,
                phf, BB, 512, 128);
            hmma_gemm<2><<<dim3(1, BB/128), 256, SM_TOT>>>(
                phf, w2 + (size_t)li*DD*DFF, b2 + li*DD, ph, ffn_ln_g + li*DD, ffn_ln_b + li*DD,
                out, BB, 128, 512);
        }
    }
}

// round 6
// speedup vs baseline: 1.8640x; 1.1213x over previous
#include <cuda_runtime.h>
#include <cuda_bf16.h>
#include <math.h>
#include <stdint.h>

// Problem constants
#define BB   512
#define SS   200
#define DD   128
#define NLAY 2
#define DH   256      // complex hidden (512 reals)
#define DFF  512
#define LPAD 256
#define PAD  56
#define MTOK (BB*LPAD)

typedef __nv_bfloat16 bf16;

// single dynamic-smem symbol shared by all kernels
extern __shared__ __align__(16) char dyn_smem[];

// ---------------- scratch (device globals) ------------------------------------
__device__ float g_x  [MTOK * DD];        // fp32 x (residual for out-proj)
__device__ float g_x2 [MTOK * DD];        // fp32 x2 (residual for ffn2)
__device__ bf16 g_xh [MTOK * DD],  g_xl [MTOK * DD];
__device__ bf16 g_x2h[MTOK * DD],  g_x2l[MTOK * DD];
__device__ bf16 g_hh [MTOK * 2*DH], g_hl [MTOK * 2*DH];
__device__ bf16 g_hfh[MTOK * DFF],  g_hfl[MTOK * DFF];
// packed per-layer weights
__device__ bf16 g_Winh[2*DH*DD], g_Winl[2*DH*DD];
__device__ float g_bin[2*DH];
__device__ bf16 g_Wouth[DD*2*DH], g_Woutl[DD*2*DH];
__device__ bf16 g_w1h[DFF*DD], g_w1l[DFF*DD];
__device__ bf16 g_w2h[DD*DFF], g_w2l[DD*DFF];
// layer-2 tail (gathered, M=BB)
__device__ float g_xg [BB * DD];
__device__ float g_sm1[BB * DD];
__device__ bf16 g_sm1h[BB*DD], g_sm1l[BB*DD];
__device__ bf16 g_sm2h[BB*DFF], g_sm2l[BB*DFF];
__device__ bf16 g_hgh[BB*2*DH], g_hgl[BB*2*DH];

// ---------------- helpers -------------------------------------------------------
__device__ __forceinline__ uint32_t smem_u32(const void* p) {
    uint32_t a;
    asm("{ .reg .u64 t; cvta.to.shared.u64 t, %1; cvt.u32.u64 %0, t; }" : "=r"(a) : "l"(p));
    return a;
}
__device__ __forceinline__ void cp_async16(uint32_t s, const void* g) {
    asm volatile("cp.async.cg.shared.global [%0], [%1], 16;" :: "r"(s), "l"(g));
}
__device__ __forceinline__ void ldsm4(uint32_t (&r)[4], uint32_t addr) {
    asm volatile("ldmatrix.sync.aligned.m8n8.x4.shared.b16 {%0,%1,%2,%3}, [%4];"
                 : "=r"(r[0]), "=r"(r[1]), "=r"(r[2]), "=r"(r[3]) : "r"(addr));
}
__device__ __forceinline__ void mma16816(float* c, const uint32_t* a, uint32_t b0, uint32_t b1) {
    asm volatile("mma.sync.aligned.m16n8k16.row.col.f32.bf16.bf16.f32 "
                 "{%0,%1,%2,%3}, {%4,%5,%6,%7}, {%8,%9}, {%0,%1,%2,%3};"
                 : "+f"(c[0]), "+f"(c[1]), "+f"(c[2]), "+f"(c[3])
                 : "r"(a[0]), "r"(a[1]), "r"(a[2]), "r"(a[3]), "r"(b0), "r"(b1));
}
__device__ __forceinline__ float block128_sum(float v, volatile float* sh) {
    #pragma unroll
    for (int o = 16; o > 0; o >>= 1) v += __shfl_xor_sync(0xffffffffu, v, o);
    __syncthreads();
    if ((threadIdx.x & 31) == 0) sh[threadIdx.x >> 5] = v;
    __syncthreads();
    return sh[0] + sh[1] + sh[2] + sh[3];
}
// store (a,b) as hi/lo bf16 pairs at element index idx (idx even)
__device__ __forceinline__ void pack2(float a, float b, bf16* Hi, bf16* Lo, size_t idx) {
    __nv_bfloat162 h = __floats2bfloat162_rn(a, b);
    __nv_bfloat162 l = __floats2bfloat162_rn(a - __bfloat162float(h.x),
                                             b - __bfloat162float(h.y));
    *reinterpret_cast<__nv_bfloat162*>(Hi + idx) = h;
    *reinterpret_cast<__nv_bfloat162*>(Lo + idx) = l;
}

#define PITCH 144                 // 64 bf16 = 128B + 16B pad (conflict-free ldsm)
#define TILE  (128*PITCH)         // 18432
#define SM_FIX 1536
#define STAGE (4*TILE)            // 73728
#define SM_TOT (SM_FIX + 2*STAGE) // 148992

// ---------------- embedding gather + LN + front-pad ----------------------------
__global__ void embed_kernel(const float* __restrict__ emb,
                             const float* __restrict__ g,
                             const float* __restrict__ bta,
                             const int*   __restrict__ seq,
                             float* __restrict__ x, bf16* __restrict__ xh, bf16* __restrict__ xl) {
    __shared__ float sh[4];
    int b = blockIdx.y, t = blockIdx.x, tid = threadIdx.x;
    size_t o = ((size_t)b * LPAD + t) * DD + tid;
    float r;
    if (t < PAD) {
        r = 0.f;
    } else {
        int item = seq[b * SS + (t - PAD)];
        float v = emb[(size_t)item * DD + tid];
        float mu  = block128_sum(v, sh) * (1.f / DD);
        float d   = v - mu;
        float var = block128_sum(d * d, sh) * (1.f / DD);
        r = d * rsqrtf(var + 1e-5f) * g[tid] + bta[tid];
    }
    x[o] = r;
    bf16 hi = __float2bfloat16(r);
    xh[o] = hi;
    xl[o] = __float2bfloat16(r - __bfloat162float(hi));
}

// ---------------- per-layer weight packing (to split bf16) ----------------------
__global__ void pack_kernel(const float* __restrict__ in_wr, const float* __restrict__ in_wi,
                            const float* __restrict__ in_br, const float* __restrict__ in_bi,
                            const float* __restrict__ out_wr, const float* __restrict__ out_wi,
                            const float* __restrict__ w1, const float* __restrict__ w2,
                            const float* __restrict__ params_log, int li) {
    int idx = blockIdx.x * 256 + threadIdx.x;   // 0 .. 262143
    int mat = idx >> 16, r = idx & 65535;
    float w;
    bf16 *Hi, *Lo;
    if (mat == 0) {
        int n = r >> 7, k = r & 127;
        int d = n >> 1, s = n & 1;
        float gamma = expf(params_log[(li * 3 + 2) * DH + d]);
        w = (s ? in_wi[(size_t)li * DH * DD + d * DD + k]
               : in_wr[(size_t)li * DH * DD + d * DD + k]) * gamma;
        if (k == 0) {
            float bv = s ? in_bi[li * DH + d] : in_br[li * DH + d];
            g_bin[n] = bv * gamma;
        }
        Hi = g_Winh; Lo = g_Winl;
    } else if (mat == 1) {
        int n = r >> 9, k = r & 511;
        int d = k >> 1, s = k & 1;
        w = s ? -out_wi[(size_t)li * DD * DH + n * DH + d]
              :  out_wr[(size_t)li * DD * DH + n * DH + d];
        Hi = g_Wouth; Lo = g_Woutl;
    } else if (mat == 2) {
        w = w1[(size_t)li * DFF * DD + r];
        Hi = g_w1h; Lo = g_w1l;
    } else {
        w = w2[(size_t)li * DD * DFF + r];
        Hi = g_w2h; Lo = g_w2l;
    }
    bf16 hi = __float2bfloat16(w);
    Hi[r] = hi;
    Lo[r] = __float2bfloat16(w - __bfloat162float(hi));
}

// ---------------- gather last valid token --------------------------------------
__global__ void gather_kernel(const bf16* __restrict__ hh, const bf16* __restrict__ hl,
                              const float* __restrict__ x, const int* __restrict__ slen,
                              bf16* __restrict__ hgh, bf16* __restrict__ hgl,
                              float* __restrict__ xg) {
    int b = blockIdx.x, tid = threadIdx.x;
    int t = PAD + slen[b] - 1;
    size_t src = ((size_t)b * LPAD + t) * 512 + tid;
    hgh[(size_t)b * 512 + tid] = hh[src];
    hgl[(size_t)b * 512 + tid] = hl[src];
    if (tid < DD) xg[(size_t)b * DD + tid] = x[((size_t)b * LPAD + t) * DD + tid];
}

// ================= fused in-projection GEMM + masked LRU scan ===================
// Per block: one batch (256 tokens) x 128 interleaved channels (64 complex).
#define FA_TILE (256*PITCH)              // 36864
#define FB_TILE (128*PITCH)              // 18432
#define F_CH   (2*FA_TILE + 2*FB_TILE)   // 110592 per chunk
#define F_SMEM (SM_FIX + 2*F_CH)         // 222720

__global__ void __launch_bounds__(512, 1) fused_inproj_scan(
        const bf16* __restrict__ Axh, const bf16* __restrict__ Axl,
        const bf16* __restrict__ Bwh, const bf16* __restrict__ Bwl,
        const float* __restrict__ bias,
        bf16* __restrict__ hh, bf16* __restrict__ hl,
        const int* __restrict__ seq, const float* __restrict__ params_log, int li) {
    char* sm = dyn_smem;
    float* sBias = (float*)sm;             // [0,512)
    float* ms    = (float*)(sm + 512);     // [512,1536)
    float* buf   = (float*)(sm + SM_FIX);  // overlay after GEMM: 256*128 fp32
    float* lamR  = (float*)(sm + SM_FIX + 131072);
    float* lamI  = lamR + 8192;
    __shared__ float s_nu[64], s_th[64];
    uint32_t sb = smem_u32(sm);

    int tid = threadIdx.x, lane = tid & 31, wid = tid >> 5;
    int q = lane & 3, hrow = lane >> 2;
    int wm = wid & 7, wn = wid >> 3;
    int b = blockIdx.y, cg = blockIdx.x;
    int m0 = b * 256, n0 = cg * 128;

    // async prefetch of both K-chunks
    #pragma unroll
    for (int c = 0; c < 2; c++) {
        int kc = c * 64;
        uint32_t st = sb + SM_FIX + c * F_CH;
        #pragma unroll
        for (int t = 0; t < 4; t++) {           // A: 256 rows x 8 segs x2
            int idx = tid + t * 512;
            int row = idx >> 3, seg = idx & 7;
            uint32_t so = row * PITCH + seg * 16;
            cp_async16(st + so,           Axh + (size_t)(m0 + row) * 128 + kc + seg * 8);
            cp_async16(st + FA_TILE + so, Axl + (size_t)(m0 + row) * 128 + kc + seg * 8);
        }
        #pragma unroll
        for (int t = 0; t < 2; t++) {           // B: 128 rows x 8 segs x2
            int idx = tid + t * 512;
            int row = idx >> 3, seg = idx & 7;
            uint32_t so = row * PITCH + seg * 16;
            cp_async16(st + 2*FA_TILE + so,           Bwh + (size_t)(n0 + row) * 128 + kc + seg * 8);
            cp_async16(st + 2*FA_TILE + FB_TILE + so, Bwl + (size_t)(n0 + row) * 128 + kc + seg * 8);
        }
        asm volatile("cp.async.commit_group;");
    }

    if (tid < 128) sBias[tid] = bias[n0 + tid];
    if (tid >= 256 && tid < 512) {
        int t = tid - 256;
        ms[t] = (t >= PAD && seq[b * SS + t - PAD] > 0) ? 1.f : 0.f;
    }
    if (tid < 64) {
        int d = cg * 64 + tid;
        s_nu[tid] = expf(params_log[(li * 3 + 0) * DH + d]);
        s_th[tid] = expf(params_log[(li * 3 + 1) * DH + d]);
    }

    float acc[2][8][4];
    #pragma unroll
    for (int a1 = 0; a1 < 2; a1++)
        #pragma unroll
        for (int a2 = 0; a2 < 8; a2++)
            #pragma unroll
            for (int a3 = 0; a3 < 4; a3++) acc[a1][a2][a3] = 0.f;

    #pragma unroll
    for (int ch = 0; ch < 2; ch++) {
        if (ch == 0) asm volatile("cp.async.wait_group 1;");
        else         asm volatile("cp.async.wait_group 0;");
        __syncthreads();
        uint32_t st = sb + SM_FIX + ch * F_CH;
        uint32_t aAh = st, aAl = st + FA_TILE, aBh = st + 2*FA_TILE, aBl = aBh + FB_TILE;
        #pragma unroll
        for (int ks = 0; ks < 4; ks++) {
            uint32_t ah[2][4], al[2][4];
            #pragma unroll
            for (int mt = 0; mt < 2; mt++) {
                uint32_t aoff = (uint32_t)((wm*32 + mt*16 + (lane & 15)) * PITCH + ks*32 + (lane >> 4) * 16);
                ldsm4(ah[mt], aAh + aoff);
                ldsm4(al[mt], aAl + aoff);
            }
            #pragma unroll
            for (int nb = 0; nb < 4; nb++) {
                uint32_t boff = (uint32_t)((wn*64 + nb*16 + (lane & 15)) * PITCH + ks*32 + (lane >> 4) * 16);
                uint32_t bh[4], bl[4];
                ldsm4(bh, aBh + boff);
                ldsm4(bl, aBl + boff);
                #pragma unroll
                for (int mt = 0; mt < 2; mt++) {
                    mma16816(acc[mt][2*nb],   ah[mt], bh[0], bh[2]);
                    mma16816(acc[mt][2*nb+1], ah[mt], bh[1], bh[3]);
                    mma16816(acc[mt][2*nb],   al[mt], bh[0], bh[2]);
                    mma16816(acc[mt][2*nb+1], al[mt], bh[1], bh[3]);
                    mma16816(acc[mt][2*nb],   ah[mt], bl[0], bl[2]);
                    mma16816(acc[mt][2*nb+1], ah[mt], bl[1], bl[3]);
                }
            }
        }
    }
    __syncthreads();

    // epilogue -> scan buffer (overlays tiles)
    #pragma unroll
    for (int mt = 0; mt < 2; mt++) {
        int r0 = wm*32 + mt*16 + hrow;
        #pragma unroll
        for (int j = 0; j < 8; j++) {
            int col = wn*64 + j*8 + q*2;
            float b0 = sBias[col], b1 = sBias[col+1];
            *(float2*)&buf[r0*128 + col]     = make_float2(acc[mt][j][0] + b0, acc[mt][j][1] + b1);
            *(float2*)&buf[(r0+8)*128 + col] = make_float2(acc[mt][j][2] + b0, acc[mt][j][3] + b1);
        }
    }
    for (int i = tid; i < 8192; i += 512) {
        int c = i & 63, p = (i >> 6) + 1;
        float mag = expf(-s_nu[c] * (float)p);
        float sv, cv;
        sincosf(s_th[c] * (float)p, &sv, &cv);
        lamR[(p-1)*64 + c] = mag * cv;
        lamI[(p-1)*64 + c] = mag * sv;
    }
    __syncthreads();

    // 8-level masked tree scan over 64 complex channels
    #pragma unroll
    for (int lev = 1; lev <= 8; lev++) {
        int half = 1 << (lev - 1);
        for (int i = tid; i < 8192; i += 512) {
            int c = i & 63, u = i >> 6;
            int blk = u >> (lev - 1);
            int p = (u & (half - 1)) + 1;
            int cpos = blk * (half << 1) + half - 1;
            int t = cpos + p;
            if (ms[cpos] != 0.f) {
                float2 src = *(float2*)&buf[cpos*128 + 2*c];
                float lr = lamR[(p-1)*64 + c], lim = lamI[(p-1)*64 + c];
                float2 dst = *(float2*)&buf[t*128 + 2*c];
                dst.x += lr * src.x - lim * src.y;
                dst.y += lr * src.y + lim * src.x;
                *(float2*)&buf[t*128 + 2*c] = dst;
            }
        }
        __syncthreads();
    }

    // write packed h
    for (int i = tid; i < 8192; i += 512) {
        int t = i >> 5, c4 = i & 31;
        float4 v = *(const float4*)&buf[t*128 + c4*4];
        size_t o = (size_t)(m0 + t) * 512 + n0 + c4*4;
        pack2(v.x, v.y, hh, hl, o);
        pack2(v.z, v.w, hh, hl, o + 2);
    }
}

// ================= pipelined split-bf16 GEMM (warp tile 32x64) ==================
// EPI 1: bias+gelu (Cf may be null). EPI 2: bias+residual+LayerNorm (N==128).
__device__ __forceinline__ void gemm_load_chunk(
        uint32_t st, const bf16* Ah, const bf16* Al, const bf16* Bh, const bf16* Bl,
        int m0, int n0, int kc, int K, int tid) {
    #pragma unroll
    for (int t = 0; t < 4; t++) {
        int idx = tid + t * 256;
        int row = idx >> 3, seg = idx & 7;
        uint32_t so = row * PITCH + seg * 16;
        cp_async16(st + so,          Ah + (size_t)(m0 + row) * K + kc + seg * 8);
        cp_async16(st + TILE + so,   Al + (size_t)(m0 + row) * K + kc + seg * 8);
        cp_async16(st + 2*TILE + so, Bh + (size_t)(n0 + row) * K + kc + seg * 8);
        cp_async16(st + 3*TILE + so, Bl + (size_t)(n0 + row) * K + kc + seg * 8);
    }
}

template<int EPI>
__global__ void __launch_bounds__(256) hmma_gemm(
        const bf16* __restrict__ Ah, const bf16* __restrict__ Al,
        const bf16* __restrict__ Bh, const bf16* __restrict__ Bl,
        const float* __restrict__ bias, const float* __restrict__ Res,
        const float* __restrict__ lng, const float* __restrict__ lnb,
        float* __restrict__ Cf, bf16* __restrict__ Chi, bf16* __restrict__ Clo,
        int M, int N, int K) {
    char* sm = dyn_smem;
    float* sBias = (float*)sm;
    float* sG    = sBias + 128;
    float* sB    = sG + 128;
    float* sred  = (float*)(sm + SM_FIX);   // overlay after mainloop
    uint32_t sb = smem_u32(sm);

    int tid = threadIdx.x, lane = tid & 31, wid = tid >> 5;
    int q = lane & 3, hrow = lane >> 2;
    int wm = wid & 3, wn = wid >> 2;
    int m0 = blockIdx.y * 128, n0 = blockIdx.x * 128;

    if (tid < 128) {
        sBias[tid] = bias[n0 + tid];
        if (EPI == 2) { sG[tid] = lng[n0 + tid]; sB[tid] = lnb[n0 + tid]; }
    }

    float acc[2][8][4];
    #pragma unroll
    for (int a1 = 0; a1 < 2; a1++)
        #pragma unroll
        for (int a2 = 0; a2 < 8; a2++)
            #pragma unroll
            for (int a3 = 0; a3 < 4; a3++) acc[a1][a2][a3] = 0.f;

    int nc = K >> 6;
    gemm_load_chunk(sb + SM_FIX, Ah, Al, Bh, Bl, m0, n0, 0, K, tid);
    asm volatile("cp.async.commit_group;");
    for (int ch = 0; ch < nc; ch++) {
        if (ch + 1 < nc) {
            gemm_load_chunk(sb + SM_FIX + ((ch + 1) & 1) * STAGE,
                            Ah, Al, Bh, Bl, m0, n0, (ch + 1) << 6, K, tid);
            asm volatile("cp.async.commit_group;");
            asm volatile("cp.async.wait_group 1;");
        } else {
            asm volatile("cp.async.wait_group 0;");
        }
        __syncthreads();
        uint32_t st = sb + SM_FIX + (ch & 1) * STAGE;
        uint32_t aAh = st, aAl = st + TILE, aBh = st + 2*TILE, aBl = st + 3*TILE;
        #pragma unroll
        for (int ks = 0; ks < 4; ks++) {
            uint32_t ah[2][4], al[2][4];
            #pragma unroll
            for (int mt = 0; mt < 2; mt++) {
                uint32_t aoff = (uint32_t)((wm*32 + mt*16 + (lane & 15)) * PITCH + ks*32 + (lane >> 4) * 16);
                ldsm4(ah[mt], aAh + aoff);
                ldsm4(al[mt], aAl + aoff);
            }
            #pragma unroll
            for (int nb = 0; nb < 4; nb++) {
                uint32_t boff = (uint32_t)((wn*64 + nb*16 + (lane & 15)) * PITCH + ks*32 + (lane >> 4) * 16);
                uint32_t bh[4], bl[4];
                ldsm4(bh, aBh + boff);
                ldsm4(bl, aBl + boff);
                #pragma unroll
                for (int mt = 0; mt < 2; mt++) {
                    mma16816(acc[mt][2*nb],   ah[mt], bh[0], bh[2]);
                    mma16816(acc[mt][2*nb+1], ah[mt], bh[1], bh[3]);
                    mma16816(acc[mt][2*nb],   al[mt], bh[0], bh[2]);
                    mma16816(acc[mt][2*nb+1], al[mt], bh[1], bh[3]);
                    mma16816(acc[mt][2*nb],   ah[mt], bl[0], bl[2]);
                    mma16816(acc[mt][2*nb+1], ah[mt], bl[1], bl[3]);
                }
            }
        }
        __syncthreads();
    }

    // ---------------- epilogue ----------------
    #pragma unroll
    for (int mt = 0; mt < 2; mt++)
        #pragma unroll
        for (int j = 0; j < 8; j++) {
            int col = wn*64 + j*8 + q*2;
            float b0 = sBias[col], b1 = sBias[col+1];
            acc[mt][j][0] += b0; acc[mt][j][1] += b1;
            acc[mt][j][2] += b0; acc[mt][j][3] += b1;
        }
    if (EPI == 1) {
        #pragma unroll
        for (int mt = 0; mt < 2; mt++)
            #pragma unroll
            for (int j = 0; j < 8; j++)
                #pragma unroll
                for (int v = 0; v < 4; v++)
                    acc[mt][j][v] = 0.5f * acc[mt][j][v] *
                                    (1.f + erff(acc[mt][j][v] * 0.70710678118654752f));
    }
    if (EPI == 2) {
        float mu[2][2], rs[2][2];
        #pragma unroll
        for (int mt = 0; mt < 2; mt++) {
            int r0 = m0 + wm*32 + mt*16 + hrow;
            #pragma unroll
            for (int j = 0; j < 8; j++) {
                int col = wn*64 + j*8 + q*2;
                float2 ra = *(const float2*)(Res + (size_t)r0 * 128 + col);
                float2 rb = *(const float2*)(Res + (size_t)(r0+8) * 128 + col);
                acc[mt][j][0] += ra.x; acc[mt][j][1] += ra.y;
                acc[mt][j][2] += rb.x; acc[mt][j][3] += rb.y;
            }
        }
        float ssum[2][2] = {{0,0},{0,0}}, ssq[2][2] = {{0,0},{0,0}};
        #pragma unroll
        for (int mt = 0; mt < 2; mt++)
            #pragma unroll
            for (int j = 0; j < 8; j++)
                #pragma unroll
                for (int hh = 0; hh < 2; hh++) {
                    float v0 = acc[mt][j][2*hh], v1 = acc[mt][j][2*hh+1];
                    ssum[mt][hh] += v0 + v1;
                    ssq[mt][hh]  += v0*v0 + v1*v1;
                }
        #pragma unroll
        for (int mt = 0; mt < 2; mt++)
            #pragma unroll
            for (int hh = 0; hh < 2; hh++) {
                ssum[mt][hh] += __shfl_xor_sync(0xffffffffu, ssum[mt][hh], 1);
                ssum[mt][hh] += __shfl_xor_sync(0xffffffffu, ssum[mt][hh], 2);
                ssq[mt][hh]  += __shfl_xor_sync(0xffffffffu, ssq[mt][hh], 1);
                ssq[mt][hh]  += __shfl_xor_sync(0xffffffffu, ssq[mt][hh], 2);
            }
        if (q == 0) {
            #pragma unroll
            for (int mt = 0; mt < 2; mt++)
                #pragma unroll
                for (int hh = 0; hh < 2; hh++) {
                    int lr = wm*32 + mt*16 + hrow + hh*8;
                    sred[lr*2 + wn]       = ssum[mt][hh];
                    sred[256 + lr*2 + wn] = ssq[mt][hh];
                }
        }
        __syncthreads();
        #pragma unroll
        for (int mt = 0; mt < 2; mt++)
            #pragma unroll
            for (int hh = 0; hh < 2; hh++) {
                int lr = wm*32 + mt*16 + hrow + hh*8;
                float S  = sred[lr*2] + sred[lr*2 + 1];
                float S2 = sred[256 + lr*2] + sred[256 + lr*2 + 1];
                float m  = S * (1.f/128.f);
                float var = S2 * (1.f/128.f) - m * m;
                mu[mt][hh] = m;
                rs[mt][hh] = rsqrtf(var + 1e-5f);
            }
        #pragma unroll
        for (int mt = 0; mt < 2; mt++)
            #pragma unroll
            for (int j = 0; j < 8; j++) {
                int col = wn*64 + j*8 + q*2;
                float g0 = sG[col], g1 = sG[col+1], bb0 = sB[col], bb1 = sB[col+1];
                acc[mt][j][0] = (acc[mt][j][0] - mu[mt][0]) * rs[mt][0] * g0 + bb0;
                acc[mt][j][1] = (acc[mt][j][1] - mu[mt][0]) * rs[mt][0] * g1 + bb1;
                acc[mt][j][2] = (acc[mt][j][2] - mu[mt][1]) * rs[mt][1] * g0 + bb0;
                acc[mt][j][3] = (acc[mt][j][3] - mu[mt][1]) * rs[mt][1] * g1 + bb1;
            }
    }
    #pragma unroll
    for (int mt = 0; mt < 2; mt++) {
        int r0 = m0 + wm*32 + mt*16 + hrow;
        #pragma unroll
        for (int j = 0; j < 8; j++) {
            int col = n0 + wn*64 + j*8 + q*2;
            if (Cf) {
                *(float2*)(Cf + (size_t)r0 * N + col)     = make_float2(acc[mt][j][0], acc[mt][j][1]);
                *(float2*)(Cf + (size_t)(r0+8) * N + col) = make_float2(acc[mt][j][2], acc[mt][j][3]);
            }
            if (Chi) {
                pack2(acc[mt][j][0], acc[mt][j][1], Chi, Clo, (size_t)r0 * N + col);
                pack2(acc[mt][j][2], acc[mt][j][3], Chi, Clo, (size_t)(r0+8) * N + col);
            }
        }
    }
}

// ---------------- host driver ---------------------------------------------------
extern "C" void kernel_launch(void* const* d_in, const int* in_sizes, int n_in,
                              void* d_out, int out_size) {
    const float* token_emb  = (const float*)d_in[0];
    const float* emb_ln_g   = (const float*)d_in[1];
    const float* emb_ln_b   = (const float*)d_in[2];
    const float* params_log = (const float*)d_in[3];
    const float* in_wr      = (const float*)d_in[4];
    const float* in_wi      = (const float*)d_in[5];
    const float* in_br      = (const float*)d_in[6];
    const float* in_bi      = (const float*)d_in[7];
    const float* out_wr     = (const float*)d_in[8];
    const float* out_wi     = (const float*)d_in[9];
    const float* out_br     = (const float*)d_in[10];
    const float* lru_ln_g   = (const float*)d_in[12];
    const float* lru_ln_b   = (const float*)d_in[13];
    const float* w1         = (const float*)d_in[14];
    const float* b1         = (const float*)d_in[15];
    const float* w2         = (const float*)d_in[16];
    const float* b2         = (const float*)d_in[17];
    const float* ffn_ln_g   = (const float*)d_in[18];
    const float* ffn_ln_b   = (const float*)d_in[19];
    const int*   item_seq   = (const int*)d_in[20];
    const int*   item_len   = (const int*)d_in[21];
    float* out = (float*)d_out;

    float *px, *px2, *pbin, *pxg, *psm1;
    bf16 *pxh, *pxl, *px2h, *px2l, *phh, *phl, *phfh, *phfl;
    bf16 *pWinh, *pWinl, *pWouth, *pWoutl, *pw1h, *pw1l, *pw2h, *pw2l;
    bf16 *psm1h, *psm1l, *psm2h, *psm2l, *phgh, *phgl;
    cudaGetSymbolAddress((void**)&px,    g_x);
    cudaGetSymbolAddress((void**)&px2,   g_x2);
    cudaGetSymbolAddress((void**)&pxh,   g_xh);   cudaGetSymbolAddress((void**)&pxl,   g_xl);
    cudaGetSymbolAddress((void**)&px2h,  g_x2h);  cudaGetSymbolAddress((void**)&px2l,  g_x2l);
    cudaGetSymbolAddress((void**)&phh,   g_hh);   cudaGetSymbolAddress((void**)&phl,   g_hl);
    cudaGetSymbolAddress((void**)&phfh,  g_hfh);  cudaGetSymbolAddress((void**)&phfl,  g_hfl);
    cudaGetSymbolAddress((void**)&pWinh, g_Winh); cudaGetSymbolAddress((void**)&pWinl, g_Winl);
    cudaGetSymbolAddress((void**)&pbin,  g_bin);
    cudaGetSymbolAddress((void**)&pWouth,g_Wouth);cudaGetSymbolAddress((void**)&pWoutl,g_Woutl);
    cudaGetSymbolAddress((void**)&pw1h,  g_w1h);  cudaGetSymbolAddress((void**)&pw1l,  g_w1l);
    cudaGetSymbolAddress((void**)&pw2h,  g_w2h);  cudaGetSymbolAddress((void**)&pw2l,  g_w2l);
    cudaGetSymbolAddress((void**)&pxg,   g_xg);
    cudaGetSymbolAddress((void**)&psm1,  g_sm1);
    cudaGetSymbolAddress((void**)&psm1h, g_sm1h); cudaGetSymbolAddress((void**)&psm1l, g_sm1l);
    cudaGetSymbolAddress((void**)&psm2h, g_sm2h); cudaGetSymbolAddress((void**)&psm2l, g_sm2l);
    cudaGetSymbolAddress((void**)&phgh,  g_hgh);  cudaGetSymbolAddress((void**)&phgl,  g_hgl);

    cudaFuncSetAttribute(hmma_gemm<1>, cudaFuncAttributeMaxDynamicSharedMemorySize, SM_TOT);
    cudaFuncSetAttribute(hmma_gemm<2>, cudaFuncAttributeMaxDynamicSharedMemorySize, SM_TOT);
    cudaFuncSetAttribute(fused_inproj_scan, cudaFuncAttributeMaxDynamicSharedMemorySize, F_SMEM);

    embed_kernel<<<dim3(LPAD, BB), 128>>>(token_emb, emb_ln_g, emb_ln_b, item_seq, px, pxh, pxl);

    for (int li = 0; li < NLAY; li++) {
        pack_kernel<<<1024, 256>>>(in_wr, in_wi, in_br, in_bi, out_wr, out_wi,
                                   w1, w2, params_log, li);
        fused_inproj_scan<<<dim3(4, BB), 512, F_SMEM>>>(
            pxh, pxl, pWinh, pWinl, pbin, phh, phl, item_seq, params_log, li);

        if (li == 0) {
            hmma_gemm<2><<<dim3(1, MTOK/128), 256, SM_TOT>>>(
                phh, phl, pWouth, pWoutl, out_br + li*DD, px,
                lru_ln_g + li*DD, lru_ln_b + li*DD,
                px2, px2h, px2l, MTOK, 128, 512);
            hmma_gemm<1><<<dim3(4, MTOK/128), 256, SM_TOT>>>(
                px2h, px2l, pw1h, pw1l, b1 + li*DFF, nullptr, nullptr, nullptr,
                nullptr, phfh, phfl, MTOK, 512, 128);
            hmma_gemm<2><<<dim3(1, MTOK/128), 256, SM_TOT>>>(
                phfh, phfl, pw2h, pw2l, b2 + li*DD, px2,
                ffn_ln_g + li*DD, ffn_ln_b + li*DD,
                px, pxh, pxl, MTOK, 128, 512);
        } else {
            gather_kernel<<<BB, 512>>>(phh, phl, px, item_len, phgh, phgl, pxg);
            hmma_gemm<2><<<dim3(1, BB/128), 256, SM_TOT>>>(
                phgh, phgl, pWouth, pWoutl, out_br + li*DD, pxg,
                lru_ln_g + li*DD, lru_ln_b + li*DD,
                psm1, psm1h, psm1l, BB, 128, 512);
            hmma_gemm<1><<<dim3(4, BB/128), 256, SM_TOT>>>(
                psm1h, psm1l, pw1h, pw1l, b1 + li*DFF, nullptr, nullptr, nullptr,
                nullptr, psm2h, psm2l, BB, 512, 128);
            hmma_gemm<2><<<dim3(1, BB/128), 256, SM_TOT>>>(
                psm2h, psm2l, pw2h, pw2l, b2 + li*DD, psm1,
                ffn_ln_g + li*DD, ffn_ln_b + li*DD,
                out, nullptr, nullptr, BB, 128, 512);
        }
    }
}

// round 7
// speedup vs baseline: 1.9439x; 1.0429x over previous
#include <cuda_runtime.h>
#include <cuda_bf16.h>
#include <math.h>
#include <stdint.h>

// Problem constants
#define BB   512
#define SS   200
#define DD   128
#define NLAY 2
#define DH   256      // complex hidden (512 reals)
#define DFF  512
#define LPAD 256
#define PAD  56
#define MTOK (BB*LPAD)

typedef __nv_bfloat16 bf16;

// single dynamic-smem symbol shared by all kernels
extern __shared__ __align__(16) char dyn_smem[];

// ---------------- scratch (device globals) ------------------------------------
__device__ float g_x  [MTOK * DD];        // fp32 x (residual for out-proj)
__device__ float g_x2 [MTOK * DD];        // fp32 x2 (residual for ffn2)
__device__ bf16 g_xh [MTOK * DD],  g_xl [MTOK * DD];
__device__ bf16 g_x2h[MTOK * DD],  g_x2l[MTOK * DD];
__device__ bf16 g_hh [MTOK * 2*DH], g_hl [MTOK * 2*DH];
__device__ bf16 g_hfh[MTOK * DFF],  g_hfl[MTOK * DFF];
// packed per-layer weights
__device__ bf16 g_Winh[2*DH*DD], g_Winl[2*DH*DD];
__device__ float g_bin[2*DH];
__device__ bf16 g_Wouth[DD*2*DH], g_Woutl[DD*2*DH];
__device__ bf16 g_w1h[DFF*DD], g_w1l[DFF*DD];
__device__ bf16 g_w2h[DD*DFF], g_w2l[DD*DFF];
// layer-2 tail (gathered, M=BB)
__device__ float g_xg [BB * DD];
__device__ float g_sm1[BB * DD];
__device__ bf16 g_sm1h[BB*DD], g_sm1l[BB*DD];
__device__ bf16 g_sm2h[BB*DFF], g_sm2l[BB*DFF];
__device__ bf16 g_hgh[BB*2*DH], g_hgl[BB*2*DH];

// ---------------- helpers -------------------------------------------------------
__device__ __forceinline__ uint32_t smem_u32(const void* p) {
    uint32_t a;
    asm("{ .reg .u64 t; cvta.to.shared.u64 t, %1; cvt.u32.u64 %0, t; }" : "=r"(a) : "l"(p));
    return a;
}
__device__ __forceinline__ void cp_async16(uint32_t s, const void* g) {
    asm volatile("cp.async.cg.shared.global [%0], [%1], 16;" :: "r"(s), "l"(g));
}
__device__ __forceinline__ void ldsm4(uint32_t (&r)[4], uint32_t addr) {
    asm volatile("ldmatrix.sync.aligned.m8n8.x4.shared.b16 {%0,%1,%2,%3}, [%4];"
                 : "=r"(r[0]), "=r"(r[1]), "=r"(r[2]), "=r"(r[3]) : "r"(addr));
}
__device__ __forceinline__ void mma16816(float* c, const uint32_t* a, uint32_t b0, uint32_t b1) {
    asm volatile("mma.sync.aligned.m16n8k16.row.col.f32.bf16.bf16.f32 "
                 "{%0,%1,%2,%3}, {%4,%5,%6,%7}, {%8,%9}, {%0,%1,%2,%3};"
                 : "+f"(c[0]), "+f"(c[1]), "+f"(c[2]), "+f"(c[3])
                 : "r"(a[0]), "r"(a[1]), "r"(a[2]), "r"(a[3]), "r"(b0), "r"(b1));
}
__device__ __forceinline__ float block128_sum(float v, volatile float* sh) {
    #pragma unroll
    for (int o = 16; o > 0; o >>= 1) v += __shfl_xor_sync(0xffffffffu, v, o);
    __syncthreads();
    if ((threadIdx.x & 31) == 0) sh[threadIdx.x >> 5] = v;
    __syncthreads();
    return sh[0] + sh[1] + sh[2] + sh[3];
}
// store (a,b) as hi/lo bf16 pairs at element index idx (idx even)
__device__ __forceinline__ void pack2(float a, float b, bf16* Hi, bf16* Lo, size_t idx) {
    __nv_bfloat162 h = __floats2bfloat162_rn(a, b);
    __nv_bfloat162 l = __floats2bfloat162_rn(a - __bfloat162float(h.x),
                                             b - __bfloat162float(h.y));
    *reinterpret_cast<__nv_bfloat162*>(Hi + idx) = h;
    *reinterpret_cast<__nv_bfloat162*>(Lo + idx) = l;
}

#define PITCH 144                 // fused kernel: 64 bf16 = 128B + 16B pad
#define SM_FIX 1536

// GEMM kernel: BK=32 tiles
#define GP     80                 // 32 bf16 = 64B + 16B pad (conflict-free ldsm)
#define GTILE  (128*GP)           // 10240
#define GSTAGE (4*GTILE)          // 40960
#define GSM_TOT (SM_FIX + 2*GSTAGE) // 83456 -> 2 CTAs/SM

// ---------------- embedding gather + LN + front-pad ----------------------------
__global__ void embed_kernel(const float* __restrict__ emb,
                             const float* __restrict__ g,
                             const float* __restrict__ bta,
                             const int*   __restrict__ seq,
                             float* __restrict__ x, bf16* __restrict__ xh, bf16* __restrict__ xl) {
    __shared__ float sh[4];
    int b = blockIdx.y, t = blockIdx.x, tid = threadIdx.x;
    size_t o = ((size_t)b * LPAD + t) * DD + tid;
    float r;
    if (t < PAD) {
        r = 0.f;
    } else {
        int item = seq[b * SS + (t - PAD)];
        float v = emb[(size_t)item * DD + tid];
        float mu  = block128_sum(v, sh) * (1.f / DD);
        float d   = v - mu;
        float var = block128_sum(d * d, sh) * (1.f / DD);
        r = d * rsqrtf(var + 1e-5f) * g[tid] + bta[tid];
    }
    x[o] = r;
    bf16 hi = __float2bfloat16(r);
    xh[o] = hi;
    xl[o] = __float2bfloat16(r - __bfloat162float(hi));
}

// ---------------- per-layer weight packing (to split bf16) ----------------------
__global__ void pack_kernel(const float* __restrict__ in_wr, const float* __restrict__ in_wi,
                            const float* __restrict__ in_br, const float* __restrict__ in_bi,
                            const float* __restrict__ out_wr, const float* __restrict__ out_wi,
                            const float* __restrict__ w1, const float* __restrict__ w2,
                            const float* __restrict__ params_log, int li) {
    int idx = blockIdx.x * 256 + threadIdx.x;   // 0 .. 262143
    int mat = idx >> 16, r = idx & 65535;
    float w;
    bf16 *Hi, *Lo;
    if (mat == 0) {
        int n = r >> 7, k = r & 127;
        int d = n >> 1, s = n & 1;
        float gamma = expf(params_log[(li * 3 + 2) * DH + d]);
        w = (s ? in_wi[(size_t)li * DH * DD + d * DD + k]
               : in_wr[(size_t)li * DH * DD + d * DD + k]) * gamma;
        if (k == 0) {
            float bv = s ? in_bi[li * DH + d] : in_br[li * DH + d];
            g_bin[n] = bv * gamma;
        }
        Hi = g_Winh; Lo = g_Winl;
    } else if (mat == 1) {
        int n = r >> 9, k = r & 511;
        int d = k >> 1, s = k & 1;
        w = s ? -out_wi[(size_t)li * DD * DH + n * DH + d]
              :  out_wr[(size_t)li * DD * DH + n * DH + d];
        Hi = g_Wouth; Lo = g_Woutl;
    } else if (mat == 2) {
        w = w1[(size_t)li * DFF * DD + r];
        Hi = g_w1h; Lo = g_w1l;
    } else {
        w = w2[(size_t)li * DD * DFF + r];
        Hi = g_w2h; Lo = g_w2l;
    }
    bf16 hi = __float2bfloat16(w);
    Hi[r] = hi;
    Lo[r] = __float2bfloat16(w - __bfloat162float(hi));
}

// ---------------- gather last valid token --------------------------------------
__global__ void gather_kernel(const bf16* __restrict__ hh, const bf16* __restrict__ hl,
                              const float* __restrict__ x, const int* __restrict__ slen,
                              bf16* __restrict__ hgh, bf16* __restrict__ hgl,
                              float* __restrict__ xg) {
    int b = blockIdx.x, tid = threadIdx.x;
    int t = PAD + slen[b] - 1;
    size_t src = ((size_t)b * LPAD + t) * 512 + tid;
    hgh[(size_t)b * 512 + tid] = hh[src];
    hgl[(size_t)b * 512 + tid] = hl[src];
    if (tid < DD) xg[(size_t)b * DD + tid] = x[((size_t)b * LPAD + t) * DD + tid];
}

// ================= fused in-projection GEMM + masked LRU scan ===================
// Per block: one batch (256 tokens) x 128 interleaved channels (64 complex).
#define FA_TILE (256*PITCH)              // 36864
#define FB_TILE (128*PITCH)              // 18432
#define F_CH   (2*FA_TILE + 2*FB_TILE)   // 110592 per chunk
#define F_SMEM (SM_FIX + 2*F_CH)         // 222720

__global__ void __launch_bounds__(512, 1) fused_inproj_scan(
        const bf16* __restrict__ Axh, const bf16* __restrict__ Axl,
        const bf16* __restrict__ Bwh, const bf16* __restrict__ Bwl,
        const float* __restrict__ bias,
        bf16* __restrict__ hh, bf16* __restrict__ hl,
        const int* __restrict__ seq, const float* __restrict__ params_log, int li) {
    char* sm = dyn_smem;
    float* sBias = (float*)sm;             // [0,512)
    float* ms    = (float*)(sm + 512);     // [512,1536)
    float* buf   = (float*)(sm + SM_FIX);  // overlay after GEMM: 256*128 fp32
    float* lamR  = (float*)(sm + SM_FIX + 131072);
    float* lamI  = lamR + 8192;
    __shared__ float s_nu[64], s_th[64];
    uint32_t sb = smem_u32(sm);

    int tid = threadIdx.x, lane = tid & 31, wid = tid >> 5;
    int q = lane & 3, hrow = lane >> 2;
    int wm = wid & 7, wn = wid >> 3;
    int b = blockIdx.y, cg = blockIdx.x;
    int m0 = b * 256, n0 = cg * 128;

    // async prefetch of both K-chunks
    #pragma unroll
    for (int c = 0; c < 2; c++) {
        int kc = c * 64;
        uint32_t st = sb + SM_FIX + c * F_CH;
        #pragma unroll
        for (int t = 0; t < 4; t++) {           // A: 256 rows x 8 segs x2
            int idx = tid + t * 512;
            int row = idx >> 3, seg = idx & 7;
            uint32_t so = row * PITCH + seg * 16;
            cp_async16(st + so,           Axh + (size_t)(m0 + row) * 128 + kc + seg * 8);
            cp_async16(st + FA_TILE + so, Axl + (size_t)(m0 + row) * 128 + kc + seg * 8);
        }
        #pragma unroll
        for (int t = 0; t < 2; t++) {           // B: 128 rows x 8 segs x2
            int idx = tid + t * 512;
            int row = idx >> 3, seg = idx & 7;
            uint32_t so = row * PITCH + seg * 16;
            cp_async16(st + 2*FA_TILE + so,           Bwh + (size_t)(n0 + row) * 128 + kc + seg * 8);
            cp_async16(st + 2*FA_TILE + FB_TILE + so, Bwl + (size_t)(n0 + row) * 128 + kc + seg * 8);
        }
        asm volatile("cp.async.commit_group;");
    }

    if (tid < 128) sBias[tid] = bias[n0 + tid];
    if (tid >= 256 && tid < 512) {
        int t = tid - 256;
        ms[t] = (t >= PAD && seq[b * SS + t - PAD] > 0) ? 1.f : 0.f;
    }
    if (tid < 64) {
        int d = cg * 64 + tid;
        s_nu[tid] = expf(params_log[(li * 3 + 0) * DH + d]);
        s_th[tid] = expf(params_log[(li * 3 + 1) * DH + d]);
    }

    float acc[2][8][4];
    #pragma unroll
    for (int a1 = 0; a1 < 2; a1++)
        #pragma unroll
        for (int a2 = 0; a2 < 8; a2++)
            #pragma unroll
            for (int a3 = 0; a3 < 4; a3++) acc[a1][a2][a3] = 0.f;

    #pragma unroll
    for (int ch = 0; ch < 2; ch++) {
        if (ch == 0) asm volatile("cp.async.wait_group 1;");
        else         asm volatile("cp.async.wait_group 0;");
        __syncthreads();
        uint32_t st = sb + SM_FIX + ch * F_CH;
        uint32_t aAh = st, aAl = st + FA_TILE, aBh = st + 2*FA_TILE, aBl = aBh + FB_TILE;
        #pragma unroll
        for (int ks = 0; ks < 4; ks++) {
            uint32_t ah[2][4], al[2][4];
            #pragma unroll
            for (int mt = 0; mt < 2; mt++) {
                uint32_t aoff = (uint32_t)((wm*32 + mt*16 + (lane & 15)) * PITCH + ks*32 + (lane >> 4) * 16);
                ldsm4(ah[mt], aAh + aoff);
                ldsm4(al[mt], aAl + aoff);
            }
            #pragma unroll
            for (int nb = 0; nb < 4; nb++) {
                uint32_t boff = (uint32_t)((wn*64 + nb*16 + (lane & 15)) * PITCH + ks*32 + (lane >> 4) * 16);
                uint32_t bh[4], bl[4];
                ldsm4(bh, aBh + boff);
                ldsm4(bl, aBl + boff);
                #pragma unroll
                for (int mt = 0; mt < 2; mt++) {
                    mma16816(acc[mt][2*nb],   ah[mt], bh[0], bh[2]);
                    mma16816(acc[mt][2*nb+1], ah[mt], bh[1], bh[3]);
                    mma16816(acc[mt][2*nb],   al[mt], bh[0], bh[2]);
                    mma16816(acc[mt][2*nb+1], al[mt], bh[1], bh[3]);
                    mma16816(acc[mt][2*nb],   ah[mt], bl[0], bl[2]);
                    mma16816(acc[mt][2*nb+1], ah[mt], bl[1], bl[3]);
                }
            }
        }
    }
    __syncthreads();

    // epilogue -> scan buffer (overlays tiles)
    #pragma unroll
    for (int mt = 0; mt < 2; mt++) {
        int r0 = wm*32 + mt*16 + hrow;
        #pragma unroll
        for (int j = 0; j < 8; j++) {
            int col = wn*64 + j*8 + q*2;
            float b0 = sBias[col], b1 = sBias[col+1];
            *(float2*)&buf[r0*128 + col]     = make_float2(acc[mt][j][0] + b0, acc[mt][j][1] + b1);
            *(float2*)&buf[(r0+8)*128 + col] = make_float2(acc[mt][j][2] + b0, acc[mt][j][3] + b1);
        }
    }
    for (int i = tid; i < 8192; i += 512) {
        int c = i & 63, p = (i >> 6) + 1;
        float mag = expf(-s_nu[c] * (float)p);
        float sv, cv;
        sincosf(s_th[c] * (float)p, &sv, &cv);
        lamR[(p-1)*64 + c] = mag * cv;
        lamI[(p-1)*64 + c] = mag * sv;
    }
    __syncthreads();

    // 8-level masked tree scan over 64 complex channels
    #pragma unroll
    for (int lev = 1; lev <= 8; lev++) {
        int half = 1 << (lev - 1);
        for (int i = tid; i < 8192; i += 512) {
            int c = i & 63, u = i >> 6;
            int blk = u >> (lev - 1);
            int p = (u & (half - 1)) + 1;
            int cpos = blk * (half << 1) + half - 1;
            int t = cpos + p;
            if (ms[cpos] != 0.f) {
                float2 src = *(float2*)&buf[cpos*128 + 2*c];
                float lr = lamR[(p-1)*64 + c], lim = lamI[(p-1)*64 + c];
                float2 dst = *(float2*)&buf[t*128 + 2*c];
                dst.x += lr * src.x - lim * src.y;
                dst.y += lr * src.y + lim * src.x;
                *(float2*)&buf[t*128 + 2*c] = dst;
            }
        }
        __syncthreads();
    }

    // write packed h
    for (int i = tid; i < 8192; i += 512) {
        int t = i >> 5, c4 = i & 31;
        float4 v = *(const float4*)&buf[t*128 + c4*4];
        size_t o = (size_t)(m0 + t) * 512 + n0 + c4*4;
        pack2(v.x, v.y, hh, hl, o);
        pack2(v.z, v.w, hh, hl, o + 2);
    }
}

// ================= pipelined split-bf16 GEMM (BK=32, 2 CTAs/SM) =================
// EPI 1: bias+gelu (Cf may be null). EPI 2: bias+residual+LayerNorm (N==128).
__device__ __forceinline__ void gemm_load_chunk(
        uint32_t st, const bf16* Ah, const bf16* Al, const bf16* Bh, const bf16* Bl,
        int m0, int n0, int kc, int K, int tid) {
    #pragma unroll
    for (int t = 0; t < 2; t++) {
        int idx = tid + t * 256;       // 0..511
        int row = idx >> 2, seg = idx & 3;
        uint32_t so = row * GP + seg * 16;
        cp_async16(st + so,           Ah + (size_t)(m0 + row) * K + kc + seg * 8);
        cp_async16(st + GTILE + so,   Al + (size_t)(m0 + row) * K + kc + seg * 8);
        cp_async16(st + 2*GTILE + so, Bh + (size_t)(n0 + row) * K + kc + seg * 8);
        cp_async16(st + 3*GTILE + so, Bl + (size_t)(n0 + row) * K + kc + seg * 8);
    }
}

template<int EPI>
__global__ void __launch_bounds__(256, 2) hmma_gemm(
        const bf16* __restrict__ Ah, const bf16* __restrict__ Al,
        const bf16* __restrict__ Bh, const bf16* __restrict__ Bl,
        const float* __restrict__ bias, const float* __restrict__ Res,
        const float* __restrict__ lng, const float* __restrict__ lnb,
        float* __restrict__ Cf, bf16* __restrict__ Chi, bf16* __restrict__ Clo,
        int M, int N, int K) {
    char* sm = dyn_smem;
    float* sBias = (float*)sm;
    float* sG    = sBias + 128;
    float* sB    = sG + 128;
    float* sred  = (float*)(sm + SM_FIX);   // overlay after mainloop
    uint32_t sb = smem_u32(sm);

    int tid = threadIdx.x, lane = tid & 31, wid = tid >> 5;
    int q = lane & 3, hrow = lane >> 2;
    int wm = wid & 3, wn = wid >> 2;
    int m0 = blockIdx.y * 128, n0 = blockIdx.x * 128;

    if (tid < 128) {
        sBias[tid] = bias[n0 + tid];
        if (EPI == 2) { sG[tid] = lng[n0 + tid]; sB[tid] = lnb[n0 + tid]; }
    }

    float acc[2][8][4];
    #pragma unroll
    for (int a1 = 0; a1 < 2; a1++)
        #pragma unroll
        for (int a2 = 0; a2 < 8; a2++)
            #pragma unroll
            for (int a3 = 0; a3 < 4; a3++) acc[a1][a2][a3] = 0.f;

    int nc = K >> 5;
    gemm_load_chunk(sb + SM_FIX, Ah, Al, Bh, Bl, m0, n0, 0, K, tid);
    asm volatile("cp.async.commit_group;");
    for (int ch = 0; ch < nc; ch++) {
        if (ch + 1 < nc) {
            gemm_load_chunk(sb + SM_FIX + ((ch + 1) & 1) * GSTAGE,
                            Ah, Al, Bh, Bl, m0, n0, (ch + 1) << 5, K, tid);
            asm volatile("cp.async.commit_group;");
            asm volatile("cp.async.wait_group 1;");
        } else {
            asm volatile("cp.async.wait_group 0;");
        }
        __syncthreads();
        uint32_t st = sb + SM_FIX + (ch & 1) * GSTAGE;
        uint32_t aAh = st, aAl = st + GTILE, aBh = st + 2*GTILE, aBl = st + 3*GTILE;
        #pragma unroll
        for (int ks = 0; ks < 2; ks++) {
            uint32_t ah[2][4], al[2][4];
            #pragma unroll
            for (int mt = 0; mt < 2; mt++) {
                uint32_t aoff = (uint32_t)((wm*32 + mt*16 + (lane & 15)) * GP + ks*32 + (lane >> 4) * 16);
                ldsm4(ah[mt], aAh + aoff);
                ldsm4(al[mt], aAl + aoff);
            }
            #pragma unroll
            for (int nb = 0; nb < 4; nb++) {
                uint32_t boff = (uint32_t)((wn*64 + nb*16 + (lane & 15)) * GP + ks*32 + (lane >> 4) * 16);
                uint32_t bh[4], bl[4];
                ldsm4(bh, aBh + boff);
                ldsm4(bl, aBl + boff);
                #pragma unroll
                for (int mt = 0; mt < 2; mt++) {
                    mma16816(acc[mt][2*nb],   ah[mt], bh[0], bh[2]);
                    mma16816(acc[mt][2*nb+1], ah[mt], bh[1], bh[3]);
                    mma16816(acc[mt][2*nb],   al[mt], bh[0], bh[2]);
                    mma16816(acc[mt][2*nb+1], al[mt], bh[1], bh[3]);
                    mma16816(acc[mt][2*nb],   ah[mt], bl[0], bl[2]);
                    mma16816(acc[mt][2*nb+1], ah[mt], bl[1], bl[3]);
                }
            }
        }
        __syncthreads();
    }

    // ---------------- epilogue ----------------
    #pragma unroll
    for (int mt = 0; mt < 2; mt++)
        #pragma unroll
        for (int j = 0; j < 8; j++) {
            int col = wn*64 + j*8 + q*2;
            float b0 = sBias[col], b1 = sBias[col+1];
            acc[mt][j][0] += b0; acc[mt][j][1] += b1;
            acc[mt][j][2] += b0; acc[mt][j][3] += b1;
        }
    if (EPI == 1) {
        #pragma unroll
        for (int mt = 0; mt < 2; mt++)
            #pragma unroll
            for (int j = 0; j < 8; j++)
                #pragma unroll
                for (int v = 0; v < 4; v++)
                    acc[mt][j][v] = 0.5f * acc[mt][j][v] *
                                    (1.f + erff(acc[mt][j][v] * 0.70710678118654752f));
    }
    if (EPI == 2) {
        float mu[2][2], rs[2][2];
        #pragma unroll
        for (int mt = 0; mt < 2; mt++) {
            int r0 = m0 + wm*32 + mt*16 + hrow;
            #pragma unroll
            for (int j = 0; j < 8; j++) {
                int col = wn*64 + j*8 + q*2;
                float2 ra = *(const float2*)(Res + (size_t)r0 * 128 + col);
                float2 rb = *(const float2*)(Res + (size_t)(r0+8) * 128 + col);
                acc[mt][j][0] += ra.x; acc[mt][j][1] += ra.y;
                acc[mt][j][2] += rb.x; acc[mt][j][3] += rb.y;
            }
        }
        float ssum[2][2] = {{0,0},{0,0}}, ssq[2][2] = {{0,0},{0,0}};
        #pragma unroll
        for (int mt = 0; mt < 2; mt++)
            #pragma unroll
            for (int j = 0; j < 8; j++)
                #pragma unroll
                for (int hh = 0; hh < 2; hh++) {
                    float v0 = acc[mt][j][2*hh], v1 = acc[mt][j][2*hh+1];
                    ssum[mt][hh] += v0 + v1;
                    ssq[mt][hh]  += v0*v0 + v1*v1;
                }
        #pragma unroll
        for (int mt = 0; mt < 2; mt++)
            #pragma unroll
            for (int hh = 0; hh < 2; hh++) {
                ssum[mt][hh] += __shfl_xor_sync(0xffffffffu, ssum[mt][hh], 1);
                ssum[mt][hh] += __shfl_xor_sync(0xffffffffu, ssum[mt][hh], 2);
                ssq[mt][hh]  += __shfl_xor_sync(0xffffffffu, ssq[mt][hh], 1);
                ssq[mt][hh]  += __shfl_xor_sync(0xffffffffu, ssq[mt][hh], 2);
            }
        if (q == 0) {
            #pragma unroll
            for (int mt = 0; mt < 2; mt++)
                #pragma unroll
                for (int hh = 0; hh < 2; hh++) {
                    int lr = wm*32 + mt*16 + hrow + hh*8;
                    sred[lr*2 + wn]       = ssum[mt][hh];
                    sred[256 + lr*2 + wn] = ssq[mt][hh];
                }
        }
        __syncthreads();
        #pragma unroll
        for (int mt = 0; mt < 2; mt++)
            #pragma unroll
            for (int hh = 0; hh < 2; hh++) {
                int lr = wm*32 + mt*16 + hrow + hh*8;
                float S  = sred[lr*2] + sred[lr*2 + 1];
                float S2 = sred[256 + lr*2] + sred[256 + lr*2 + 1];
                float m  = S * (1.f/128.f);
                float var = S2 * (1.f/128.f) - m * m;
                mu[mt][hh] = m;
                rs[mt][hh] = rsqrtf(var + 1e-5f);
            }
        #pragma unroll
        for (int mt = 0; mt < 2; mt++)
            #pragma unroll
            for (int j = 0; j < 8; j++) {
                int col = wn*64 + j*8 + q*2;
                float g0 = sG[col], g1 = sG[col+1], bb0 = sB[col], bb1 = sB[col+1];
                acc[mt][j][0] = (acc[mt][j][0] - mu[mt][0]) * rs[mt][0] * g0 + bb0;
                acc[mt][j][1] = (acc[mt][j][1] - mu[mt][0]) * rs[mt][0] * g1 + bb1;
                acc[mt][j][2] = (acc[mt][j][2] - mu[mt][1]) * rs[mt][1] * g0 + bb0;
                acc[mt][j][3] = (acc[mt][j][3] - mu[mt][1]) * rs[mt][1] * g1 + bb1;
            }
    }
    #pragma unroll
    for (int mt = 0; mt < 2; mt++) {
        int r0 = m0 + wm*32 + mt*16 + hrow;
        #pragma unroll
        for (int j = 0; j < 8; j++) {
            int col = n0 + wn*64 + j*8 + q*2;
            if (Cf) {
                *(float2*)(Cf + (size_t)r0 * N + col)     = make_float2(acc[mt][j][0], acc[mt][j][1]);
                *(float2*)(Cf + (size_t)(r0+8) * N + col) = make_float2(acc[mt][j][2], acc[mt][j][3]);
            }
            if (Chi) {
                pack2(acc[mt][j][0], acc[mt][j][1], Chi, Clo, (size_t)r0 * N + col);
                pack2(acc[mt][j][2], acc[mt][j][3], Chi, Clo, (size_t)(r0+8) * N + col);
            }
        }
    }
}

// ---------------- host driver ---------------------------------------------------
extern "C" void kernel_launch(void* const* d_in, const int* in_sizes, int n_in,
                              void* d_out, int out_size) {
    const float* token_emb  = (const float*)d_in[0];
    const float* emb_ln_g   = (const float*)d_in[1];
    const float* emb_ln_b   = (const float*)d_in[2];
    const float* params_log = (const float*)d_in[3];
    const float* in_wr      = (const float*)d_in[4];
    const float* in_wi      = (const float*)d_in[5];
    const float* in_br      = (const float*)d_in[6];
    const float* in_bi      = (const float*)d_in[7];
    const float* out_wr     = (const float*)d_in[8];
    const float* out_wi     = (const float*)d_in[9];
    const float* out_br     = (const float*)d_in[10];
    const float* lru_ln_g   = (const float*)d_in[12];
    const float* lru_ln_b   = (const float*)d_in[13];
    const float* w1         = (const float*)d_in[14];
    const float* b1         = (const float*)d_in[15];
    const float* w2         = (const float*)d_in[16];
    const float* b2         = (const float*)d_in[17];
    const float* ffn_ln_g   = (const float*)d_in[18];
    const float* ffn_ln_b   = (const float*)d_in[19];
    const int*   item_seq   = (const int*)d_in[20];
    const int*   item_len   = (const int*)d_in[21];
    float* out = (float*)d_out;

    float *px, *px2, *pbin, *pxg, *psm1;
    bf16 *pxh, *pxl, *px2h, *px2l, *phh, *phl, *phfh, *phfl;
    bf16 *pWinh, *pWinl, *pWouth, *pWoutl, *pw1h, *pw1l, *pw2h, *pw2l;
    bf16 *psm1h, *psm1l, *psm2h, *psm2l, *phgh, *phgl;
    cudaGetSymbolAddress((void**)&px,    g_x);
    cudaGetSymbolAddress((void**)&px2,   g_x2);
    cudaGetSymbolAddress((void**)&pxh,   g_xh);   cudaGetSymbolAddress((void**)&pxl,   g_xl);
    cudaGetSymbolAddress((void**)&px2h,  g_x2h);  cudaGetSymbolAddress((void**)&px2l,  g_x2l);
    cudaGetSymbolAddress((void**)&phh,   g_hh);   cudaGetSymbolAddress((void**)&phl,   g_hl);
    cudaGetSymbolAddress((void**)&phfh,  g_hfh);  cudaGetSymbolAddress((void**)&phfl,  g_hfl);
    cudaGetSymbolAddress((void**)&pWinh, g_Winh); cudaGetSymbolAddress((void**)&pWinl, g_Winl);
    cudaGetSymbolAddress((void**)&pbin,  g_bin);
    cudaGetSymbolAddress((void**)&pWouth,g_Wouth);cudaGetSymbolAddress((void**)&pWoutl,g_Woutl);
    cudaGetSymbolAddress((void**)&pw1h,  g_w1h);  cudaGetSymbolAddress((void**)&pw1l,  g_w1l);
    cudaGetSymbolAddress((void**)&pw2h,  g_w2h);  cudaGetSymbolAddress((void**)&pw2l,  g_w2l);
    cudaGetSymbolAddress((void**)&pxg,   g_xg);
    cudaGetSymbolAddress((void**)&psm1,  g_sm1);
    cudaGetSymbolAddress((void**)&psm1h, g_sm1h); cudaGetSymbolAddress((void**)&psm1l, g_sm1l);
    cudaGetSymbolAddress((void**)&psm2h, g_sm2h); cudaGetSymbolAddress((void**)&psm2l, g_sm2l);
    cudaGetSymbolAddress((void**)&phgh,  g_hgh);  cudaGetSymbolAddress((void**)&phgl,  g_hgl);

    cudaFuncSetAttribute(hmma_gemm<1>, cudaFuncAttributeMaxDynamicSharedMemorySize, GSM_TOT);
    cudaFuncSetAttribute(hmma_gemm<2>, cudaFuncAttributeMaxDynamicSharedMemorySize, GSM_TOT);
    cudaFuncSetAttribute(fused_inproj_scan, cudaFuncAttributeMaxDynamicSharedMemorySize, F_SMEM);

    embed_kernel<<<dim3(LPAD, BB), 128>>>(token_emb, emb_ln_g, emb_ln_b, item_seq, px, pxh, pxl);

    for (int li = 0; li < NLAY; li++) {
        pack_kernel<<<1024, 256>>>(in_wr, in_wi, in_br, in_bi, out_wr, out_wi,
                                   w1, w2, params_log, li);
        fused_inproj_scan<<<dim3(4, BB), 512, F_SMEM>>>(
            pxh, pxl, pWinh, pWinl, pbin, phh, phl, item_seq, params_log, li);

        if (li == 0) {
            hmma_gemm<2><<<dim3(1, MTOK/128), 256, GSM_TOT>>>(
                phh, phl, pWouth, pWoutl, out_br + li*DD, px,
                lru_ln_g + li*DD, lru_ln_b + li*DD,
                px2, px2h, px2l, MTOK, 128, 512);
            hmma_gemm<1><<<dim3(4, MTOK/128), 256, GSM_TOT>>>(
                px2h, px2l, pw1h, pw1l, b1 + li*DFF, nullptr, nullptr, nullptr,
                nullptr, phfh, phfl, MTOK, 512, 128);
            hmma_gemm<2><<<dim3(1, MTOK/128), 256, GSM_TOT>>>(
                phfh, phfl, pw2h, pw2l, b2 + li*DD, px2,
                ffn_ln_g + li*DD, ffn_ln_b + li*DD,
                px, pxh, pxl, MTOK, 128, 512);
        } else {
            gather_kernel<<<BB, 512>>>(phh, phl, px, item_len, phgh, phgl, pxg);
            hmma_gemm<2><<<dim3(1, BB/128), 256, GSM_TOT>>>(
                phgh, phgl, pWouth, pWoutl, out_br + li*DD, pxg,
                lru_ln_g + li*DD, lru_ln_b + li*DD,
                psm1, psm1h, psm1l, BB, 128, 512);
            hmma_gemm<1><<<dim3(4, BB/128), 256, GSM_TOT>>>(
                psm1h, psm1l, pw1h, pw1l, b1 + li*DFF, nullptr, nullptr, nullptr,
                nullptr, psm2h, psm2l, BB, 512, 128);
            hmma_gemm<2><<<dim3(1, BB/128), 256, GSM_TOT>>>(
                psm2h, psm2l, pw2h, pw2l, b2 + li*DD, psm1,
                ffn_ln_g + li*DD, ffn_ln_b + li*DD,
                out, nullptr, nullptr, BB, 128, 512);
        }
    }
}

// round 8
// speedup vs baseline: 3.0459x; 1.5669x over previous
#include <cuda_runtime.h>
#include <cuda_bf16.h>
#include <cuda_fp16.h>
#include <math.h>
#include <stdint.h>

// Problem constants
#define BB   512
#define SS   200
#define DD   128
#define NLAY 2
#define DH   256      // complex hidden (512 reals)
#define DFF  512
#define LPAD 256
#define PAD  56
#define MTOK (BB*LPAD)

typedef __half fp16;

// single dynamic-smem symbol shared by all kernels
extern __shared__ __align__(16) char dyn_smem[];

// ---------------- scratch (device globals) ------------------------------------
__device__ float g_x  [MTOK * DD];        // fp32 x (residual for out-proj)
__device__ float g_x2 [MTOK * DD];        // fp32 x2 (residual for ffn2)
__device__ fp16 g_xh [MTOK * DD];
__device__ fp16 g_x2h[MTOK * DD];
__device__ fp16 g_hh [MTOK * 2*DH];
__device__ fp16 g_hfh[MTOK * DFF];
// packed per-layer weights
__device__ fp16 g_Win[2*DH*DD];
__device__ float g_bin[2*DH];
__device__ fp16 g_Wout[DD*2*DH];
__device__ fp16 g_w1[DFF*DD];
__device__ fp16 g_w2[DD*DFF];
// layer-2 tail (gathered, M=BB)
__device__ float g_xg [BB * DD];
__device__ float g_sm1[BB * DD];
__device__ fp16 g_sm1h[BB*DD];
__device__ fp16 g_sm2h[BB*DFF];
__device__ fp16 g_hgh[BB*2*DH];

// ---------------- helpers -------------------------------------------------------
__device__ __forceinline__ uint32_t smem_u32(const void* p) {
    uint32_t a;
    asm("{ .reg .u64 t; cvta.to.shared.u64 t, %1; cvt.u32.u64 %0, t; }" : "=r"(a) : "l"(p));
    return a;
}
__device__ __forceinline__ void cp_async16(uint32_t s, const void* g) {
    asm volatile("cp.async.cg.shared.global [%0], [%1], 16;" :: "r"(s), "l"(g));
}
__device__ __forceinline__ void ldsm4(uint32_t (&r)[4], uint32_t addr) {
    asm volatile("ldmatrix.sync.aligned.m8n8.x4.shared.b16 {%0,%1,%2,%3}, [%4];"
                 : "=r"(r[0]), "=r"(r[1]), "=r"(r[2]), "=r"(r[3]) : "r"(addr));
}
__device__ __forceinline__ void mma16816(float* c, const uint32_t* a, uint32_t b0, uint32_t b1) {
    asm volatile("mma.sync.aligned.m16n8k16.row.col.f32.f16.f16.f32 "
                 "{%0,%1,%2,%3}, {%4,%5,%6,%7}, {%8,%9}, {%0,%1,%2,%3};"
                 : "+f"(c[0]), "+f"(c[1]), "+f"(c[2]), "+f"(c[3])
                 : "r"(a[0]), "r"(a[1]), "r"(a[2]), "r"(a[3]), "r"(b0), "r"(b1));
}
__device__ __forceinline__ float block128_sum(float v, volatile float* sh) {
    #pragma unroll
    for (int o = 16; o > 0; o >>= 1) v += __shfl_xor_sync(0xffffffffu, v, o);
    __syncthreads();
    if ((threadIdx.x & 31) == 0) sh[threadIdx.x >> 5] = v;
    __syncthreads();
    return sh[0] + sh[1] + sh[2] + sh[3];
}
__device__ __forceinline__ void packh2(float a, float b, fp16* H, size_t idx) {
    *reinterpret_cast<__half2*>(H + idx) = __floats2half2_rn(a, b);
}

#define SM_FIX 1536
#define GP     144                // 64 fp16 = 128B + 16B pad (ldsm conflict-free)
#define GTILE  (128*GP)           // 18432
#define GSTAGE (2*GTILE)          // 36864 (A + B)
#define NSTAGE 3
#define GSM_TOT (SM_FIX + NSTAGE*GSTAGE)   // 112128 -> 2 CTAs/SM

// ---------------- embedding gather + LN + front-pad ----------------------------
__global__ void embed_kernel(const float* __restrict__ emb,
                             const float* __restrict__ g,
                             const float* __restrict__ bta,
                             const int*   __restrict__ seq,
                             float* __restrict__ x, fp16* __restrict__ xh) {
    __shared__ float sh[4];
    int b = blockIdx.y, t = blockIdx.x, tid = threadIdx.x;
    size_t o = ((size_t)b * LPAD + t) * DD + tid;
    float r;
    if (t < PAD) {
        r = 0.f;
    } else {
        int item = seq[b * SS + (t - PAD)];
        float v = emb[(size_t)item * DD + tid];
        float mu  = block128_sum(v, sh) * (1.f / DD);
        float d   = v - mu;
        float var = block128_sum(d * d, sh) * (1.f / DD);
        r = d * rsqrtf(var + 1e-5f) * g[tid] + bta[tid];
    }
    x[o] = r;
    xh[o] = __float2half_rn(r);
}

// ---------------- per-layer weight packing (to fp16) ----------------------------
__global__ void pack_kernel(const float* __restrict__ in_wr, const float* __restrict__ in_wi,
                            const float* __restrict__ in_br, const float* __restrict__ in_bi,
                            const float* __restrict__ out_wr, const float* __restrict__ out_wi,
                            const float* __restrict__ w1, const float* __restrict__ w2,
                            const float* __restrict__ params_log, int li) {
    int idx = blockIdx.x * 256 + threadIdx.x;   // 0 .. 262143
    int mat = idx >> 16, r = idx & 65535;
    float w;
    fp16* Dst;
    if (mat == 0) {
        int n = r >> 7, k = r & 127;
        int d = n >> 1, s = n & 1;
        float gamma = expf(params_log[(li * 3 + 2) * DH + d]);
        w = (s ? in_wi[(size_t)li * DH * DD + d * DD + k]
               : in_wr[(size_t)li * DH * DD + d * DD + k]) * gamma;
        if (k == 0) {
            float bv = s ? in_bi[li * DH + d] : in_br[li * DH + d];
            g_bin[n] = bv * gamma;
        }
        Dst = g_Win;
    } else if (mat == 1) {
        int n = r >> 9, k = r & 511;
        int d = k >> 1, s = k & 1;
        w = s ? -out_wi[(size_t)li * DD * DH + n * DH + d]
              :  out_wr[(size_t)li * DD * DH + n * DH + d];
        Dst = g_Wout;
    } else if (mat == 2) {
        w = w1[(size_t)li * DFF * DD + r];
        Dst = g_w1;
    } else {
        w = w2[(size_t)li * DD * DFF + r];
        Dst = g_w2;
    }
    Dst[r] = __float2half_rn(w);
}

// ---------------- gather last valid token --------------------------------------
__global__ void gather_kernel(const fp16* __restrict__ hh,
                              const float* __restrict__ x, const int* __restrict__ slen,
                              fp16* __restrict__ hgh, float* __restrict__ xg) {
    int b = blockIdx.x, tid = threadIdx.x;
    int t = PAD + slen[b] - 1;
    hgh[(size_t)b * 512 + tid] = hh[((size_t)b * LPAD + t) * 512 + tid];
    if (tid < DD) xg[(size_t)b * DD + tid] = x[((size_t)b * LPAD + t) * DD + tid];
}

// ================= fused in-projection GEMM + masked LRU scan ===================
// Per block: one batch (256 tokens) x 128 interleaved channels (64 complex).
#define FA_TILE (256*GP)                 // 36864
#define FB_TILE (128*GP)                 // 18432
#define F_CH   (FA_TILE + FB_TILE)       // 55296 per chunk
#define F_SMEM (SM_FIX + 131072 + 65536) // 198144 (scan region dominates)

__global__ void __launch_bounds__(512, 1) fused_inproj_scan(
        const fp16* __restrict__ Ax, const fp16* __restrict__ Bw,
        const float* __restrict__ bias,
        fp16* __restrict__ hh,
        const int* __restrict__ seq, const float* __restrict__ params_log, int li) {
    char* sm = dyn_smem;
    float* sBias = (float*)sm;             // [0,512)
    float* ms    = (float*)(sm + 512);     // [512,1536)
    float* buf   = (float*)(sm + SM_FIX);  // overlay after GEMM: 256*128 fp32
    float* lamR  = (float*)(sm + SM_FIX + 131072);
    float* lamI  = lamR + 8192;
    __shared__ float s_nu[64], s_th[64];
    uint32_t sb = smem_u32(sm);

    int tid = threadIdx.x, lane = tid & 31, wid = tid >> 5;
    int q = lane & 3, hrow = lane >> 2;
    int wm = wid & 7, wn = wid >> 3;
    int b = blockIdx.y, cg = blockIdx.x;
    int m0 = b * 256, n0 = cg * 128;

    // async prefetch of both K-chunks
    #pragma unroll
    for (int c = 0; c < 2; c++) {
        int kc = c * 64;
        uint32_t st = sb + SM_FIX + c * F_CH;
        #pragma unroll
        for (int t = 0; t < 4; t++) {           // A: 256 rows x 8 segs
            int idx = tid + t * 512;
            int row = idx >> 3, seg = idx & 7;
            cp_async16(st + row * GP + seg * 16,
                       Ax + (size_t)(m0 + row) * 128 + kc + seg * 8);
        }
        #pragma unroll
        for (int t = 0; t < 2; t++) {           // B: 128 rows x 8 segs
            int idx = tid + t * 512;
            int row = idx >> 3, seg = idx & 7;
            cp_async16(st + FA_TILE + row * GP + seg * 16,
                       Bw + (size_t)(n0 + row) * 128 + kc + seg * 8);
        }
        asm volatile("cp.async.commit_group;");
    }

    if (tid < 128) sBias[tid] = bias[n0 + tid];
    if (tid >= 256 && tid < 512) {
        int t = tid - 256;
        ms[t] = (t >= PAD && seq[b * SS + t - PAD] > 0) ? 1.f : 0.f;
    }
    if (tid < 64) {
        int d = cg * 64 + tid;
        s_nu[tid] = expf(params_log[(li * 3 + 0) * DH + d]);
        s_th[tid] = expf(params_log[(li * 3 + 1) * DH + d]);
    }

    float acc[2][8][4];
    #pragma unroll
    for (int a1 = 0; a1 < 2; a1++)
        #pragma unroll
        for (int a2 = 0; a2 < 8; a2++)
            #pragma unroll
            for (int a3 = 0; a3 < 4; a3++) acc[a1][a2][a3] = 0.f;

    #pragma unroll
    for (int ch = 0; ch < 2; ch++) {
        if (ch == 0) asm volatile("cp.async.wait_group 1;");
        else         asm volatile("cp.async.wait_group 0;");
        __syncthreads();
        uint32_t st = sb + SM_FIX + ch * F_CH;
        uint32_t aA = st, aB = st + FA_TILE;
        #pragma unroll
        for (int ks = 0; ks < 4; ks++) {
            uint32_t ah[2][4];
            #pragma unroll
            for (int mt = 0; mt < 2; mt++) {
                uint32_t aoff = (uint32_t)((wm*32 + mt*16 + (lane & 15)) * GP + ks*32 + (lane >> 4) * 16);
                ldsm4(ah[mt], aA + aoff);
            }
            #pragma unroll
            for (int nb = 0; nb < 4; nb++) {
                uint32_t boff = (uint32_t)((wn*64 + nb*16 + (lane & 15)) * GP + ks*32 + (lane >> 4) * 16);
                uint32_t bh[4];
                ldsm4(bh, aB + boff);
                #pragma unroll
                for (int mt = 0; mt < 2; mt++) {
                    mma16816(acc[mt][2*nb],   ah[mt], bh[0], bh[2]);
                    mma16816(acc[mt][2*nb+1], ah[mt], bh[1], bh[3]);
                }
            }
        }
    }
    __syncthreads();

    // epilogue -> scan buffer (overlays tiles)
    #pragma unroll
    for (int mt = 0; mt < 2; mt++) {
        int r0 = wm*32 + mt*16 + hrow;
        #pragma unroll
        for (int j = 0; j < 8; j++) {
            int col = wn*64 + j*8 + q*2;
            float b0 = sBias[col], b1 = sBias[col+1];
            *(float2*)&buf[r0*128 + col]     = make_float2(acc[mt][j][0] + b0, acc[mt][j][1] + b1);
            *(float2*)&buf[(r0+8)*128 + col] = make_float2(acc[mt][j][2] + b0, acc[mt][j][3] + b1);
        }
    }
    for (int i = tid; i < 8192; i += 512) {
        int c = i & 63, p = (i >> 6) + 1;
        float mag = expf(-s_nu[c] * (float)p);
        float sv, cv;
        sincosf(s_th[c] * (float)p, &sv, &cv);
        lamR[(p-1)*64 + c] = mag * cv;
        lamI[(p-1)*64 + c] = mag * sv;
    }
    __syncthreads();

    // 8-level masked tree scan over 64 complex channels
    #pragma unroll
    for (int lev = 1; lev <= 8; lev++) {
        int half = 1 << (lev - 1);
        for (int i = tid; i < 8192; i += 512) {
            int c = i & 63, u = i >> 6;
            int blk = u >> (lev - 1);
            int p = (u & (half - 1)) + 1;
            int cpos = blk * (half << 1) + half - 1;
            int t = cpos + p;
            if (ms[cpos] != 0.f) {
                float2 src = *(float2*)&buf[cpos*128 + 2*c];
                float lr = lamR[(p-1)*64 + c], lim = lamI[(p-1)*64 + c];
                float2 dst = *(float2*)&buf[t*128 + 2*c];
                dst.x += lr * src.x - lim * src.y;
                dst.y += lr * src.y + lim * src.x;
                *(float2*)&buf[t*128 + 2*c] = dst;
            }
        }
        __syncthreads();
    }

    // write packed h (fp16)
    for (int i = tid; i < 8192; i += 512) {
        int t = i >> 5, c4 = i & 31;
        float4 v = *(const float4*)&buf[t*128 + c4*4];
        size_t o = (size_t)(m0 + t) * 512 + n0 + c4*4;
        packh2(v.x, v.y, hh, o);
        packh2(v.z, v.w, hh, o + 2);
    }
}

// ================= pipelined fp16 GEMM (BK=64, 3 stages, 2 CTAs/SM) =============
// EPI 1: bias+gelu. EPI 2: bias+residual+LayerNorm (N==128).
__device__ __forceinline__ void gemm_load_chunk(
        uint32_t st, const fp16* A, const fp16* B,
        int m0, int n0, int kc, int K, int tid) {
    #pragma unroll
    for (int t = 0; t < 4; t++) {
        int idx = tid + t * 256;       // 0..1023
        int row = idx >> 3, seg = idx & 7;
        uint32_t so = row * GP + seg * 16;
        cp_async16(st + so,         A + (size_t)(m0 + row) * K + kc + seg * 8);
        cp_async16(st + GTILE + so, B + (size_t)(n0 + row) * K + kc + seg * 8);
    }
}

template<int EPI>
__global__ void __launch_bounds__(256, 2) hmma_gemm(
        const fp16* __restrict__ A, const fp16* __restrict__ B,
        const float* __restrict__ bias, const float* __restrict__ Res,
        const float* __restrict__ lng, const float* __restrict__ lnb,
        float* __restrict__ Cf, fp16* __restrict__ Ch,
        int M, int N, int K) {
    char* sm = dyn_smem;
    float* sBias = (float*)sm;
    float* sG    = sBias + 128;
    float* sB    = sG + 128;
    float* sred  = (float*)(sm + SM_FIX);   // overlay after mainloop
    uint32_t sb = smem_u32(sm);

    int tid = threadIdx.x, lane = tid & 31, wid = tid >> 5;
    int q = lane & 3, hrow = lane >> 2;
    int wm = wid & 3, wn = wid >> 2;
    int m0 = blockIdx.y * 128, n0 = blockIdx.x * 128;

    if (tid < 128) {
        sBias[tid] = bias[n0 + tid];
        if (EPI == 2) { sG[tid] = lng[n0 + tid]; sB[tid] = lnb[n0 + tid]; }
    }

    float acc[2][8][4];
    #pragma unroll
    for (int a1 = 0; a1 < 2; a1++)
        #pragma unroll
        for (int a2 = 0; a2 < 8; a2++)
            #pragma unroll
            for (int a3 = 0; a3 < 4; a3++) acc[a1][a2][a3] = 0.f;

    int nc = K >> 6;
    // preload up to 2 chunks
    gemm_load_chunk(sb + SM_FIX, A, B, m0, n0, 0, K, tid);
    asm volatile("cp.async.commit_group;");
    if (nc > 1) gemm_load_chunk(sb + SM_FIX + GSTAGE, A, B, m0, n0, 64, K, tid);
    asm volatile("cp.async.commit_group;");

    for (int ch = 0; ch < nc; ch++) {
        if (ch + 2 < nc)
            gemm_load_chunk(sb + SM_FIX + ((ch + 2) % NSTAGE) * GSTAGE,
                            A, B, m0, n0, (ch + 2) << 6, K, tid);
        asm volatile("cp.async.commit_group;");
        asm volatile("cp.async.wait_group 2;");
        __syncthreads();
        uint32_t st = sb + SM_FIX + (ch % NSTAGE) * GSTAGE;
        uint32_t aA = st, aB = st + GTILE;
        #pragma unroll
        for (int ks = 0; ks < 4; ks++) {
            uint32_t ah[2][4];
            #pragma unroll
            for (int mt = 0; mt < 2; mt++) {
                uint32_t aoff = (uint32_t)((wm*32 + mt*16 + (lane & 15)) * GP + ks*32 + (lane >> 4) * 16);
                ldsm4(ah[mt], aA + aoff);
            }
            #pragma unroll
            for (int nb = 0; nb < 4; nb++) {
                uint32_t boff = (uint32_t)((wn*64 + nb*16 + (lane & 15)) * GP + ks*32 + (lane >> 4) * 16);
                uint32_t bh[4];
                ldsm4(bh, aB + boff);
                #pragma unroll
                for (int mt = 0; mt < 2; mt++) {
                    mma16816(acc[mt][2*nb],   ah[mt], bh[0], bh[2]);
                    mma16816(acc[mt][2*nb+1], ah[mt], bh[1], bh[3]);
                }
            }
        }
        __syncthreads();
    }

    // ---------------- epilogue ----------------
    #pragma unroll
    for (int mt = 0; mt < 2; mt++)
        #pragma unroll
        for (int j = 0; j < 8; j++) {
            int col = wn*64 + j*8 + q*2;
            float b0 = sBias[col], b1 = sBias[col+1];
            acc[mt][j][0] += b0; acc[mt][j][1] += b1;
            acc[mt][j][2] += b0; acc[mt][j][3] += b1;
        }
    if (EPI == 1) {
        #pragma unroll
        for (int mt = 0; mt < 2; mt++)
            #pragma unroll
            for (int j = 0; j < 8; j++)
                #pragma unroll
                for (int v = 0; v < 4; v++)
                    acc[mt][j][v] = 0.5f * acc[mt][j][v] *
                                    (1.f + erff(acc[mt][j][v] * 0.70710678118654752f));
    }
    if (EPI == 2) {
        float mu[2][2], rs[2][2];
        #pragma unroll
        for (int mt = 0; mt < 2; mt++) {
            int r0 = m0 + wm*32 + mt*16 + hrow;
            #pragma unroll
            for (int j = 0; j < 8; j++) {
                int col = wn*64 + j*8 + q*2;
                float2 ra = *(const float2*)(Res + (size_t)r0 * 128 + col);
                float2 rb = *(const float2*)(Res + (size_t)(r0+8) * 128 + col);
                acc[mt][j][0] += ra.x; acc[mt][j][1] += ra.y;
                acc[mt][j][2] += rb.x; acc[mt][j][3] += rb.y;
            }
        }
        float ssum[2][2] = {{0,0},{0,0}}, ssq[2][2] = {{0,0},{0,0}};
        #pragma unroll
        for (int mt = 0; mt < 2; mt++)
            #pragma unroll
            for (int j = 0; j < 8; j++)
                #pragma unroll
                for (int hh = 0; hh < 2; hh++) {
                    float v0 = acc[mt][j][2*hh], v1 = acc[mt][j][2*hh+1];
                    ssum[mt][hh] += v0 + v1;
                    ssq[mt][hh]  += v0*v0 + v1*v1;
                }
        #pragma unroll
        for (int mt = 0; mt < 2; mt++)
            #pragma unroll
            for (int hh = 0; hh < 2; hh++) {
                ssum[mt][hh] += __shfl_xor_sync(0xffffffffu, ssum[mt][hh], 1);
                ssum[mt][hh] += __shfl_xor_sync(0xffffffffu, ssum[mt][hh], 2);
                ssq[mt][hh]  += __shfl_xor_sync(0xffffffffu, ssq[mt][hh], 1);
                ssq[mt][hh]  += __shfl_xor_sync(0xffffffffu, ssq[mt][hh], 2);
            }
        if (q == 0) {
            #pragma unroll
            for (int mt = 0; mt < 2; mt++)
                #pragma unroll
                for (int hh = 0; hh < 2; hh++) {
                    int lr = wm*32 + mt*16 + hrow + hh*8;
                    sred[lr*2 + wn]       = ssum[mt][hh];
                    sred[256 + lr*2 + wn] = ssq[mt][hh];
                }
        }
        __syncthreads();
        #pragma unroll
        for (int mt = 0; mt < 2; mt++)
            #pragma unroll
            for (int hh = 0; hh < 2; hh++) {
                int lr = wm*32 + mt*16 + hrow + hh*8;
                float S  = sred[lr*2] + sred[lr*2 + 1];
                float S2 = sred[256 + lr*2] + sred[256 + lr*2 + 1];
                float m  = S * (1.f/128.f);
                float var = S2 * (1.f/128.f) - m * m;
                mu[mt][hh] = m;
                rs[mt][hh] = rsqrtf(var + 1e-5f);
            }
        #pragma unroll
        for (int mt = 0; mt < 2; mt++)
            #pragma unroll
            for (int j = 0; j < 8; j++) {
                int col = wn*64 + j*8 + q*2;
                float g0 = sG[col], g1 = sG[col+1], bb0 = sB[col], bb1 = sB[col+1];
                acc[mt][j][0] = (acc[mt][j][0] - mu[mt][0]) * rs[mt][0] * g0 + bb0;
                acc[mt][j][1] = (acc[mt][j][1] - mu[mt][0]) * rs[mt][0] * g1 + bb1;
                acc[mt][j][2] = (acc[mt][j][2] - mu[mt][1]) * rs[mt][1] * g0 + bb0;
                acc[mt][j][3] = (acc[mt][j][3] - mu[mt][1]) * rs[mt][1] * g1 + bb1;
            }
    }
    #pragma unroll
    for (int mt = 0; mt < 2; mt++) {
        int r0 = m0 + wm*32 + mt*16 + hrow;
        #pragma unroll
        for (int j = 0; j < 8; j++) {
            int col = n0 + wn*64 + j*8 + q*2;
            if (Cf) {
                *(float2*)(Cf + (size_t)r0 * N + col)     = make_float2(acc[mt][j][0], acc[mt][j][1]);
                *(float2*)(Cf + (size_t)(r0+8) * N + col) = make_float2(acc[mt][j][2], acc[mt][j][3]);
            }
            if (Ch) {
                packh2(acc[mt][j][0], acc[mt][j][1], Ch, (size_t)r0 * N + col);
                packh2(acc[mt][j][2], acc[mt][j][3], Ch, (size_t)(r0+8) * N + col);
            }
        }
    }
}

// ---------------- host driver ---------------------------------------------------
extern "C" void kernel_launch(void* const* d_in, const int* in_sizes, int n_in,
                              void* d_out, int out_size) {
    const float* token_emb  = (const float*)d_in[0];
    const float* emb_ln_g   = (const float*)d_in[1];
    const float* emb_ln_b   = (const float*)d_in[2];
    const float* params_log = (const float*)d_in[3];
    const float* in_wr      = (const float*)d_in[4];
    const float* in_wi      = (const float*)d_in[5];
    const float* in_br      = (const float*)d_in[6];
    const float* in_bi      = (const float*)d_in[7];
    const float* out_wr     = (const float*)d_in[8];
    const float* out_wi     = (const float*)d_in[9];
    const float* out_br     = (const float*)d_in[10];
    const float* lru_ln_g   = (const float*)d_in[12];
    const float* lru_ln_b   = (const float*)d_in[13];
    const float* w1         = (const float*)d_in[14];
    const float* b1         = (const float*)d_in[15];
    const float* w2         = (const float*)d_in[16];
    const float* b2         = (const float*)d_in[17];
    const float* ffn_ln_g   = (const float*)d_in[18];
    const float* ffn_ln_b   = (const float*)d_in[19];
    const int*   item_seq   = (const int*)d_in[20];
    const int*   item_len   = (const int*)d_in[21];
    float* out = (float*)d_out;

    float *px, *px2, *pbin, *pxg, *psm1;
    fp16 *pxh, *px2h, *phh, *phfh, *pWin, *pWout, *pw1, *pw2;
    fp16 *psm1h, *psm2h, *phgh;
    cudaGetSymbolAddress((void**)&px,    g_x);
    cudaGetSymbolAddress((void**)&px2,   g_x2);
    cudaGetSymbolAddress((void**)&pxh,   g_xh);
    cudaGetSymbolAddress((void**)&px2h,  g_x2h);
    cudaGetSymbolAddress((void**)&phh,   g_hh);
    cudaGetSymbolAddress((void**)&phfh,  g_hfh);
    cudaGetSymbolAddress((void**)&pWin,  g_Win);
    cudaGetSymbolAddress((void**)&pbin,  g_bin);
    cudaGetSymbolAddress((void**)&pWout, g_Wout);
    cudaGetSymbolAddress((void**)&pw1,   g_w1);
    cudaGetSymbolAddress((void**)&pw2,   g_w2);
    cudaGetSymbolAddress((void**)&pxg,   g_xg);
    cudaGetSymbolAddress((void**)&psm1,  g_sm1);
    cudaGetSymbolAddress((void**)&psm1h, g_sm1h);
    cudaGetSymbolAddress((void**)&psm2h, g_sm2h);
    cudaGetSymbolAddress((void**)&phgh,  g_hgh);

    cudaFuncSetAttribute(hmma_gemm<1>, cudaFuncAttributeMaxDynamicSharedMemorySize, GSM_TOT);
    cudaFuncSetAttribute(hmma_gemm<2>, cudaFuncAttributeMaxDynamicSharedMemorySize, GSM_TOT);
    cudaFuncSetAttribute(fused_inproj_scan, cudaFuncAttributeMaxDynamicSharedMemorySize, F_SMEM);

    embed_kernel<<<dim3(LPAD, BB), 128>>>(token_emb, emb_ln_g, emb_ln_b, item_seq, px, pxh);

    for (int li = 0; li < NLAY; li++) {
        pack_kernel<<<1024, 256>>>(in_wr, in_wi, in_br, in_bi, out_wr, out_wi,
                                   w1, w2, params_log, li);
        fused_inproj_scan<<<dim3(4, BB), 512, F_SMEM>>>(
            pxh, pWin, pbin, phh, item_seq, params_log, li);

        if (li == 0) {
            hmma_gemm<2><<<dim3(1, MTOK/128), 256, GSM_TOT>>>(
                phh, pWout, out_br + li*DD, px,
                lru_ln_g + li*DD, lru_ln_b + li*DD,
                px2, px2h, MTOK, 128, 512);
            hmma_gemm<1><<<dim3(4, MTOK/128), 256, GSM_TOT>>>(
                px2h, pw1, b1 + li*DFF, nullptr, nullptr, nullptr,
                nullptr, phfh, MTOK, 512, 128);
            hmma_gemm<2><<<dim3(1, MTOK/128), 256, GSM_TOT>>>(
                phfh, pw2, b2 + li*DD, px2,
                ffn_ln_g + li*DD, ffn_ln_b + li*DD,
                px, pxh, MTOK, 128, 512);
        } else {
            gather_kernel<<<BB, 512>>>(phh, px, item_len, phgh, pxg);
            hmma_gemm<2><<<dim3(1, BB/128), 256, GSM_TOT>>>(
                phgh, pWout, out_br + li*DD, pxg,
                lru_ln_g + li*DD, lru_ln_b + li*DD,
                psm1, psm1h, BB, 128, 512);
            hmma_gemm<1><<<dim3(4, BB/128), 256, GSM_TOT>>>(
                psm1h, pw1, b1 + li*DFF, nullptr, nullptr, nullptr,
                nullptr, psm2h, BB, 512, 128);
            hmma_gemm<2><<<dim3(1, BB/128), 256, GSM_TOT>>>(
                psm2h, pw2, b2 + li*DD, psm1,
                ffn_ln_g + li*DD, ffn_ln_b + li*DD,
                out, nullptr, BB, 128, 512);
        }
    }
}

// round 9
// speedup vs baseline: 3.0876x; 1.0137x over previous
#include <cuda_runtime.h>
#include <cuda_bf16.h>
#include <cuda_fp16.h>
#include <math.h>
#include <stdint.h>

// Problem constants
#define BB   512
#define SS   200
#define DD   128
#define NLAY 2
#define DH   256      // complex hidden (512 reals)
#define DFF  512
#define LPAD 256
#define PAD  56
#define MTOK (BB*LPAD)

typedef __half fp16;

// single dynamic-smem symbol shared by all kernels
extern __shared__ __align__(16) char dyn_smem[];

// ---------------- scratch (device globals) ------------------------------------
__device__ fp16 g_xh [MTOK * DD];
__device__ fp16 g_x2h[MTOK * DD];
__device__ fp16 g_hh [MTOK * 2*DH];
__device__ fp16 g_hfh[MTOK * DFF];
// packed per-layer weights + lambda-power table
__device__ fp16 g_Win[2*DH*DD];
__device__ float g_bin[2*DH];
__device__ fp16 g_Wout[DD*2*DH];
__device__ fp16 g_w1[DFF*DD];
__device__ fp16 g_w2[DD*DFF];
__device__ float g_lamR[4*128*64];   // [cg][p-1][c]
__device__ float g_lamI[4*128*64];
// layer-2 tail (gathered, M=BB)
__device__ fp16 g_xgh[BB * DD];
__device__ fp16 g_sm1h[BB*DD];
__device__ fp16 g_sm2h[BB*DFF];
__device__ fp16 g_hgh[BB*2*DH];

// ---------------- helpers -------------------------------------------------------
__device__ __forceinline__ uint32_t smem_u32(const void* p) {
    uint32_t a;
    asm("{ .reg .u64 t; cvta.to.shared.u64 t, %1; cvt.u32.u64 %0, t; }" : "=r"(a) : "l"(p));
    return a;
}
__device__ __forceinline__ void cp_async16(uint32_t s, const void* g) {
    asm volatile("cp.async.cg.shared.global [%0], [%1], 16;" :: "r"(s), "l"(g));
}
__device__ __forceinline__ void ldsm4(uint32_t (&r)[4], uint32_t addr) {
    asm volatile("ldmatrix.sync.aligned.m8n8.x4.shared.b16 {%0,%1,%2,%3}, [%4];"
                 : "=r"(r[0]), "=r"(r[1]), "=r"(r[2]), "=r"(r[3]) : "r"(addr));
}
__device__ __forceinline__ void mma16816(float* c, const uint32_t* a, uint32_t b0, uint32_t b1) {
    asm volatile("mma.sync.aligned.m16n8k16.row.col.f32.f16.f16.f32 "
                 "{%0,%1,%2,%3}, {%4,%5,%6,%7}, {%8,%9}, {%0,%1,%2,%3};"
                 : "+f"(c[0]), "+f"(c[1]), "+f"(c[2]), "+f"(c[3])
                 : "r"(a[0]), "r"(a[1]), "r"(a[2]), "r"(a[3]), "r"(b0), "r"(b1));
}
__device__ __forceinline__ float block128_sum(float v, volatile float* sh) {
    #pragma unroll
    for (int o = 16; o > 0; o >>= 1) v += __shfl_xor_sync(0xffffffffu, v, o);
    __syncthreads();
    if ((threadIdx.x & 31) == 0) sh[threadIdx.x >> 5] = v;
    __syncthreads();
    return sh[0] + sh[1] + sh[2] + sh[3];
}
__device__ __forceinline__ void packh2(float a, float b, fp16* H, size_t idx) {
    *reinterpret_cast<__half2*>(H + idx) = __floats2half2_rn(a, b);
}

#define SM_FIX 1536
#define GP     144                // 64 fp16 = 128B + 16B pad (ldsm conflict-free)
#define GTILE  (128*GP)           // 18432
#define GSTAGE (2*GTILE)          // 36864 (A + B)
#define NSTAGE 3
#define GSM_TOT (SM_FIX + NSTAGE*GSTAGE)   // 112128 -> 2 CTAs/SM

// ---------------- embedding gather + LN + front-pad ----------------------------
__global__ void embed_kernel(const float* __restrict__ emb,
                             const float* __restrict__ g,
                             const float* __restrict__ bta,
                             const int*   __restrict__ seq,
                             fp16* __restrict__ xh) {
    __shared__ float sh[4];
    int b = blockIdx.y, t = blockIdx.x, tid = threadIdx.x;
    size_t o = ((size_t)b * LPAD + t) * DD + tid;
    float r;
    if (t < PAD) {
        r = 0.f;
    } else {
        int item = seq[b * SS + (t - PAD)];
        float v = emb[(size_t)item * DD + tid];
        float mu  = block128_sum(v, sh) * (1.f / DD);
        float d   = v - mu;
        float var = block128_sum(d * d, sh) * (1.f / DD);
        r = d * rsqrtf(var + 1e-5f) * g[tid] + bta[tid];
    }
    xh[o] = __float2half_rn(r);
}

// ---------------- per-layer lambda-power table ----------------------------------
__global__ void lam_kernel(const float* __restrict__ params_log, int li) {
    int idx = blockIdx.x * 256 + threadIdx.x;   // 0..32767
    int cg = idx >> 13, rem = idx & 8191;
    int p = (rem >> 6) + 1, c = rem & 63;
    int d = cg * 64 + c;
    float nu = expf(params_log[(li * 3 + 0) * DH + d]);
    float th = expf(params_log[(li * 3 + 1) * DH + d]);
    float mag = expf(-nu * (float)p);
    float sv, cv;
    sincosf(th * (float)p, &sv, &cv);
    g_lamR[idx] = mag * cv;
    g_lamI[idx] = mag * sv;
}

// ---------------- per-layer weight packing (to fp16) ----------------------------
__global__ void pack_kernel(const float* __restrict__ in_wr, const float* __restrict__ in_wi,
                            const float* __restrict__ in_br, const float* __restrict__ in_bi,
                            const float* __restrict__ out_wr, const float* __restrict__ out_wi,
                            const float* __restrict__ w1, const float* __restrict__ w2,
                            const float* __restrict__ params_log, int li) {
    int idx = blockIdx.x * 256 + threadIdx.x;   // 0 .. 262143
    int mat = idx >> 16, r = idx & 65535;
    float w;
    fp16* Dst;
    if (mat == 0) {
        int n = r >> 7, k = r & 127;
        int d = n >> 1, s = n & 1;
        float gamma = expf(params_log[(li * 3 + 2) * DH + d]);
        w = (s ? in_wi[(size_t)li * DH * DD + d * DD + k]
               : in_wr[(size_t)li * DH * DD + d * DD + k]) * gamma;
        if (k == 0) {
            float bv = s ? in_bi[li * DH + d] : in_br[li * DH + d];
            g_bin[n] = bv * gamma;
        }
        Dst = g_Win;
    } else if (mat == 1) {
        int n = r >> 9, k = r & 511;
        int d = k >> 1, s = k & 1;
        w = s ? -out_wi[(size_t)li * DD * DH + n * DH + d]
              :  out_wr[(size_t)li * DD * DH + n * DH + d];
        Dst = g_Wout;
    } else if (mat == 2) {
        w = w1[(size_t)li * DFF * DD + r];
        Dst = g_w1;
    } else {
        w = w2[(size_t)li * DD * DFF + r];
        Dst = g_w2;
    }
    Dst[r] = __float2half_rn(w);
}

// ---------------- gather last valid token --------------------------------------
__global__ void gather_kernel(const fp16* __restrict__ hh,
                              const fp16* __restrict__ xh, const int* __restrict__ slen,
                              fp16* __restrict__ hgh, fp16* __restrict__ xgh) {
    int b = blockIdx.x, tid = threadIdx.x;
    int t = PAD + slen[b] - 1;
    hgh[(size_t)b * 512 + tid] = hh[((size_t)b * LPAD + t) * 512 + tid];
    if (tid < DD) xgh[(size_t)b * DD + tid] = xh[((size_t)b * LPAD + t) * DD + tid];
}

// ================= fused in-projection GEMM + masked LRU scan ===================
// Per block: one batch (256 tokens) x 128 interleaved channels (64 complex).
#define FA_TILE (256*GP)                 // 36864
#define FB_TILE (128*GP)                 // 18432
#define F_CH   (FA_TILE + FB_TILE)       // 55296 per chunk
#define F_SMEM (SM_FIX + 131072)         // 132608

__global__ void __launch_bounds__(512, 1) fused_inproj_scan(
        const fp16* __restrict__ Ax, const fp16* __restrict__ Bw,
        const float* __restrict__ bias,
        fp16* __restrict__ hh,
        const int* __restrict__ seq) {
    char* sm = dyn_smem;
    float* sBias = (float*)sm;             // [0,512)
    float* ms    = (float*)(sm + 512);     // [512,1536)
    float* buf   = (float*)(sm + SM_FIX);  // overlay after GEMM: 256*128 fp32
    uint32_t sb = smem_u32(sm);

    int tid = threadIdx.x, lane = tid & 31, wid = tid >> 5;
    int q = lane & 3, hrow = lane >> 2;
    int wm = wid & 7, wn = wid >> 3;
    int b = blockIdx.y, cg = blockIdx.x;
    int m0 = b * 256, n0 = cg * 128;
    const float* lamR = g_lamR + cg * 8192;
    const float* lamI = g_lamI + cg * 8192;

    // async prefetch of both K-chunks
    #pragma unroll
    for (int c = 0; c < 2; c++) {
        int kc = c * 64;
        uint32_t st = sb + SM_FIX + c * F_CH;
        #pragma unroll
        for (int t = 0; t < 4; t++) {           // A: 256 rows x 8 segs
            int idx = tid + t * 512;
            int row = idx >> 3, seg = idx & 7;
            cp_async16(st + row * GP + seg * 16,
                       Ax + (size_t)(m0 + row) * 128 + kc + seg * 8);
        }
        #pragma unroll
        for (int t = 0; t < 2; t++) {           // B: 128 rows x 8 segs
            int idx = tid + t * 512;
            int row = idx >> 3, seg = idx & 7;
            cp_async16(st + FA_TILE + row * GP + seg * 16,
                       Bw + (size_t)(n0 + row) * 128 + kc + seg * 8);
        }
        asm volatile("cp.async.commit_group;");
    }

    if (tid < 128) sBias[tid] = bias[n0 + tid];
    if (tid >= 256 && tid < 512) {
        int t = tid - 256;
        ms[t] = (t >= PAD && seq[b * SS + t - PAD] > 0) ? 1.f : 0.f;
    }

    float acc[2][8][4];
    #pragma unroll
    for (int a1 = 0; a1 < 2; a1++)
        #pragma unroll
        for (int a2 = 0; a2 < 8; a2++)
            #pragma unroll
            for (int a3 = 0; a3 < 4; a3++) acc[a1][a2][a3] = 0.f;

    #pragma unroll
    for (int ch = 0; ch < 2; ch++) {
        if (ch == 0) asm volatile("cp.async.wait_group 1;");
        else         asm volatile("cp.async.wait_group 0;");
        __syncthreads();
        uint32_t st = sb + SM_FIX + ch * F_CH;
        uint32_t aA = st, aB = st + FA_TILE;
        #pragma unroll
        for (int ks = 0; ks < 4; ks++) {
            uint32_t ah[2][4];
            #pragma unroll
            for (int mt = 0; mt < 2; mt++) {
                uint32_t aoff = (uint32_t)((wm*32 + mt*16 + (lane & 15)) * GP + ks*32 + (lane >> 4) * 16);
                ldsm4(ah[mt], aA + aoff);
            }
            #pragma unroll
            for (int nb = 0; nb < 4; nb++) {
                uint32_t boff = (uint32_t)((wn*64 + nb*16 + (lane & 15)) * GP + ks*32 + (lane >> 4) * 16);
                uint32_t bh[4];
                ldsm4(bh, aB + boff);
                #pragma unroll
                for (int mt = 0; mt < 2; mt++) {
                    mma16816(acc[mt][2*nb],   ah[mt], bh[0], bh[2]);
                    mma16816(acc[mt][2*nb+1], ah[mt], bh[1], bh[3]);
                }
            }
        }
    }
    __syncthreads();

    // epilogue -> scan buffer (overlays tiles)
    #pragma unroll
    for (int mt = 0; mt < 2; mt++) {
        int r0 = wm*32 + mt*16 + hrow;
        #pragma unroll
        for (int j = 0; j < 8; j++) {
            int col = wn*64 + j*8 + q*2;
            float b0 = sBias[col], b1 = sBias[col+1];
            *(float2*)&buf[r0*128 + col]     = make_float2(acc[mt][j][0] + b0, acc[mt][j][1] + b1);
            *(float2*)&buf[(r0+8)*128 + col] = make_float2(acc[mt][j][2] + b0, acc[mt][j][3] + b1);
        }
    }
    __syncthreads();

    // 8-level masked tree scan over 64 complex channels (lambda table from gmem)
    #pragma unroll
    for (int lev = 1; lev <= 8; lev++) {
        int half = 1 << (lev - 1);
        for (int i = tid; i < 8192; i += 512) {
            int c = i & 63, u = i >> 6;
            int blk = u >> (lev - 1);
            int p = (u & (half - 1)) + 1;
            int cpos = blk * (half << 1) + half - 1;
            int t = cpos + p;
            if (ms[cpos] != 0.f) {
                float2 src = *(float2*)&buf[cpos*128 + 2*c];
                float lr  = lamR[(p-1)*64 + c];
                float lim = lamI[(p-1)*64 + c];
                float2 dst = *(float2*)&buf[t*128 + 2*c];
                dst.x += lr * src.x - lim * src.y;
                dst.y += lr * src.y + lim * src.x;
                *(float2*)&buf[t*128 + 2*c] = dst;
            }
        }
        __syncthreads();
    }

    // write packed h (fp16)
    for (int i = tid; i < 8192; i += 512) {
        int t = i >> 5, c4 = i & 31;
        float4 v = *(const float4*)&buf[t*128 + c4*4];
        size_t o = (size_t)(m0 + t) * 512 + n0 + c4*4;
        packh2(v.x, v.y, hh, o);
        packh2(v.z, v.w, hh, o + 2);
    }
}

// ================= pipelined fp16 GEMM (BK=64, 3 stages, 2 CTAs/SM) =============
// EPI 1: bias+gelu. EPI 2: bias+residual(fp16)+LayerNorm (N==128).
__device__ __forceinline__ void gemm_load_chunk(
        uint32_t st, const fp16* A, const fp16* B,
        int m0, int n0, int kc, int K, int tid) {
    #pragma unroll
    for (int t = 0; t < 4; t++) {
        int idx = tid + t * 256;       // 0..1023
        int row = idx >> 3, seg = idx & 7;
        uint32_t so = row * GP + seg * 16;
        cp_async16(st + so,         A + (size_t)(m0 + row) * K + kc + seg * 8);
        cp_async16(st + GTILE + so, B + (size_t)(n0 + row) * K + kc + seg * 8);
    }
}

template<int EPI>
__global__ void __launch_bounds__(256, 2) hmma_gemm(
        const fp16* __restrict__ A, const fp16* __restrict__ B,
        const float* __restrict__ bias, const fp16* __restrict__ Res,
        const float* __restrict__ lng, const float* __restrict__ lnb,
        float* __restrict__ Cf, fp16* __restrict__ Ch,
        int M, int N, int K) {
    char* sm = dyn_smem;
    float* sBias = (float*)sm;
    float* sG    = sBias + 128;
    float* sB    = sG + 128;
    float* sred  = (float*)(sm + SM_FIX);   // overlay after mainloop
    uint32_t sb = smem_u32(sm);

    int tid = threadIdx.x, lane = tid & 31, wid = tid >> 5;
    int q = lane & 3, hrow = lane >> 2;
    int wm = wid & 3, wn = wid >> 2;
    int m0 = blockIdx.y * 128, n0 = blockIdx.x * 128;

    if (tid < 128) {
        sBias[tid] = bias[n0 + tid];
        if (EPI == 2) { sG[tid] = lng[n0 + tid]; sB[tid] = lnb[n0 + tid]; }
    }

    float acc[2][8][4];
    #pragma unroll
    for (int a1 = 0; a1 < 2; a1++)
        #pragma unroll
        for (int a2 = 0; a2 < 8; a2++)
            #pragma unroll
            for (int a3 = 0; a3 < 4; a3++) acc[a1][a2][a3] = 0.f;

    int nc = K >> 6;
    gemm_load_chunk(sb + SM_FIX, A, B, m0, n0, 0, K, tid);
    asm volatile("cp.async.commit_group;");
    if (nc > 1) gemm_load_chunk(sb + SM_FIX + GSTAGE, A, B, m0, n0, 64, K, tid);
    asm volatile("cp.async.commit_group;");

    for (int ch = 0; ch < nc; ch++) {
        if (ch + 2 < nc)
            gemm_load_chunk(sb + SM_FIX + ((ch + 2) % NSTAGE) * GSTAGE,
                            A, B, m0, n0, (ch + 2) << 6, K, tid);
        asm volatile("cp.async.commit_group;");
        asm volatile("cp.async.wait_group 2;");
        __syncthreads();
        uint32_t st = sb + SM_FIX + (ch % NSTAGE) * GSTAGE;
        uint32_t aA = st, aB = st + GTILE;
        #pragma unroll
        for (int ks = 0; ks < 4; ks++) {
            uint32_t ah[2][4];
            #pragma unroll
            for (int mt = 0; mt < 2; mt++) {
                uint32_t aoff = (uint32_t)((wm*32 + mt*16 + (lane & 15)) * GP + ks*32 + (lane >> 4) * 16);
                ldsm4(ah[mt], aA + aoff);
            }
            #pragma unroll
            for (int nb = 0; nb < 4; nb++) {
                uint32_t boff = (uint32_t)((wn*64 + nb*16 + (lane & 15)) * GP + ks*32 + (lane >> 4) * 16);
                uint32_t bh[4];
                ldsm4(bh, aB + boff);
                #pragma unroll
                for (int mt = 0; mt < 2; mt++) {
                    mma16816(acc[mt][2*nb],   ah[mt], bh[0], bh[2]);
                    mma16816(acc[mt][2*nb+1], ah[mt], bh[1], bh[3]);
                }
            }
        }
        __syncthreads();
    }

    // ---------------- epilogue ----------------
    #pragma unroll
    for (int mt = 0; mt < 2; mt++)
        #pragma unroll
        for (int j = 0; j < 8; j++) {
            int col = wn*64 + j*8 + q*2;
            float b0 = sBias[col], b1 = sBias[col+1];
            acc[mt][j][0] += b0; acc[mt][j][1] += b1;
            acc[mt][j][2] += b0; acc[mt][j][3] += b1;
        }
    if (EPI == 1) {
        #pragma unroll
        for (int mt = 0; mt < 2; mt++)
            #pragma unroll
            for (int j = 0; j < 8; j++)
                #pragma unroll
                for (int v = 0; v < 4; v++)
                    acc[mt][j][v] = 0.5f * acc[mt][j][v] *
                                    (1.f + erff(acc[mt][j][v] * 0.70710678118654752f));
    }
    if (EPI == 2) {
        float mu[2][2], rs[2][2];
        #pragma unroll
        for (int mt = 0; mt < 2; mt++) {
            int r0 = m0 + wm*32 + mt*16 + hrow;
            #pragma unroll
            for (int j = 0; j < 8; j++) {
                int col = wn*64 + j*8 + q*2;
                float2 ra = __half22float2(*(const __half2*)(Res + (size_t)r0 * 128 + col));
                float2 rb = __half22float2(*(const __half2*)(Res + (size_t)(r0+8) * 128 + col));
                acc[mt][j][0] += ra.x; acc[mt][j][1] += ra.y;
                acc[mt][j][2] += rb.x; acc[mt][j][3] += rb.y;
            }
        }
        float ssum[2][2] = {{0,0},{0,0}}, ssq[2][2] = {{0,0},{0,0}};
        #pragma unroll
        for (int mt = 0; mt < 2; mt++)
            #pragma unroll
            for (int j = 0; j < 8; j++)
                #pragma unroll
                for (int hh = 0; hh < 2; hh++) {
                    float v0 = acc[mt][j][2*hh], v1 = acc[mt][j][2*hh+1];
                    ssum[mt][hh] += v0 + v1;
                    ssq[mt][hh]  += v0*v0 + v1*v1;
                }
        #pragma unroll
        for (int mt = 0; mt < 2; mt++)
            #pragma unroll
            for (int hh = 0; hh < 2; hh++) {
                ssum[mt][hh] += __shfl_xor_sync(0xffffffffu, ssum[mt][hh], 1);
                ssum[mt][hh] += __shfl_xor_sync(0xffffffffu, ssum[mt][hh], 2);
                ssq[mt][hh]  += __shfl_xor_sync(0xffffffffu, ssq[mt][hh], 1);
                ssq[mt][hh]  += __shfl_xor_sync(0xffffffffu, ssq[mt][hh], 2);
            }
        if (q == 0) {
            #pragma unroll
            for (int mt = 0; mt < 2; mt++)
                #pragma unroll
                for (int hh = 0; hh < 2; hh++) {
                    int lr = wm*32 + mt*16 + hrow + hh*8;
                    sred[lr*2 + wn]       = ssum[mt][hh];
                    sred[256 + lr*2 + wn] = ssq[mt][hh];
                }
        }
        __syncthreads();
        #pragma unroll
        for (int mt = 0; mt < 2; mt++)
            #pragma unroll
            for (int hh = 0; hh < 2; hh++) {
                int lr = wm*32 + mt*16 + hrow + hh*8;
                float S  = sred[lr*2] + sred[lr*2 + 1];
                float S2 = sred[256 + lr*2] + sred[256 + lr*2 + 1];
                float m  = S * (1.f/128.f);
                float var = S2 * (1.f/128.f) - m * m;
                mu[mt][hh] = m;
                rs[mt][hh] = rsqrtf(var + 1e-5f);
            }
        #pragma unroll
        for (int mt = 0; mt < 2; mt++)
            #pragma unroll
            for (int j = 0; j < 8; j++) {
                int col = wn*64 + j*8 + q*2;
                float g0 = sG[col], g1 = sG[col+1], bb0 = sB[col], bb1 = sB[col+1];
                acc[mt][j][0] = (acc[mt][j][0] - mu[mt][0]) * rs[mt][0] * g0 + bb0;
                acc[mt][j][1] = (acc[mt][j][1] - mu[mt][0]) * rs[mt][0] * g1 + bb1;
                acc[mt][j][2] = (acc[mt][j][2] - mu[mt][1]) * rs[mt][1] * g0 + bb0;
                acc[mt][j][3] = (acc[mt][j][3] - mu[mt][1]) * rs[mt][1] * g1 + bb1;
            }
    }
    #pragma unroll
    for (int mt = 0; mt < 2; mt++) {
        int r0 = m0 + wm*32 + mt*16 + hrow;
        #pragma unroll
        for (int j = 0; j < 8; j++) {
            int col = n0 + wn*64 + j*8 + q*2;
            if (Cf) {
                *(float2*)(Cf + (size_t)r0 * N + col)     = make_float2(acc[mt][j][0], acc[mt][j][1]);
                *(float2*)(Cf + (size_t)(r0+8) * N + col) = make_float2(acc[mt][j][2], acc[mt][j][3]);
            }
            if (Ch) {
                packh2(acc[mt][j][0], acc[mt][j][1], Ch, (size_t)r0 * N + col);
                packh2(acc[mt][j][2], acc[mt][j][3], Ch, (size_t)(r0+8) * N + col);
            }
        }
    }
}

// ---------------- host driver ---------------------------------------------------
extern "C" void kernel_launch(void* const* d_in, const int* in_sizes, int n_in,
                              void* d_out, int out_size) {
    const float* token_emb  = (const float*)d_in[0];
    const float* emb_ln_g   = (const float*)d_in[1];
    const float* emb_ln_b   = (const float*)d_in[2];
    const float* params_log = (const float*)d_in[3];
    const float* in_wr      = (const float*)d_in[4];
    const float* in_wi      = (const float*)d_in[5];
    const float* in_br      = (const float*)d_in[6];
    const float* in_bi      = (const float*)d_in[7];
    const float* out_wr     = (const float*)d_in[8];
    const float* out_wi     = (const float*)d_in[9];
    const float* out_br     = (const float*)d_in[10];
    const float* lru_ln_g   = (const float*)d_in[12];
    const float* lru_ln_b   = (const float*)d_in[13];
    const float* w1         = (const float*)d_in[14];
    const float* b1         = (const float*)d_in[15];
    const float* w2         = (const float*)d_in[16];
    const float* b2         = (const float*)d_in[17];
    const float* ffn_ln_g   = (const float*)d_in[18];
    const float* ffn_ln_b   = (const float*)d_in[19];
    const int*   item_seq   = (const int*)d_in[20];
    const int*   item_len   = (const int*)d_in[21];
    float* out = (float*)d_out;

    float *pbin;
    fp16 *pxh, *px2h, *phh, *phfh, *pWin, *pWout, *pw1, *pw2;
    fp16 *psm1h, *psm2h, *phgh, *pxgh;
    cudaGetSymbolAddress((void**)&pxh,   g_xh);
    cudaGetSymbolAddress((void**)&px2h,  g_x2h);
    cudaGetSymbolAddress((void**)&phh,   g_hh);
    cudaGetSymbolAddress((void**)&phfh,  g_hfh);
    cudaGetSymbolAddress((void**)&pWin,  g_Win);
    cudaGetSymbolAddress((void**)&pbin,  g_bin);
    cudaGetSymbolAddress((void**)&pWout, g_Wout);
    cudaGetSymbolAddress((void**)&pw1,   g_w1);
    cudaGetSymbolAddress((void**)&pw2,   g_w2);
    cudaGetSymbolAddress((void**)&pxgh,  g_xgh);
    cudaGetSymbolAddress((void**)&psm1h, g_sm1h);
    cudaGetSymbolAddress((void**)&psm2h, g_sm2h);
    cudaGetSymbolAddress((void**)&phgh,  g_hgh);

    cudaFuncSetAttribute(hmma_gemm<1>, cudaFuncAttributeMaxDynamicSharedMemorySize, GSM_TOT);
    cudaFuncSetAttribute(hmma_gemm<2>, cudaFuncAttributeMaxDynamicSharedMemorySize, GSM_TOT);
    cudaFuncSetAttribute(fused_inproj_scan, cudaFuncAttributeMaxDynamicSharedMemorySize, F_SMEM);

    embed_kernel<<<dim3(LPAD, BB), 128>>>(token_emb, emb_ln_g, emb_ln_b, item_seq, pxh);

    for (int li = 0; li < NLAY; li++) {
        pack_kernel<<<1024, 256>>>(in_wr, in_wi, in_br, in_bi, out_wr, out_wi,
                                   w1, w2, params_log, li);
        lam_kernel<<<128, 256>>>(params_log, li);
        fused_inproj_scan<<<dim3(4, BB), 512, F_SMEM>>>(
            pxh, pWin, pbin, phh, item_seq);

        if (li == 0) {
            hmma_gemm<2><<<dim3(1, MTOK/128), 256, GSM_TOT>>>(
                phh, pWout, out_br + li*DD, pxh,
                lru_ln_g + li*DD, lru_ln_b + li*DD,
                nullptr, px2h, MTOK, 128, 512);
            hmma_gemm<1><<<dim3(4, MTOK/128), 256, GSM_TOT>>>(
                px2h, pw1, b1 + li*DFF, nullptr, nullptr, nullptr,
                nullptr, phfh, MTOK, 512, 128);
            hmma_gemm<2><<<dim3(1, MTOK/128), 256, GSM_TOT>>>(
                phfh, pw2, b2 + li*DD, px2h,
                ffn_ln_g + li*DD, ffn_ln_b + li*DD,
                nullptr, pxh, MTOK, 128, 512);
        } else {
            gather_kernel<<<BB, 512>>>(phh, pxh, item_len, phgh, pxgh);
            hmma_gemm<2><<<dim3(1, BB/128), 256, GSM_TOT>>>(
                phgh, pWout, out_br + li*DD, pxgh,
                lru_ln_g + li*DD, lru_ln_b + li*DD,
                nullptr, psm1h, BB, 128, 512);
            hmma_gemm<1><<<dim3(4, BB/128), 256, GSM_TOT>>>(
                psm1h, pw1, b1 + li*DFF, nullptr, nullptr, nullptr,
                nullptr, psm2h, BB, 512, 128);
            hmma_gemm<2><<<dim3(1, BB/128), 256, GSM_TOT>>>(
                psm2h, pw2, b2 + li*DD, psm1h,
                ffn_ln_g + li*DD, ffn_ln_b + li*DD,
                out, nullptr, BB, 128, 512);
        }
    }
}

// round 10
// speedup vs baseline: 3.7769x; 1.2232x over previous
#include <cuda_runtime.h>
#include <cuda_bf16.h>
#include <cuda_fp16.h>
#include <math.h>
#include <stdint.h>

// Problem constants
#define BB   512
#define SS   200
#define DD   128
#define NLAY 2
#define DH   256      // complex hidden (512 reals)
#define DFF  512
#define LPAD 256
#define PAD  56
#define MTOK (BB*LPAD)

typedef __half fp16;

// single dynamic-smem symbol shared by all kernels
extern __shared__ __align__(16) char dyn_smem[];

// ---------------- scratch (device globals) ------------------------------------
__device__ fp16 g_xh [MTOK * DD];
__device__ fp16 g_x2h[MTOK * DD];
__device__ fp16 g_hh [MTOK * 2*DH];
__device__ fp16 g_hfh[MTOK * DFF];
// packed per-layer weights + lambda-power table [cg 0..7][p-1 0..127][c 0..31]
__device__ fp16 g_Win[2*DH*DD];
__device__ float g_bin[2*DH];
__device__ fp16 g_Wout[DD*2*DH];
__device__ fp16 g_w1[DFF*DD];
__device__ fp16 g_w2[DD*DFF];
__device__ float g_lamR[8*128*32];
__device__ float g_lamI[8*128*32];
// layer-2 tail (gathered, M=BB)
__device__ fp16 g_xgh[BB * DD];
__device__ fp16 g_sm1h[BB*DD];
__device__ fp16 g_sm2h[BB*DFF];
__device__ fp16 g_hgh[BB*2*DH];

// ---------------- helpers -------------------------------------------------------
__device__ __forceinline__ uint32_t smem_u32(const void* p) {
    uint32_t a;
    asm("{ .reg .u64 t; cvta.to.shared.u64 t, %1; cvt.u32.u64 %0, t; }" : "=r"(a) : "l"(p));
    return a;
}
__device__ __forceinline__ void cp_async16(uint32_t s, const void* g) {
    asm volatile("cp.async.cg.shared.global [%0], [%1], 16;" :: "r"(s), "l"(g));
}
__device__ __forceinline__ void ldsm4(uint32_t (&r)[4], uint32_t addr) {
    asm volatile("ldmatrix.sync.aligned.m8n8.x4.shared.b16 {%0,%1,%2,%3}, [%4];"
                 : "=r"(r[0]), "=r"(r[1]), "=r"(r[2]), "=r"(r[3]) : "r"(addr));
}
__device__ __forceinline__ void mma16816(float* c, const uint32_t* a, uint32_t b0, uint32_t b1) {
    asm volatile("mma.sync.aligned.m16n8k16.row.col.f32.f16.f16.f32 "
                 "{%0,%1,%2,%3}, {%4,%5,%6,%7}, {%8,%9}, {%0,%1,%2,%3};"
                 : "+f"(c[0]), "+f"(c[1]), "+f"(c[2]), "+f"(c[3])
                 : "r"(a[0]), "r"(a[1]), "r"(a[2]), "r"(a[3]), "r"(b0), "r"(b1));
}
__device__ __forceinline__ float block128_sum(float v, volatile float* sh) {
    #pragma unroll
    for (int o = 16; o > 0; o >>= 1) v += __shfl_xor_sync(0xffffffffu, v, o);
    __syncthreads();
    if ((threadIdx.x & 31) == 0) sh[threadIdx.x >> 5] = v;
    __syncthreads();
    return sh[0] + sh[1] + sh[2] + sh[3];
}
__device__ __forceinline__ void packh2(float a, float b, fp16* H, size_t idx) {
    *reinterpret_cast<__half2*>(H + idx) = __floats2half2_rn(a, b);
}

#define SM_FIX 1536
#define GP     144                // 64 fp16 = 128B + 16B pad (ldsm conflict-free)
#define GTILE  (128*GP)           // 18432
#define GSTAGE (2*GTILE)          // 36864 (A + B)
#define NSTAGE 3
#define GSM_TOT (SM_FIX + NSTAGE*GSTAGE)   // 112128 -> 2 CTAs/SM

// ---------------- embedding gather + LN + front-pad ----------------------------
__global__ void embed_kernel(const float* __restrict__ emb,
                             const float* __restrict__ g,
                             const float* __restrict__ bta,
                             const int*   __restrict__ seq,
                             fp16* __restrict__ xh) {
    __shared__ float sh[4];
    int b = blockIdx.y, t = blockIdx.x, tid = threadIdx.x;
    size_t o = ((size_t)b * LPAD + t) * DD + tid;
    float r;
    if (t < PAD) {
        r = 0.f;
    } else {
        int item = seq[b * SS + (t - PAD)];
        float v = emb[(size_t)item * DD + tid];
        float mu  = block128_sum(v, sh) * (1.f / DD);
        float d   = v - mu;
        float var = block128_sum(d * d, sh) * (1.f / DD);
        r = d * rsqrtf(var + 1e-5f) * g[tid] + bta[tid];
    }
    xh[o] = __float2half_rn(r);
}

// ---------------- per-layer lambda-power table ----------------------------------
__global__ void lam_kernel(const float* __restrict__ params_log, int li) {
    int idx = blockIdx.x * 256 + threadIdx.x;   // 0..32767
    int cg = idx >> 12, rem = idx & 4095;
    int p = (rem >> 5) + 1, c = rem & 31;
    int d = cg * 32 + c;
    float nu = expf(params_log[(li * 3 + 0) * DH + d]);
    float th = expf(params_log[(li * 3 + 1) * DH + d]);
    float mag = expf(-nu * (float)p);
    float sv, cv;
    sincosf(th * (float)p, &sv, &cv);
    g_lamR[idx] = mag * cv;
    g_lamI[idx] = mag * sv;
}

// ---------------- per-layer weight packing (to fp16) ----------------------------
__global__ void pack_kernel(const float* __restrict__ in_wr, const float* __restrict__ in_wi,
                            const float* __restrict__ in_br, const float* __restrict__ in_bi,
                            const float* __restrict__ out_wr, const float* __restrict__ out_wi,
                            const float* __restrict__ w1, const float* __restrict__ w2,
                            const float* __restrict__ params_log, int li) {
    int idx = blockIdx.x * 256 + threadIdx.x;   // 0 .. 262143
    int mat = idx >> 16, r = idx & 65535;
    float w;
    fp16* Dst;
    if (mat == 0) {
        int n = r >> 7, k = r & 127;
        int d = n >> 1, s = n & 1;
        float gamma = expf(params_log[(li * 3 + 2) * DH + d]);
        w = (s ? in_wi[(size_t)li * DH * DD + d * DD + k]
               : in_wr[(size_t)li * DH * DD + d * DD + k]) * gamma;
        if (k == 0) {
            float bv = s ? in_bi[li * DH + d] : in_br[li * DH + d];
            g_bin[n] = bv * gamma;
        }
        Dst = g_Win;
    } else if (mat == 1) {
        int n = r >> 9, k = r & 511;
        int d = k >> 1, s = k & 1;
        w = s ? -out_wi[(size_t)li * DD * DH + n * DH + d]
              :  out_wr[(size_t)li * DD * DH + n * DH + d];
        Dst = g_Wout;
    } else if (mat == 2) {
        w = w1[(size_t)li * DFF * DD + r];
        Dst = g_w1;
    } else {
        w = w2[(size_t)li * DD * DFF + r];
        Dst = g_w2;
    }
    Dst[r] = __float2half_rn(w);
}

// ---------------- gather last valid token --------------------------------------
__global__ void gather_kernel(const fp16* __restrict__ hh,
                              const fp16* __restrict__ xh, const int* __restrict__ slen,
                              fp16* __restrict__ hgh, fp16* __restrict__ xgh) {
    int b = blockIdx.x, tid = threadIdx.x;
    int t = PAD + slen[b] - 1;
    hgh[(size_t)b * 512 + tid] = hh[((size_t)b * LPAD + t) * 512 + tid];
    if (tid < DD) xgh[(size_t)b * DD + tid] = xh[((size_t)b * LPAD + t) * DD + tid];
}

// ================= register-resident masked LRU tree scan =======================
// Block = (cg, b): 32 complex channels x 256 timesteps, in place on fp16 h.
// Thread (tc, c): 32 consecutive timesteps of channel c in registers.
// Levels 1-5 (l<=32) in-register; levels 6-8 via 2KB chunk-boundary smem.
__global__ void __launch_bounds__(256) scan_kernel(fp16* __restrict__ hh,
                                                   const int* __restrict__ seq) {
    __shared__ float ms[LPAD];
    __shared__ float2 bnd[8][32];
    int b = blockIdx.y, cg = blockIdx.x;     // cg 0..7
    int tid = threadIdx.x;
    int c = tid & 31, tc = tid >> 5;         // tc 0..7
    const float* lamR = g_lamR + cg * 4096;  // [(p-1)*32 + c]
    const float* lamI = g_lamI + cg * 4096;

    ms[tid] = (tid >= PAD && seq[b * SS + tid - PAD] > 0) ? 1.f : 0.f;

    int t0 = tc * 32;
    size_t base = ((size_t)b * LPAD + t0) * 512 + cg * 64 + 2 * c;
    float2 h[32];
    #pragma unroll
    for (int j = 0; j < 32; j++)
        h[j] = __half22float2(*reinterpret_cast<const __half2*>(hh + base + (size_t)j * 512));
    __syncthreads();

    // levels 1..5 entirely in registers (l = 2..32)
    #pragma unroll
    for (int lev = 1; lev <= 5; lev++) {
        int l = 1 << lev, half = l >> 1;
        #pragma unroll
        for (int s = 0; s < 32; s += (1 << lev)) {
            int cpos = t0 + s + half - 1;
            if (ms[cpos] != 0.f) {
                float2 src = h[s + half - 1];
                #pragma unroll
                for (int p = 1; p <= (1 << (lev - 1)); p++) {
                    int j = s + half - 1 + p;
                    float lr = lamR[(p - 1) * 32 + c], li = lamI[(p - 1) * 32 + c];
                    h[j].x += lr * src.x - li * src.y;
                    h[j].y += lr * src.y + li * src.x;
                }
            }
        }
    }

    // chunk-boundary exchange for levels 6..8 (l = 64, 128, 256)
    bnd[tc][c] = h[31];
    __syncthreads();
    #pragma unroll
    for (int lev = 6; lev <= 8; lev++) {
        int l = 1 << lev, half = l >> 1;
        int blk = t0 >> lev;
        int cpos = blk * l + half - 1;
        if (t0 > cpos && ms[cpos] != 0.f) {
            float2 src = bnd[cpos >> 5][c];
            int p0 = t0 - cpos;
            #pragma unroll
            for (int j = 0; j < 32; j++) {
                int p = p0 + j;
                float lr = lamR[(p - 1) * 32 + c], li = lamI[(p - 1) * 32 + c];
                h[j].x += lr * src.x - li * src.y;
                h[j].y += lr * src.y + li * src.x;
            }
            bnd[tc][c] = h[31];
        }
        __syncthreads();
    }

    #pragma unroll
    for (int j = 0; j < 32; j++)
        *reinterpret_cast<__half2*>(hh + base + (size_t)j * 512) =
            __floats2half2_rn(h[j].x, h[j].y);
}

// ================= pipelined fp16 GEMM (BK=64, 3 stages, 2 CTAs/SM) =============
// EPI 0: bias only. EPI 1: bias+gelu. EPI 2: bias+residual(fp16)+LayerNorm (N==128).
__device__ __forceinline__ void gemm_load_chunk(
        uint32_t st, const fp16* A, const fp16* B,
        int m0, int n0, int kc, int K, int tid) {
    #pragma unroll
    for (int t = 0; t < 4; t++) {
        int idx = tid + t * 256;       // 0..1023
        int row = idx >> 3, seg = idx & 7;
        uint32_t so = row * GP + seg * 16;
        cp_async16(st + so,         A + (size_t)(m0 + row) * K + kc + seg * 8);
        cp_async16(st + GTILE + so, B + (size_t)(n0 + row) * K + kc + seg * 8);
    }
}

template<int EPI>
__global__ void __launch_bounds__(256, 2) hmma_gemm(
        const fp16* __restrict__ A, const fp16* __restrict__ B,
        const float* __restrict__ bias, const fp16* __restrict__ Res,
        const float* __restrict__ lng, const float* __restrict__ lnb,
        float* __restrict__ Cf, fp16* __restrict__ Ch,
        int M, int N, int K) {
    char* sm = dyn_smem;
    float* sBias = (float*)sm;
    float* sG    = sBias + 128;
    float* sB    = sG + 128;
    float* sred  = (float*)(sm + SM_FIX);   // overlay after mainloop
    uint32_t sb = smem_u32(sm);

    int tid = threadIdx.x, lane = tid & 31, wid = tid >> 5;
    int q = lane & 3, hrow = lane >> 2;
    int wm = wid & 3, wn = wid >> 2;
    int m0 = blockIdx.y * 128, n0 = blockIdx.x * 128;

    if (tid < 128) {
        sBias[tid] = bias[n0 + tid];
        if (EPI == 2) { sG[tid] = lng[n0 + tid]; sB[tid] = lnb[n0 + tid]; }
    }

    float acc[2][8][4];
    #pragma unroll
    for (int a1 = 0; a1 < 2; a1++)
        #pragma unroll
        for (int a2 = 0; a2 < 8; a2++)
            #pragma unroll
            for (int a3 = 0; a3 < 4; a3++) acc[a1][a2][a3] = 0.f;

    int nc = K >> 6;
    gemm_load_chunk(sb + SM_FIX, A, B, m0, n0, 0, K, tid);
    asm volatile("cp.async.commit_group;");
    if (nc > 1) gemm_load_chunk(sb + SM_FIX + GSTAGE, A, B, m0, n0, 64, K, tid);
    asm volatile("cp.async.commit_group;");

    for (int ch = 0; ch < nc; ch++) {
        if (ch + 2 < nc)
            gemm_load_chunk(sb + SM_FIX + ((ch + 2) % NSTAGE) * GSTAGE,
                            A, B, m0, n0, (ch + 2) << 6, K, tid);
        asm volatile("cp.async.commit_group;");
        asm volatile("cp.async.wait_group 2;");
        __syncthreads();
        uint32_t st = sb + SM_FIX + (ch % NSTAGE) * GSTAGE;
        uint32_t aA = st, aB = st + GTILE;
        #pragma unroll
        for (int ks = 0; ks < 4; ks++) {
            uint32_t ah[2][4];
            #pragma unroll
            for (int mt = 0; mt < 2; mt++) {
                uint32_t aoff = (uint32_t)((wm*32 + mt*16 + (lane & 15)) * GP + ks*32 + (lane >> 4) * 16);
                ldsm4(ah[mt], aA + aoff);
            }
            #pragma unroll
            for (int nb = 0; nb < 4; nb++) {
                uint32_t boff = (uint32_t)((wn*64 + nb*16 + (lane & 15)) * GP + ks*32 + (lane >> 4) * 16);
                uint32_t bh[4];
                ldsm4(bh, aB + boff);
                #pragma unroll
                for (int mt = 0; mt < 2; mt++) {
                    mma16816(acc[mt][2*nb],   ah[mt], bh[0], bh[2]);
                    mma16816(acc[mt][2*nb+1], ah[mt], bh[1], bh[3]);
                }
            }
        }
        __syncthreads();
    }

    // ---------------- epilogue ----------------
    #pragma unroll
    for (int mt = 0; mt < 2; mt++)
        #pragma unroll
        for (int j = 0; j < 8; j++) {
            int col = wn*64 + j*8 + q*2;
            float b0 = sBias[col], b1 = sBias[col+1];
            acc[mt][j][0] += b0; acc[mt][j][1] += b1;
            acc[mt][j][2] += b0; acc[mt][j][3] += b1;
        }
    if (EPI == 1) {
        #pragma unroll
        for (int mt = 0; mt < 2; mt++)
            #pragma unroll
            for (int j = 0; j < 8; j++)
                #pragma unroll
                for (int v = 0; v < 4; v++)
                    acc[mt][j][v] = 0.5f * acc[mt][j][v] *
                                    (1.f + erff(acc[mt][j][v] * 0.70710678118654752f));
    }
    if (EPI == 2) {
        float mu[2][2], rs[2][2];
        #pragma unroll
        for (int mt = 0; mt < 2; mt++) {
            int r0 = m0 + wm*32 + mt*16 + hrow;
            #pragma unroll
            for (int j = 0; j < 8; j++) {
                int col = wn*64 + j*8 + q*2;
                float2 ra = __half22float2(*(const __half2*)(Res + (size_t)r0 * 128 + col));
                float2 rb = __half22float2(*(const __half2*)(Res + (size_t)(r0+8) * 128 + col));
                acc[mt][j][0] += ra.x; acc[mt][j][1] += ra.y;
                acc[mt][j][2] += rb.x; acc[mt][j][3] += rb.y;
            }
        }
        float ssum[2][2] = {{0,0},{0,0}}, ssq[2][2] = {{0,0},{0,0}};
        #pragma unroll
        for (int mt = 0; mt < 2; mt++)
            #pragma unroll
            for (int j = 0; j < 8; j++)
                #pragma unroll
                for (int hh = 0; hh < 2; hh++) {
                    float v0 = acc[mt][j][2*hh], v1 = acc[mt][j][2*hh+1];
                    ssum[mt][hh] += v0 + v1;
                    ssq[mt][hh]  += v0*v0 + v1*v1;
                }
        #pragma unroll
        for (int mt = 0; mt < 2; mt++)
            #pragma unroll
            for (int hh = 0; hh < 2; hh++) {
                ssum[mt][hh] += __shfl_xor_sync(0xffffffffu, ssum[mt][hh], 1);
                ssum[mt][hh] += __shfl_xor_sync(0xffffffffu, ssum[mt][hh], 2);
                ssq[mt][hh]  += __shfl_xor_sync(0xffffffffu, ssq[mt][hh], 1);
                ssq[mt][hh]  += __shfl_xor_sync(0xffffffffu, ssq[mt][hh], 2);
            }
        if (q == 0) {
            #pragma unroll
            for (int mt = 0; mt < 2; mt++)
                #pragma unroll
                for (int hh = 0; hh < 2; hh++) {
                    int lr = wm*32 + mt*16 + hrow + hh*8;
                    sred[lr*2 + wn]       = ssum[mt][hh];
                    sred[256 + lr*2 + wn] = ssq[mt][hh];
                }
        }
        __syncthreads();
        #pragma unroll
        for (int mt = 0; mt < 2; mt++)
            #pragma unroll
            for (int hh = 0; hh < 2; hh++) {
                int lr = wm*32 + mt*16 + hrow + hh*8;
                float S  = sred[lr*2] + sred[lr*2 + 1];
                float S2 = sred[256 + lr*2] + sred[256 + lr*2 + 1];
                float m  = S * (1.f/128.f);
                float var = S2 * (1.f/128.f) - m * m;
                mu[mt][hh] = m;
                rs[mt][hh] = rsqrtf(var + 1e-5f);
            }
        #pragma unroll
        for (int mt = 0; mt < 2; mt++)
            #pragma unroll
            for (int j = 0; j < 8; j++) {
                int col = wn*64 + j*8 + q*2;
                float g0 = sG[col], g1 = sG[col+1], bb0 = sB[col], bb1 = sB[col+1];
                acc[mt][j][0] = (acc[mt][j][0] - mu[mt][0]) * rs[mt][0] * g0 + bb0;
                acc[mt][j][1] = (acc[mt][j][1] - mu[mt][0]) * rs[mt][0] * g1 + bb1;
                acc[mt][j][2] = (acc[mt][j][2] - mu[mt][1]) * rs[mt][1] * g0 + bb0;
                acc[mt][j][3] = (acc[mt][j][3] - mu[mt][1]) * rs[mt][1] * g1 + bb1;
            }
    }
    #pragma unroll
    for (int mt = 0; mt < 2; mt++) {
        int r0 = m0 + wm*32 + mt*16 + hrow;
        #pragma unroll
        for (int j = 0; j < 8; j++) {
            int col = n0 + wn*64 + j*8 + q*2;
            if (Cf) {
                *(float2*)(Cf + (size_t)r0 * N + col)     = make_float2(acc[mt][j][0], acc[mt][j][1]);
                *(float2*)(Cf + (size_t)(r0+8) * N + col) = make_float2(acc[mt][j][2], acc[mt][j][3]);
            }
            if (Ch) {
                packh2(acc[mt][j][0], acc[mt][j][1], Ch, (size_t)r0 * N + col);
                packh2(acc[mt][j][2], acc[mt][j][3], Ch, (size_t)(r0+8) * N + col);
            }
        }
    }
}

// ---------------- host driver ---------------------------------------------------
extern "C" void kernel_launch(void* const* d_in, const int* in_sizes, int n_in,
                              void* d_out, int out_size) {
    const float* token_emb  = (const float*)d_in[0];
    const float* emb_ln_g   = (const float*)d_in[1];
    const float* emb_ln_b   = (const float*)d_in[2];
    const float* params_log = (const float*)d_in[3];
    const float* in_wr      = (const float*)d_in[4];
    const float* in_wi      = (const float*)d_in[5];
    const float* in_br      = (const float*)d_in[6];
    const float* in_bi      = (const float*)d_in[7];
    const float* out_wr     = (const float*)d_in[8];
    const float* out_wi     = (const float*)d_in[9];
    const float* out_br     = (const float*)d_in[10];
    const float* lru_ln_g   = (const float*)d_in[12];
    const float* lru_ln_b   = (const float*)d_in[13];
    const float* w1         = (const float*)d_in[14];
    const float* b1         = (const float*)d_in[15];
    const float* w2         = (const float*)d_in[16];
    const float* b2         = (const float*)d_in[17];
    const float* ffn_ln_g   = (const float*)d_in[18];
    const float* ffn_ln_b   = (const float*)d_in[19];
    const int*   item_seq   = (const int*)d_in[20];
    const int*   item_len   = (const int*)d_in[21];
    float* out = (float*)d_out;

    float *pbin;
    fp16 *pxh, *px2h, *phh, *phfh, *pWin, *pWout, *pw1, *pw2;
    fp16 *psm1h, *psm2h, *phgh, *pxgh;
    cudaGetSymbolAddress((void**)&pxh,   g_xh);
    cudaGetSymbolAddress((void**)&px2h,  g_x2h);
    cudaGetSymbolAddress((void**)&phh,   g_hh);
    cudaGetSymbolAddress((void**)&phfh,  g_hfh);
    cudaGetSymbolAddress((void**)&pWin,  g_Win);
    cudaGetSymbolAddress((void**)&pbin,  g_bin);
    cudaGetSymbolAddress((void**)&pWout, g_Wout);
    cudaGetSymbolAddress((void**)&pw1,   g_w1);
    cudaGetSymbolAddress((void**)&pw2,   g_w2);
    cudaGetSymbolAddress((void**)&pxgh,  g_xgh);
    cudaGetSymbolAddress((void**)&psm1h, g_sm1h);
    cudaGetSymbolAddress((void**)&psm2h, g_sm2h);
    cudaGetSymbolAddress((void**)&phgh,  g_hgh);

    cudaFuncSetAttribute(hmma_gemm<0>, cudaFuncAttributeMaxDynamicSharedMemorySize, GSM_TOT);
    cudaFuncSetAttribute(hmma_gemm<1>, cudaFuncAttributeMaxDynamicSharedMemorySize, GSM_TOT);
    cudaFuncSetAttribute(hmma_gemm<2>, cudaFuncAttributeMaxDynamicSharedMemorySize, GSM_TOT);

    embed_kernel<<<dim3(LPAD, BB), 128>>>(token_emb, emb_ln_g, emb_ln_b, item_seq, pxh);

    for (int li = 0; li < NLAY; li++) {
        pack_kernel<<<1024, 256>>>(in_wr, in_wi, in_br, in_bi, out_wr, out_wi,
                                   w1, w2, params_log, li);
        lam_kernel<<<128, 256>>>(params_log, li);
        // in-projection (bias folded, fp16 out, interleaved complex columns)
        hmma_gemm<0><<<dim3(4, MTOK/128), 256, GSM_TOT>>>(
            pxh, pWin, pbin, nullptr, nullptr, nullptr,
            nullptr, phh, MTOK, 512, 128);
        // masked LRU tree scan, register-resident, in place
        scan_kernel<<<dim3(8, BB), 256>>>(phh, item_seq);

        if (li == 0) {
            hmma_gemm<2><<<dim3(1, MTOK/128), 256, GSM_TOT>>>(
                phh, pWout, out_br + li*DD, pxh,
                lru_ln_g + li*DD, lru_ln_b + li*DD,
                nullptr, px2h, MTOK, 128, 512);
            hmma_gemm<1><<<dim3(4, MTOK/128), 256, GSM_TOT>>>(
                px2h, pw1, b1 + li*DFF, nullptr, nullptr, nullptr,
                nullptr, phfh, MTOK, 512, 128);
            hmma_gemm<2><<<dim3(1, MTOK/128), 256, GSM_TOT>>>(
                phfh, pw2, b2 + li*DD, px2h,
                ffn_ln_g + li*DD, ffn_ln_b + li*DD,
                nullptr, pxh, MTOK, 128, 512);
        } else {
            gather_kernel<<<BB, 512>>>(phh, pxh, item_len, phgh, pxgh);
            hmma_gemm<2><<<dim3(1, BB/128), 256, GSM_TOT>>>(
                phgh, pWout, out_br + li*DD, pxgh,
                lru_ln_g + li*DD, lru_ln_b + li*DD,
                nullptr, psm1h, BB, 128, 512);
            hmma_gemm<1><<<dim3(4, BB/128), 256, GSM_TOT>>>(
                psm1h, pw1, b1 + li*DFF, nullptr, nullptr, nullptr,
                nullptr, psm2h, BB, 512, 128);
            hmma_gemm<2><<<dim3(1, BB/128), 256, GSM_TOT>>>(
                psm2h, pw2, b2 + li*DD, psm1h,
                ffn_ln_g + li*DD, ffn_ln_b + li*DD,
                out, nullptr, BB, 128, 512);
        }
    }
}

// round 11
// speedup vs baseline: 3.8252x; 1.0128x over previous
#include <cuda_runtime.h>
#include <cuda_bf16.h>
#include <cuda_fp16.h>
#include <math.h>
#include <stdint.h>

// Problem constants
#define BB   512
#define SS   200
#define DD   128
#define NLAY 2
#define DH   256      // complex hidden (512 reals)
#define DFF  512
#define LPAD 256
#define PAD  56
#define MTOK (BB*LPAD)

typedef __half fp16;

// single dynamic-smem symbol shared by all kernels
extern __shared__ __align__(16) char dyn_smem[];

// ---------------- scratch (device globals) ------------------------------------
__device__ fp16 g_xh [MTOK * DD];
__device__ fp16 g_x2h[MTOK * DD];
__device__ fp16 g_hh [MTOK * 2*DH];
__device__ fp16 g_hfh[MTOK * DFF];
// packed per-layer weights + lambda-power table [cg 0..7][p-1 0..127][c 0..31]
__device__ fp16 g_Win[2*DH*DD];
__device__ float g_bin[2*DH];
__device__ fp16 g_Wout[DD*2*DH];
__device__ fp16 g_w1[DFF*DD];
__device__ fp16 g_w2[DD*DFF];
__device__ float g_lamR[8*128*32];
__device__ float g_lamI[8*128*32];
// layer-2 tail (gathered, M=BB)
__device__ fp16 g_xgh[BB * DD];
__device__ fp16 g_sm1h[BB*DD];
__device__ fp16 g_sm2h[BB*DFF];
__device__ fp16 g_hgh[BB*2*DH];

// ---------------- helpers -------------------------------------------------------
__device__ __forceinline__ uint32_t smem_u32(const void* p) {
    uint32_t a;
    asm("{ .reg .u64 t; cvta.to.shared.u64 t, %1; cvt.u32.u64 %0, t; }" : "=r"(a) : "l"(p));
    return a;
}
__device__ __forceinline__ void cp_async16(uint32_t s, const void* g) {
    asm volatile("cp.async.cg.shared.global [%0], [%1], 16;" :: "r"(s), "l"(g));
}
__device__ __forceinline__ void ldsm4(uint32_t (&r)[4], uint32_t addr) {
    asm volatile("ldmatrix.sync.aligned.m8n8.x4.shared.b16 {%0,%1,%2,%3}, [%4];"
                 : "=r"(r[0]), "=r"(r[1]), "=r"(r[2]), "=r"(r[3]) : "r"(addr));
}
__device__ __forceinline__ void mma16816(float* c, const uint32_t* a, uint32_t b0, uint32_t b1) {
    asm volatile("mma.sync.aligned.m16n8k16.row.col.f32.f16.f16.f32 "
                 "{%0,%1,%2,%3}, {%4,%5,%6,%7}, {%8,%9}, {%0,%1,%2,%3};"
                 : "+f"(c[0]), "+f"(c[1]), "+f"(c[2]), "+f"(c[3])
                 : "r"(a[0]), "r"(a[1]), "r"(a[2]), "r"(a[3]), "r"(b0), "r"(b1));
}
__device__ __forceinline__ float block128_sum(float v, volatile float* sh) {
    #pragma unroll
    for (int o = 16; o > 0; o >>= 1) v += __shfl_xor_sync(0xffffffffu, v, o);
    __syncthreads();
    if ((threadIdx.x & 31) == 0) sh[threadIdx.x >> 5] = v;
    __syncthreads();
    return sh[0] + sh[1] + sh[2] + sh[3];
}
__device__ __forceinline__ void packh2(float a, float b, fp16* H, size_t idx) {
    *reinterpret_cast<__half2*>(H + idx) = __floats2half2_rn(a, b);
}

#define SM_FIX 1536
#define GP     144                // 64 fp16 = 128B + 16B pad (ldsm conflict-free)
#define GTILE  (128*GP)           // 18432
#define GSTAGE (2*GTILE)          // 36864 (A + B)
#define NSTAGE 3
#define GSM_TOT (SM_FIX + NSTAGE*GSTAGE)   // 112128 -> 2 CTAs/SM

// ---------------- embedding gather + LN + front-pad ----------------------------
__global__ void embed_kernel(const float* __restrict__ emb,
                             const float* __restrict__ g,
                             const float* __restrict__ bta,
                             const int*   __restrict__ seq,
                             fp16* __restrict__ xh) {
    __shared__ float sh[4];
    int b = blockIdx.y, t = blockIdx.x, tid = threadIdx.x;
    size_t o = ((size_t)b * LPAD + t) * DD + tid;
    float r;
    if (t < PAD) {
        r = 0.f;
    } else {
        int item = seq[b * SS + (t - PAD)];
        float v = emb[(size_t)item * DD + tid];
        float mu  = block128_sum(v, sh) * (1.f / DD);
        float d   = v - mu;
        float var = block128_sum(d * d, sh) * (1.f / DD);
        r = d * rsqrtf(var + 1e-5f) * g[tid] + bta[tid];
    }
    xh[o] = __float2half_rn(r);
}

// ---------------- per-layer lambda-power table ----------------------------------
__global__ void lam_kernel(const float* __restrict__ params_log, int li) {
    int idx = blockIdx.x * 256 + threadIdx.x;   // 0..32767
    int cg = idx >> 12, rem = idx & 4095;
    int p = (rem >> 5) + 1, c = rem & 31;
    int d = cg * 32 + c;
    float nu = expf(params_log[(li * 3 + 0) * DH + d]);
    float th = expf(params_log[(li * 3 + 1) * DH + d]);
    float mag = expf(-nu * (float)p);
    float sv, cv;
    sincosf(th * (float)p, &sv, &cv);
    g_lamR[idx] = mag * cv;
    g_lamI[idx] = mag * sv;
}

// ---------------- per-layer weight packing (to fp16) ----------------------------
__global__ void pack_kernel(const float* __restrict__ in_wr, const float* __restrict__ in_wi,
                            const float* __restrict__ in_br, const float* __restrict__ in_bi,
                            const float* __restrict__ out_wr, const float* __restrict__ out_wi,
                            const float* __restrict__ w1, const float* __restrict__ w2,
                            const float* __restrict__ params_log, int li) {
    int idx = blockIdx.x * 256 + threadIdx.x;   // 0 .. 262143
    int mat = idx >> 16, r = idx & 65535;
    float w;
    fp16* Dst;
    if (mat == 0) {
        int n = r >> 7, k = r & 127;
        int d = n >> 1, s = n & 1;
        float gamma = expf(params_log[(li * 3 + 2) * DH + d]);
        w = (s ? in_wi[(size_t)li * DH * DD + d * DD + k]
               : in_wr[(size_t)li * DH * DD + d * DD + k]) * gamma;
        if (k == 0) {
            float bv = s ? in_bi[li * DH + d] : in_br[li * DH + d];
            g_bin[n] = bv * gamma;
        }
        Dst = g_Win;
    } else if (mat == 1) {
        int n = r >> 9, k = r & 511;
        int d = k >> 1, s = k & 1;
        w = s ? -out_wi[(size_t)li * DD * DH + n * DH + d]
              :  out_wr[(size_t)li * DD * DH + n * DH + d];
        Dst = g_Wout;
    } else if (mat == 2) {
        w = w1[(size_t)li * DFF * DD + r];
        Dst = g_w1;
    } else {
        w = w2[(size_t)li * DD * DFF + r];
        Dst = g_w2;
    }
    Dst[r] = __float2half_rn(w);
}

// ---------------- gather last valid token --------------------------------------
__global__ void gather_kernel(const fp16* __restrict__ hh,
                              const fp16* __restrict__ xh, const int* __restrict__ slen,
                              fp16* __restrict__ hgh, fp16* __restrict__ xgh) {
    int b = blockIdx.x, tid = threadIdx.x;
    int t = PAD + slen[b] - 1;
    hgh[(size_t)b * 512 + tid] = hh[((size_t)b * LPAD + t) * 512 + tid];
    if (tid < DD) xgh[(size_t)b * DD + tid] = xh[((size_t)b * LPAD + t) * DD + tid];
}

// ================= register-resident masked LRU tree scan =======================
// Block = (cg, b): 32 complex channels x 256 timesteps, in place on fp16 h.
// Chunks entirely beyond the gathered position t_b are dead: skip their I/O.
__global__ void __launch_bounds__(256) scan_kernel(fp16* __restrict__ hh,
                                                   const int* __restrict__ seq,
                                                   const int* __restrict__ slen) {
    __shared__ float ms[LPAD];
    __shared__ float2 bnd[8][32];
    int b = blockIdx.y, cg = blockIdx.x;     // cg 0..7
    int tid = threadIdx.x;
    int c = tid & 31, tc = tid >> 5;         // tc 0..7
    const float* lamR = g_lamR + cg * 4096;  // [(p-1)*32 + c]
    const float* lamI = g_lamI + cg * 4096;

    ms[tid] = (tid >= PAD && seq[b * SS + tid - PAD] > 0) ? 1.f : 0.f;
    int tb = PAD + slen[b] - 1;              // last live position

    int t0 = tc * 32;
    bool live = (t0 <= tb);
    size_t base = ((size_t)b * LPAD + t0) * 512 + cg * 64 + 2 * c;
    float2 h[32];
    if (live) {
        #pragma unroll
        for (int j = 0; j < 32; j++)
            h[j] = __half22float2(*reinterpret_cast<const __half2*>(hh + base + (size_t)j * 512));
    } else {
        #pragma unroll
        for (int j = 0; j < 32; j++) h[j] = make_float2(0.f, 0.f);
    }
    __syncthreads();

    // levels 1..5 entirely in registers (l = 2..32)
    #pragma unroll
    for (int lev = 1; lev <= 5; lev++) {
        int half = 1 << (lev - 1);
        #pragma unroll
        for (int s = 0; s < 32; s += (1 << lev)) {
            int cpos = t0 + s + half - 1;
            if (ms[cpos] != 0.f) {
                float2 src = h[s + half - 1];
                #pragma unroll
                for (int p = 1; p <= (1 << (lev - 1)); p++) {
                    int j = s + half - 1 + p;
                    float lr = lamR[(p - 1) * 32 + c], li = lamI[(p - 1) * 32 + c];
                    h[j].x += lr * src.x - li * src.y;
                    h[j].y += lr * src.y + li * src.x;
                }
            }
        }
    }

    // chunk-boundary exchange for levels 6..8 (l = 64, 128, 256)
    bnd[tc][c] = h[31];
    __syncthreads();
    #pragma unroll
    for (int lev = 6; lev <= 8; lev++) {
        int l = 1 << lev, half = l >> 1;
        int blk = t0 >> lev;
        int cpos = blk * l + half - 1;
        if (live && t0 > cpos && ms[cpos] != 0.f) {
            float2 src = bnd[cpos >> 5][c];
            int p0 = t0 - cpos;
            #pragma unroll
            for (int j = 0; j < 32; j++) {
                int p = p0 + j;
                float lr = lamR[(p - 1) * 32 + c], li = lamI[(p - 1) * 32 + c];
                h[j].x += lr * src.x - li * src.y;
                h[j].y += lr * src.y + li * src.x;
            }
            bnd[tc][c] = h[31];
        }
        __syncthreads();
    }

    if (live) {
        #pragma unroll
        for (int j = 0; j < 32; j++)
            *reinterpret_cast<__half2*>(hh + base + (size_t)j * 512) =
                __floats2half2_rn(h[j].x, h[j].y);
    }
}

// ================= pipelined fp16 GEMM (BK=64, 3 stages, 2 CTAs/SM) =============
// EPI 0: bias only. EPI 1: bias+gelu. EPI 2: bias+residual(fp16)+LayerNorm (N==128).
// lenp != null: M is token-major (256 tokens/batch, 128-row tiles); the upper tile
// of batch b is dead when PAD+len_b-1 < 128 (len < 73) -> whole block exits.
__device__ __forceinline__ void gemm_load_chunk(
        uint32_t st, const fp16* A, const fp16* B,
        int m0, int n0, int kc, int K, int tid) {
    #pragma unroll
    for (int t = 0; t < 4; t++) {
        int idx = tid + t * 256;       // 0..1023
        int row = idx >> 3, seg = idx & 7;
        uint32_t so = row * GP + seg * 16;
        cp_async16(st + so,         A + (size_t)(m0 + row) * K + kc + seg * 8);
        cp_async16(st + GTILE + so, B + (size_t)(n0 + row) * K + kc + seg * 8);
    }
}

template<int EPI>
__global__ void __launch_bounds__(256, 2) hmma_gemm(
        const fp16* __restrict__ A, const fp16* __restrict__ B,
        const float* __restrict__ bias, const fp16* __restrict__ Res,
        const float* __restrict__ lng, const float* __restrict__ lnb,
        float* __restrict__ Cf, fp16* __restrict__ Ch,
        const int* __restrict__ lenp,
        int M, int N, int K) {
    // ragged early-exit: dead upper tile of a short batch
    if (lenp && (blockIdx.y & 1) && lenp[blockIdx.y >> 1] < 73) return;

    char* sm = dyn_smem;
    float* sBias = (float*)sm;
    float* sG    = sBias + 128;
    float* sB    = sG + 128;
    float* sred  = (float*)(sm + SM_FIX);   // overlay after mainloop
    uint32_t sb = smem_u32(sm);

    int tid = threadIdx.x, lane = tid & 31, wid = tid >> 5;
    int q = lane & 3, hrow = lane >> 2;
    int wm = wid & 3, wn = wid >> 2;
    int m0 = blockIdx.y * 128, n0 = blockIdx.x * 128;

    if (tid < 128) {
        sBias[tid] = bias[n0 + tid];
        if (EPI == 2) { sG[tid] = lng[n0 + tid]; sB[tid] = lnb[n0 + tid]; }
    }

    float acc[2][8][4];
    #pragma unroll
    for (int a1 = 0; a1 < 2; a1++)
        #pragma unroll
        for (int a2 = 0; a2 < 8; a2++)
            #pragma unroll
            for (int a3 = 0; a3 < 4; a3++) acc[a1][a2][a3] = 0.f;

    int nc = K >> 6;
    gemm_load_chunk(sb + SM_FIX, A, B, m0, n0, 0, K, tid);
    asm volatile("cp.async.commit_group;");
    if (nc > 1) gemm_load_chunk(sb + SM_FIX + GSTAGE, A, B, m0, n0, 64, K, tid);
    asm volatile("cp.async.commit_group;");

    for (int ch = 0; ch < nc; ch++) {
        if (ch + 2 < nc)
            gemm_load_chunk(sb + SM_FIX + ((ch + 2) % NSTAGE) * GSTAGE,
                            A, B, m0, n0, (ch + 2) << 6, K, tid);
        asm volatile("cp.async.commit_group;");
        asm volatile("cp.async.wait_group 2;");
        __syncthreads();
        uint32_t st = sb + SM_FIX + (ch % NSTAGE) * GSTAGE;
        uint32_t aA = st, aB = st + GTILE;
        #pragma unroll
        for (int ks = 0; ks < 4; ks++) {
            uint32_t ah[2][4];
            #pragma unroll
            for (int mt = 0; mt < 2; mt++) {
                uint32_t aoff = (uint32_t)((wm*32 + mt*16 + (lane & 15)) * GP + ks*32 + (lane >> 4) * 16);
                ldsm4(ah[mt], aA + aoff);
            }
            #pragma unroll
            for (int nb = 0; nb < 4; nb++) {
                uint32_t boff = (uint32_t)((wn*64 + nb*16 + (lane & 15)) * GP + ks*32 + (lane >> 4) * 16);
                uint32_t bh[4];
                ldsm4(bh, aB + boff);
                #pragma unroll
                for (int mt = 0; mt < 2; mt++) {
                    mma16816(acc[mt][2*nb],   ah[mt], bh[0], bh[2]);
                    mma16816(acc[mt][2*nb+1], ah[mt], bh[1], bh[3]);
                }
            }
        }
        __syncthreads();
    }

    // ---------------- epilogue ----------------
    #pragma unroll
    for (int mt = 0; mt < 2; mt++)
        #pragma unroll
        for (int j = 0; j < 8; j++) {
            int col = wn*64 + j*8 + q*2;
            float b0 = sBias[col], b1 = sBias[col+1];
            acc[mt][j][0] += b0; acc[mt][j][1] += b1;
            acc[mt][j][2] += b0; acc[mt][j][3] += b1;
        }
    if (EPI == 1) {
        #pragma unroll
        for (int mt = 0; mt < 2; mt++)
            #pragma unroll
            for (int j = 0; j < 8; j++)
                #pragma unroll
                for (int v = 0; v < 4; v++)
                    acc[mt][j][v] = 0.5f * acc[mt][j][v] *
                                    (1.f + erff(acc[mt][j][v] * 0.70710678118654752f));
    }
    if (EPI == 2) {
        float mu[2][2], rs[2][2];
        #pragma unroll
        for (int mt = 0; mt < 2; mt++) {
            int r0 = m0 + wm*32 + mt*16 + hrow;
            #pragma unroll
            for (int j = 0; j < 8; j++) {
                int col = wn*64 + j*8 + q*2;
                float2 ra = __half22float2(*(const __half2*)(Res + (size_t)r0 * 128 + col));
                float2 rb = __half22float2(*(const __half2*)(Res + (size_t)(r0+8) * 128 + col));
                acc[mt][j][0] += ra.x; acc[mt][j][1] += ra.y;
                acc[mt][j][2] += rb.x; acc[mt][j][3] += rb.y;
            }
        }
        float ssum[2][2] = {{0,0},{0,0}}, ssq[2][2] = {{0,0},{0,0}};
        #pragma unroll
        for (int mt = 0; mt < 2; mt++)
            #pragma unroll
            for (int j = 0; j < 8; j++)
                #pragma unroll
                for (int hh = 0; hh < 2; hh++) {
                    float v0 = acc[mt][j][2*hh], v1 = acc[mt][j][2*hh+1];
                    ssum[mt][hh] += v0 + v1;
                    ssq[mt][hh]  += v0*v0 + v1*v1;
                }
        #pragma unroll
        for (int mt = 0; mt < 2; mt++)
            #pragma unroll
            for (int hh = 0; hh < 2; hh++) {
                ssum[mt][hh] += __shfl_xor_sync(0xffffffffu, ssum[mt][hh], 1);
                ssum[mt][hh] += __shfl_xor_sync(0xffffffffu, ssum[mt][hh], 2);
                ssq[mt][hh]  += __shfl_xor_sync(0xffffffffu, ssq[mt][hh], 1);
                ssq[mt][hh]  += __shfl_xor_sync(0xffffffffu, ssq[mt][hh], 2);
            }
        if (q == 0) {
            #pragma unroll
            for (int mt = 0; mt < 2; mt++)
                #pragma unroll
                for (int hh = 0; hh < 2; hh++) {
                    int lr = wm*32 + mt*16 + hrow + hh*8;
                    sred[lr*2 + wn]       = ssum[mt][hh];
                    sred[256 + lr*2 + wn] = ssq[mt][hh];
                }
        }
        __syncthreads();
        #pragma unroll
        for (int mt = 0; mt < 2; mt++)
            #pragma unroll
            for (int hh = 0; hh < 2; hh++) {
                int lr = wm*32 + mt*16 + hrow + hh*8;
                float S  = sred[lr*2] + sred[lr*2 + 1];
                float S2 = sred[256 + lr*2] + sred[256 + lr*2 + 1];
                float m  = S * (1.f/128.f);
                float var = S2 * (1.f/128.f) - m * m;
                mu[mt][hh] = m;
                rs[mt][hh] = rsqrtf(var + 1e-5f);
            }
        #pragma unroll
        for (int mt = 0; mt < 2; mt++)
            #pragma unroll
            for (int j = 0; j < 8; j++) {
                int col = wn*64 + j*8 + q*2;
                float g0 = sG[col], g1 = sG[col+1], bb0 = sB[col], bb1 = sB[col+1];
                acc[mt][j][0] = (acc[mt][j][0] - mu[mt][0]) * rs[mt][0] * g0 + bb0;
                acc[mt][j][1] = (acc[mt][j][1] - mu[mt][0]) * rs[mt][0] * g1 + bb1;
                acc[mt][j][2] = (acc[mt][j][2] - mu[mt][1]) * rs[mt][1] * g0 + bb0;
                acc[mt][j][3] = (acc[mt][j][3] - mu[mt][1]) * rs[mt][1] * g1 + bb1;
            }
    }
    #pragma unroll
    for (int mt = 0; mt < 2; mt++) {
        int r0 = m0 + wm*32 + mt*16 + hrow;
        #pragma unroll
        for (int j = 0; j < 8; j++) {
            int col = n0 + wn*64 + j*8 + q*2;
            if (Cf) {
                *(float2*)(Cf + (size_t)r0 * N + col)     = make_float2(acc[mt][j][0], acc[mt][j][1]);
                *(float2*)(Cf + (size_t)(r0+8) * N + col) = make_float2(acc[mt][j][2], acc[mt][j][3]);
            }
            if (Ch) {
                packh2(acc[mt][j][0], acc[mt][j][1], Ch, (size_t)r0 * N + col);
                packh2(acc[mt][j][2], acc[mt][j][3], Ch, (size_t)(r0+8) * N + col);
            }
        }
    }
}

// ---------------- host driver ---------------------------------------------------
extern "C" void kernel_launch(void* const* d_in, const int* in_sizes, int n_in,
                              void* d_out, int out_size) {
    const float* token_emb  = (const float*)d_in[0];
    const float* emb_ln_g   = (const float*)d_in[1];
    const float* emb_ln_b   = (const float*)d_in[2];
    const float* params_log = (const float*)d_in[3];
    const float* in_wr      = (const float*)d_in[4];
    const float* in_wi      = (const float*)d_in[5];
    const float* in_br      = (const float*)d_in[6];
    const float* in_bi      = (const float*)d_in[7];
    const float* out_wr     = (const float*)d_in[8];
    const float* out_wi     = (const float*)d_in[9];
    const float* out_br     = (const float*)d_in[10];
    const float* lru_ln_g   = (const float*)d_in[12];
    const float* lru_ln_b   = (const float*)d_in[13];
    const float* w1         = (const float*)d_in[14];
    const float* b1         = (const float*)d_in[15];
    const float* w2         = (const float*)d_in[16];
    const float* b2         = (const float*)d_in[17];
    const float* ffn_ln_g   = (const float*)d_in[18];
    const float* ffn_ln_b   = (const float*)d_in[19];
    const int*   item_seq   = (const int*)d_in[20];
    const int*   item_len   = (const int*)d_in[21];
    float* out = (float*)d_out;

    float *pbin;
    fp16 *pxh, *px2h, *phh, *phfh, *pWin, *pWout, *pw1, *pw2;
    fp16 *psm1h, *psm2h, *phgh, *pxgh;
    cudaGetSymbolAddress((void**)&pxh,   g_xh);
    cudaGetSymbolAddress((void**)&px2h,  g_x2h);
    cudaGetSymbolAddress((void**)&phh,   g_hh);
    cudaGetSymbolAddress((void**)&phfh,  g_hfh);
    cudaGetSymbolAddress((void**)&pWin,  g_Win);
    cudaGetSymbolAddress((void**)&pbin,  g_bin);
    cudaGetSymbolAddress((void**)&pWout, g_Wout);
    cudaGetSymbolAddress((void**)&pw1,   g_w1);
    cudaGetSymbolAddress((void**)&pw2,   g_w2);
    cudaGetSymbolAddress((void**)&pxgh,  g_xgh);
    cudaGetSymbolAddress((void**)&psm1h, g_sm1h);
    cudaGetSymbolAddress((void**)&psm2h, g_sm2h);
    cudaGetSymbolAddress((void**)&phgh,  g_hgh);

    cudaFuncSetAttribute(hmma_gemm<0>, cudaFuncAttributeMaxDynamicSharedMemorySize, GSM_TOT);
    cudaFuncSetAttribute(hmma_gemm<1>, cudaFuncAttributeMaxDynamicSharedMemorySize, GSM_TOT);
    cudaFuncSetAttribute(hmma_gemm<2>, cudaFuncAttributeMaxDynamicSharedMemorySize, GSM_TOT);

    embed_kernel<<<dim3(LPAD, BB), 128>>>(token_emb, emb_ln_g, emb_ln_b, item_seq, pxh);

    for (int li = 0; li < NLAY; li++) {
        pack_kernel<<<1024, 256>>>(in_wr, in_wi, in_br, in_bi, out_wr, out_wi,
                                   w1, w2, params_log, li);
        lam_kernel<<<128, 256>>>(params_log, li);
        // in-projection (bias folded, fp16 out, interleaved complex columns)
        hmma_gemm<0><<<dim3(4, MTOK/128), 256, GSM_TOT>>>(
            pxh, pWin, pbin, nullptr, nullptr, nullptr,
            nullptr, phh, item_len, MTOK, 512, 128);
        // masked LRU tree scan, register-resident, in place
        scan_kernel<<<dim3(8, BB), 256>>>(phh, item_seq, item_len);

        if (li == 0) {
            hmma_gemm<2><<<dim3(1, MTOK/128), 256, GSM_TOT>>>(
                phh, pWout, out_br + li*DD, pxh,
                lru_ln_g + li*DD, lru_ln_b + li*DD,
                nullptr, px2h, item_len, MTOK, 128, 512);
            hmma_gemm<1><<<dim3(4, MTOK/128), 256, GSM_TOT>>>(
                px2h, pw1, b1 + li*DFF, nullptr, nullptr, nullptr,
                nullptr, phfh, item_len, MTOK, 512, 128);
            hmma_gemm<2><<<dim3(1, MTOK/128), 256, GSM_TOT>>>(
                phfh, pw2, b2 + li*DD, px2h,
                ffn_ln_g + li*DD, ffn_ln_b + li*DD,
                nullptr, pxh, item_len, MTOK, 128, 512);
        } else {
            gather_kernel<<<BB, 512>>>(phh, pxh, item_len, phgh, pxgh);
            hmma_gemm<2><<<dim3(1, BB/128), 256, GSM_TOT>>>(
                phgh, pWout, out_br + li*DD, pxgh,
                lru_ln_g + li*DD, lru_ln_b + li*DD,
                nullptr, psm1h, nullptr, BB, 128, 512);
            hmma_gemm<1><<<dim3(4, BB/128), 256, GSM_TOT>>>(
                psm1h, pw1, b1 + li*DFF, nullptr, nullptr, nullptr,
                nullptr, psm2h, nullptr, BB, 512, 128);
            hmma_gemm<2><<<dim3(1, BB/128), 256, GSM_TOT>>>(
                psm2h, pw2, b2 + li*DD, psm1h,
                ffn_ln_g + li*DD, ffn_ln_b + li*DD,
                out, nullptr, nullptr, BB, 128, 512);
        }
    }
}